// round 10
// baseline (speedup 1.0000x reference)
#include <cuda_runtime.h>
#include <cuda_bf16.h>
#include <stdint.h>
#include <math.h>

#define BSZ 64
#define NN 512
#define DD 256
#define BIGC 1.0e9f

__device__ float g_eA[BSZ*NN*DD];
__device__ float g_eB[BSZ*NN*DD];
__device__ float g_nA[BSZ*NN];
__device__ float g_nB[BSZ*NN];
__device__ __nv_bfloat16 g_K[(size_t)BSZ*NN*NN];
__device__ int   g_cA[BSZ*NN];
__device__ int   g_cB[BSZ*NN];
__device__ double g_acc[3];

// ---- helpers ----
__device__ __forceinline__ uint32_t pack_bf2(float a, float b) {
    __nv_bfloat162 h = __floats2bfloat162_rn(a, b);
    return *reinterpret_cast<uint32_t*>(&h);
}
__device__ __forceinline__ void unpack_bf2(uint32_t u, float& a, float& b) {
    a = __uint_as_float(u << 16);
    b = __uint_as_float(u & 0xffff0000u);
}
__device__ __forceinline__ void cp_async16(void* smem_dst, const void* gmem_src) {
    uint32_t s = (uint32_t)__cvta_generic_to_shared(smem_dst);
    asm volatile("cp.async.cg.shared.global [%0], [%1], 16;" :: "r"(s), "l"(gmem_src));
}
__device__ __forceinline__ void cp_commit() {
    asm volatile("cp.async.commit_group;");
}
__device__ __forceinline__ void cp_wait0() {
    asm volatile("cp.async.wait_group 0;");
}
__device__ __forceinline__ void mma_tf32(float* c,
    uint32_t a0, uint32_t a1, uint32_t a2, uint32_t a3,
    uint32_t b0, uint32_t b1)
{
    asm volatile(
        "mma.sync.aligned.m16n8k8.row.col.f32.tf32.tf32.f32 "
        "{%0,%1,%2,%3}, {%4,%5,%6,%7}, {%8,%9}, {%0,%1,%2,%3};"
        : "+f"(c[0]), "+f"(c[1]), "+f"(c[2]), "+f"(c[3])
        : "r"(a0), "r"(a1), "r"(a2), "r"(a3), "r"(b0), "r"(b1));
}

__global__ void zero_acc_kernel() {
    if (threadIdx.x < 3) g_acc[threadIdx.x] = 0.0;
}

__global__ void class_argmax_kernel(const float* __restrict__ la,
                                    const float* __restrict__ lb) {
    int t = blockIdx.x * blockDim.x + threadIdx.x;
    if (t >= BSZ*NN) return;
    float4 a = ((const float4*)la)[t];
    int ba = 0; float bv = a.x;
    if (a.y > bv) { bv = a.y; ba = 1; }
    if (a.z > bv) { bv = a.z; ba = 2; }
    if (a.w > bv) { bv = a.w; ba = 3; }
    g_cA[t] = ba;
    float4 b = ((const float4*)lb)[t];
    int bb = 0; bv = b.x;
    if (b.y > bv) { bv = b.y; bb = 1; }
    if (b.z > bv) { bv = b.z; bb = 2; }
    if (b.w > bv) { bv = b.w; bb = 3; }
    g_cB[t] = bb;
}

__device__ __forceinline__ void ln_row(float v[8],
    const float4& g0, const float4& g1, const float4& e0, const float4& e1,
    float* o)
{
    float s = 0.f, sq = 0.f;
    #pragma unroll
    for (int j = 0; j < 8; j++) {
        v[j] = v[j] > 0.f ? v[j] : 0.01f * v[j];
        s += v[j]; sq += v[j]*v[j];
    }
    #pragma unroll
    for (int off = 16; off; off >>= 1) {
        s  += __shfl_xor_sync(0xffffffffu, s, off);
        sq += __shfl_xor_sync(0xffffffffu, sq, off);
    }
    float mean = s * (1.f/256.f);
    float var  = sq * (1.f/256.f) - mean*mean;
    float rstd = rsqrtf(var + 1e-5f);
    o[0] = (v[0]-mean)*rstd*g0.x + e0.x;
    o[1] = (v[1]-mean)*rstd*g0.y + e0.y;
    o[2] = (v[2]-mean)*rstd*g0.z + e0.z;
    o[3] = (v[3]-mean)*rstd*g0.w + e0.w;
    o[4] = (v[4]-mean)*rstd*g1.x + e1.x;
    o[5] = (v[5]-mean)*rstd*g1.y + e1.y;
    o[6] = (v[6]-mean)*rstd*g1.z + e1.z;
    o[7] = (v[7]-mean)*rstd*g1.w + e1.w;
}

// Fused 2-layer MLP+LN embed, tf32 mma, now 512 threads (16 warps, 4x4 warp grid)
// for 4 warps/SMSP latency hiding. Warp tile 16 rows x 64 cols (8 C-frags).
#define EMBED_SMEM ((64*256 + 2*16*256 + 2*64*16) * 4)

__global__ __launch_bounds__(512, 1)
void embed_kernel(const float* __restrict__ xA, const float* __restrict__ xB,
                  const float* __restrict__ W1, const float* __restrict__ b1,
                  const float* __restrict__ g1, const float* __restrict__ be1,
                  const float* __restrict__ W2, const float* __restrict__ b2,
                  const float* __restrict__ g2, const float* __restrict__ be2)
{
    extern __shared__ float sm[];
    float* Hs = sm;                  // 64*256 (swizzled)
    float* Ws = sm + 64*256;         // 2 x 16*256 (swizzled)
    float* Xs = Ws + 2*16*256;       // 2 x 64*16 (swizzled)

    const float* X  = blockIdx.y ? xB   : xA;
    float* E        = blockIdx.y ? g_eB : g_eA;
    float* NRM      = blockIdx.y ? g_nB : g_nA;

    const int tid  = threadIdx.x;
    const int lane = tid & 31;
    const int warp = tid >> 5;
    const int wm   = warp & 3;      // rows wm*16..+15
    const int wn   = warp >> 2;     // cols wn*64..+63 (0..3)
    const int g    = lane >> 3 ? (lane >> 2) : (lane >> 2); // = lane>>2
    const int gg   = lane >> 2;     // 0..7
    const int t    = lane & 3;      // 0..3
    const int row0 = blockIdx.x * 64;

    const int xr = (tid & 255) >> 2, xkq = (tid & 3) << 2;
    const int xdst = xr*16 + (xkq ^ (((xr>>1)&3)<<2));

    float c[8][4];
    #pragma unroll
    for (int j = 0; j < 8; j++)
        #pragma unroll
        for (int q = 0; q < 4; q++) c[j][q] = 0.f;

    // ---------------- stage 1: pre1 = x @ W1 ----------------
    {
        #pragma unroll
        for (int i = 0; i < 2; i++) {
            int f = tid + i*512;
            int k = f >> 6, n4 = (f & 63) << 2;
            cp_async16(Ws + k*256 + (n4 ^ ((k&3)<<3)), W1 + (size_t)k*256 + n4);
        }
        if (tid < 256)
            cp_async16(Xs + xdst, X + (size_t)(row0 + xr)*DD + xkq);
        cp_commit(); cp_wait0();
    }
    __syncthreads();

    for (int kt = 0; kt < 16; kt++) {
        const int cur = kt & 1, nxt = cur ^ 1;
        if (kt < 15) {
            const float* Wsrc = W1 + (size_t)(kt+1)*16*DD;
            float* Wdst = Ws + nxt*4096;
            #pragma unroll
            for (int i = 0; i < 2; i++) {
                int f = tid + i*512;
                int k = f >> 6, n4 = (f & 63) << 2;
                cp_async16(Wdst + k*256 + (n4 ^ ((k&3)<<3)), Wsrc + (size_t)k*256 + n4);
            }
            if (tid < 256)
                cp_async16(Xs + nxt*1024 + xdst,
                           X + (size_t)(row0 + xr)*DD + (kt+1)*16 + xkq);
            cp_commit();
        }
        const float* Wc = Ws + cur*4096;
        const float* Xc = Xs + cur*1024;
        const int sA = ((gg>>1)&3) << 2;
        const int sB = t << 3;
        #pragma unroll
        for (int h = 0; h < 2; h++) {
            int kl = h*8 + t;
            uint32_t a0 = __float_as_uint(Xc[(wm*16+gg  )*16 + ((kl  ) ^ sA)]);
            uint32_t a1 = __float_as_uint(Xc[(wm*16+gg+8)*16 + ((kl  ) ^ sA)]);
            uint32_t a2 = __float_as_uint(Xc[(wm*16+gg  )*16 + ((kl+4) ^ sA)]);
            uint32_t a3 = __float_as_uint(Xc[(wm*16+gg+8)*16 + ((kl+4) ^ sA)]);
            const float* Wr0 = Wc + (kl  )*256;
            const float* Wr1 = Wc + (kl+4)*256;
            #pragma unroll
            for (int j = 0; j < 8; j++) {
                int n = wn*64 + j*8 + gg;
                uint32_t b0 = __float_as_uint(Wr0[n ^ sB]);
                uint32_t b1 = __float_as_uint(Wr1[n ^ sB]);
                mma_tf32(c[j], a0, a1, a2, a3, b0, b1);
            }
        }
        if (kt < 15) cp_wait0();
        __syncthreads();
    }

    // stage-2 W prologue overlaps LN pass
    {
        #pragma unroll
        for (int i = 0; i < 2; i++) {
            int f = tid + i*512;
            int k = f >> 6, n4 = (f & 63) << 2;
            cp_async16(Ws + k*256 + (n4 ^ ((k&3)<<3)), W2 + (size_t)k*256 + n4);
        }
        cp_commit();
    }

    // write raw pre-act frags to Hs (swizzled)
    #pragma unroll
    for (int j = 0; j < 8; j++) {
        int r  = wm*16 + gg;
        int cc = wn*64 + j*8 + 2*t;
        *(float2*)&Hs[r*256 + (cc ^ ((r&7)<<2))] = make_float2(c[j][0], c[j][1]);
        int r2 = r + 8;
        *(float2*)&Hs[r2*256 + (cc ^ ((r2&7)<<2))] = make_float2(c[j][2], c[j][3]);
    }
    __syncthreads();

    // LN pass 1: warp owns rows warp*4..+3
    {
        const int c0 = lane*4, c1 = 128 + lane*4;
        float4 bv0 = *(const float4*)(b1 + c0), bv1 = *(const float4*)(b1 + c1);
        float4 gv0 = *(const float4*)(g1 + c0), gv1 = *(const float4*)(g1 + c1);
        float4 ev0 = *(const float4*)(be1 + c0), ev1 = *(const float4*)(be1 + c1);
        #pragma unroll
        for (int r = 0; r < 4; r++) {
            int row = warp*4 + r;
            int sH = (row & 7) << 2;
            float4 x0 = *(const float4*)&Hs[row*256 + (c0 ^ sH)];
            float4 x1 = *(const float4*)&Hs[row*256 + (c1 ^ sH)];
            float v[8], o[8];
            v[0]=x0.x+bv0.x; v[1]=x0.y+bv0.y; v[2]=x0.z+bv0.z; v[3]=x0.w+bv0.w;
            v[4]=x1.x+bv1.x; v[5]=x1.y+bv1.y; v[6]=x1.z+bv1.z; v[7]=x1.w+bv1.w;
            ln_row(v, gv0, gv1, ev0, ev1, o);
            *(float4*)&Hs[row*256 + (c0 ^ sH)] = make_float4(o[0],o[1],o[2],o[3]);
            *(float4*)&Hs[row*256 + (c1 ^ sH)] = make_float4(o[4],o[5],o[6],o[7]);
        }
    }
    cp_wait0();
    __syncthreads();

    // ---------------- stage 2: pre2 = h @ W2 ----------------
    #pragma unroll
    for (int j = 0; j < 8; j++)
        #pragma unroll
        for (int q = 0; q < 4; q++) c[j][q] = 0.f;

    for (int kt = 0; kt < 16; kt++) {
        const int cur = kt & 1, nxt = cur ^ 1;
        if (kt < 15) {
            const float* Wsrc = W2 + (size_t)(kt+1)*16*DD;
            float* Wdst = Ws + nxt*4096;
            #pragma unroll
            for (int i = 0; i < 2; i++) {
                int f = tid + i*512;
                int k = f >> 6, n4 = (f & 63) << 2;
                cp_async16(Wdst + k*256 + (n4 ^ ((k&3)<<3)), Wsrc + (size_t)k*256 + n4);
            }
            cp_commit();
        }
        const float* Wc = Ws + cur*4096;
        const float* H0 = Hs + (wm*16 + gg  )*256;
        const float* H1 = Hs + (wm*16 + gg+8)*256;
        const int sH = gg << 2;
        const int sB = t << 3;
        #pragma unroll
        for (int h = 0; h < 2; h++) {
            int k = kt*16 + h*8;
            uint32_t a0 = __float_as_uint(H0[(k+t  ) ^ sH]);
            uint32_t a1 = __float_as_uint(H1[(k+t  ) ^ sH]);
            uint32_t a2 = __float_as_uint(H0[(k+t+4) ^ sH]);
            uint32_t a3 = __float_as_uint(H1[(k+t+4) ^ sH]);
            const float* Wr0 = Wc + (h*8+t  )*256;
            const float* Wr1 = Wc + (h*8+t+4)*256;
            #pragma unroll
            for (int j = 0; j < 8; j++) {
                int n = wn*64 + j*8 + gg;
                uint32_t b0 = __float_as_uint(Wr0[n ^ sB]);
                uint32_t b1 = __float_as_uint(Wr1[n ^ sB]);
                mma_tf32(c[j], a0, a1, a2, a3, b0, b1);
            }
        }
        if (kt < 15) cp_wait0();
        __syncthreads();
    }

    #pragma unroll
    for (int j = 0; j < 8; j++) {
        int r  = wm*16 + gg;
        int cc = wn*64 + j*8 + 2*t;
        *(float2*)&Hs[r*256 + (cc ^ ((r&7)<<2))] = make_float2(c[j][0], c[j][1]);
        int r2 = r + 8;
        *(float2*)&Hs[r2*256 + (cc ^ ((r2&7)<<2))] = make_float2(c[j][2], c[j][3]);
    }
    __syncthreads();

    // LN pass 2 + store
    {
        const int c0 = lane*4, c1 = 128 + lane*4;
        float4 bv0 = *(const float4*)(b2 + c0), bv1 = *(const float4*)(b2 + c1);
        float4 gv0 = *(const float4*)(g2 + c0), gv1 = *(const float4*)(g2 + c1);
        float4 ev0 = *(const float4*)(be2 + c0), ev1 = *(const float4*)(be2 + c1);
        #pragma unroll
        for (int r = 0; r < 4; r++) {
            int row = warp*4 + r;
            int sH = (row & 7) << 2;
            float4 x0 = *(const float4*)&Hs[row*256 + (c0 ^ sH)];
            float4 x1 = *(const float4*)&Hs[row*256 + (c1 ^ sH)];
            float v[8], o[8];
            v[0]=x0.x+bv0.x; v[1]=x0.y+bv0.y; v[2]=x0.z+bv0.z; v[3]=x0.w+bv0.w;
            v[4]=x1.x+bv1.x; v[5]=x1.y+bv1.y; v[6]=x1.z+bv1.z; v[7]=x1.w+bv1.w;
            ln_row(v, gv0, gv1, ev0, ev1, o);
            float ns = o[0]*o[0]+o[1]*o[1]+o[2]*o[2]+o[3]*o[3]
                     + o[4]*o[4]+o[5]*o[5]+o[6]*o[6]+o[7]*o[7];
            #pragma unroll
            for (int off = 16; off; off >>= 1)
                ns += __shfl_xor_sync(0xffffffffu, ns, off);
            size_t grow = (size_t)(row0 + row);
            *(float4*)(E + grow*DD + c0) = make_float4(o[0],o[1],o[2],o[3]);
            *(float4*)(E + grow*DD + c1) = make_float4(o[4],o[5],o[6],o[7]);
            if (lane == 0) NRM[grow] = ns;
        }
    }
}

// cdist + cost_class + in/out loss + K(bf16) via tf32 mma (unchanged R9 winner).
__global__ __launch_bounds__(256, 2)
void cost_kernel(const float* __restrict__ pa, const float* __restrict__ pb)
{
    __shared__ __align__(16) float As[2][128*16];
    __shared__ __align__(16) float Bs[2][128*16];
    __shared__ float redi[8], redo[8];

    const int b  = blockIdx.z;
    const int ti = blockIdx.y;
    const int tj = blockIdx.x;
    const int tid = threadIdx.x;
    const int lane = tid & 31;
    const int warp = tid >> 5;
    const int wm   = warp & 3;
    const int wn   = warp >> 2;
    const int g    = lane >> 2;
    const int t    = lane & 3;

    const float* Ab = g_eA + (size_t)b*NN*DD + (size_t)ti*128*DD;
    const float* Bb = g_eB + (size_t)b*NN*DD + (size_t)tj*128*DD;

    const int lr  = tid >> 2;
    const int lkq = (tid & 3) << 2;

    float c[2][8][4];
    #pragma unroll
    for (int m = 0; m < 2; m++)
        #pragma unroll
        for (int j = 0; j < 8; j++)
            #pragma unroll
            for (int q = 0; q < 4; q++) c[m][j][q] = 0.f;

    {
        #pragma unroll
        for (int i = 0; i < 2; i++) {
            int row = lr + i*64;
            int dst = row*16 + (lkq ^ (((row>>1)&3)<<2));
            cp_async16(&As[0][dst], Ab + (size_t)row*DD + lkq);
            cp_async16(&Bs[0][dst], Bb + (size_t)row*DD + lkq);
        }
        cp_commit(); cp_wait0();
    }
    __syncthreads();

    const int sA = ((g>>1)&3) << 2;

    for (int kt = 0; kt < 16; kt++) {
        const int cur = kt & 1, nxt = cur ^ 1;
        if (kt < 15) {
            #pragma unroll
            for (int i = 0; i < 2; i++) {
                int row = lr + i*64;
                int dst = row*16 + (lkq ^ (((row>>1)&3)<<2));
                cp_async16(&As[nxt][dst], Ab + (size_t)row*DD + (kt+1)*16 + lkq);
                cp_async16(&Bs[nxt][dst], Bb + (size_t)row*DD + (kt+1)*16 + lkq);
            }
            cp_commit();
        }
        const float* Ac = As[cur];
        const float* Bc = Bs[cur];
        #pragma unroll
        for (int h = 0; h < 2; h++) {
            int kl = h*8 + t;
            #pragma unroll
            for (int m = 0; m < 2; m++) {
                int r = wm*32 + m*16 + g;
                uint32_t a0 = __float_as_uint(Ac[(r  )*16 + ((kl  ) ^ sA)]);
                uint32_t a1 = __float_as_uint(Ac[(r+8)*16 + ((kl  ) ^ sA)]);
                uint32_t a2 = __float_as_uint(Ac[(r  )*16 + ((kl+4) ^ sA)]);
                uint32_t a3 = __float_as_uint(Ac[(r+8)*16 + ((kl+4) ^ sA)]);
                #pragma unroll
                for (int j = 0; j < 8; j++) {
                    int n = wn*64 + j*8 + g;
                    uint32_t b0 = __float_as_uint(Bc[n*16 + ((kl  ) ^ sA)]);
                    uint32_t b1 = __float_as_uint(Bc[n*16 + ((kl+4) ^ sA)]);
                    mma_tf32(c[m][j], a0, a1, a2, a3, b0, b1);
                }
            }
        }
        if (kt < 15) cp_wait0();
        __syncthreads();
    }

    float sin = 0.f, sout = 0.f;
    #pragma unroll
    for (int m = 0; m < 2; m++) {
        int il1 = ti*128 + wm*32 + m*16 + g;
        int il2 = il1 + 8;
        int gi1 = b*NN + il1, gi2 = b*NN + il2;
        float ni1 = g_nA[gi1], ni2 = g_nA[gi2];
        float pa1 = pa[gi1],   pa2 = pa[gi2];
        int   ca1 = g_cA[gi1], ca2 = g_cA[gi2];
        size_t rb1 = (size_t)gi1 * NN;
        size_t rb2 = (size_t)gi2 * NN;
        #pragma unroll
        for (int j = 0; j < 8; j++) {
            int jl = tj*128 + wn*64 + j*8 + 2*t;
            int gj = b*NN + jl;
            float nj0 = g_nB[gj], nj1 = g_nB[gj+1];
            float pb0 = pb[gj],   pb1 = pb[gj+1];
            int   cb0 = g_cB[gj], cb1 = g_cB[gj+1];

            float sq, cost, pm, cc, w;
            float k00, k01, k10, k11;

            sq = ni1 + nj0 - 2.f*c[m][j][0];
            cost = sqrtf(fmaxf(sq, 0.f));
            pm = pa1*pb0; cc = cost + (BIGC - BIGC*pm); w = cc*pm;
            if (ca1 == cb0) sin += w; else sout += w;
            k00 = __expf(-2.f*cc);

            sq = ni1 + nj1 - 2.f*c[m][j][1];
            cost = sqrtf(fmaxf(sq, 0.f));
            pm = pa1*pb1; cc = cost + (BIGC - BIGC*pm); w = cc*pm;
            if (ca1 == cb1) sin += w; else sout += w;
            k01 = __expf(-2.f*cc);

            sq = ni2 + nj0 - 2.f*c[m][j][2];
            cost = sqrtf(fmaxf(sq, 0.f));
            pm = pa2*pb0; cc = cost + (BIGC - BIGC*pm); w = cc*pm;
            if (ca2 == cb0) sin += w; else sout += w;
            k10 = __expf(-2.f*cc);

            sq = ni2 + nj1 - 2.f*c[m][j][3];
            cost = sqrtf(fmaxf(sq, 0.f));
            pm = pa2*pb1; cc = cost + (BIGC - BIGC*pm); w = cc*pm;
            if (ca2 == cb1) sin += w; else sout += w;
            k11 = __expf(-2.f*cc);

            *(uint32_t*)(g_K + rb1 + jl) = pack_bf2(k00, k01);
            *(uint32_t*)(g_K + rb2 + jl) = pack_bf2(k10, k11);
        }
    }
    #pragma unroll
    for (int off = 16; off; off >>= 1) {
        sin  += __shfl_xor_sync(0xffffffffu, sin,  off);
        sout += __shfl_xor_sync(0xffffffffu, sout, off);
    }
    if (lane == 0) { redi[warp] = sin; redo[warp] = sout; }
    __syncthreads();
    if (tid == 0) {
        float a = 0.f, o2 = 0.f;
        #pragma unroll
        for (int w = 0; w < 8; w++) { a += redi[w]; o2 += redo[w]; }
        atomicAdd(&g_acc[0], (double)a);
        atomicAdd(&g_acc[1], (double)o2);
    }
}

// Sinkhorn + fused sup loss. 1 CTA (1024 threads) per batch (unchanged).
__global__ __launch_bounds__(1024)
void sinkhorn_kernel(const float* __restrict__ rel, const float* __restrict__ pa)
{
    __shared__ __align__(16) float su[NN];
    __shared__ __align__(16) float sv[NN];
    __shared__ __align__(16) float part[8][NN];
    __shared__ float sred[32];

    const int b = blockIdx.x;
    const __nv_bfloat16* Kb = g_K + (size_t)b*NN*NN;
    const int tid  = threadIdx.x;
    const int lane = tid & 31;
    const int warp = tid >> 5;
    const int grp  = tid >> 7;
    const int jc   = (tid & 127) * 4;

    if (tid < NN) su[tid] = 1.f/512.f;
    __syncthreads();

    for (int it = 0; it < 10; it++) {
        float a0 = 0.f, a1 = 0.f, a2 = 0.f, a3 = 0.f;
        const int i0 = grp * 64;
        const uint2* K2 = (const uint2*)Kb;
        #pragma unroll 8
        for (int i = 0; i < 64; i++) {
            uint2 kq = K2[(((size_t)(i0 + i))*NN + jc) >> 2];
            float k0,k1,k2,k3;
            unpack_bf2(kq.x, k0, k1);
            unpack_bf2(kq.y, k2, k3);
            float ui = su[i0 + i];
            a0 = fmaf(k0, ui, a0);
            a1 = fmaf(k1, ui, a1);
            a2 = fmaf(k2, ui, a2);
            a3 = fmaf(k3, ui, a3);
        }
        *(float4*)(&part[grp][jc]) = make_float4(a0,a1,a2,a3);
        __syncthreads();
        if (tid < NN) {
            float y = part[0][tid] + part[1][tid] + part[2][tid] + part[3][tid]
                    + part[4][tid] + part[5][tid] + part[6][tid] + part[7][tid];
            sv[tid] = (1.f/512.f) / y;
        }
        __syncthreads();
        for (int rr = 0; rr < 16; rr++) {
            int i = warp*16 + rr;
            const uint4* kr = (const uint4*)(Kb + (size_t)i*NN);
            uint4 q0 = kr[lane*2];
            uint4 q1 = kr[lane*2 + 1];
            float s = 0.f;
            float k0,k1;
            float4 vv;
            vv = *(const float4*)(sv + lane*16 + 0);
            unpack_bf2(q0.x, k0, k1); s = fmaf(k0, vv.x, s); s = fmaf(k1, vv.y, s);
            unpack_bf2(q0.y, k0, k1); s = fmaf(k0, vv.z, s); s = fmaf(k1, vv.w, s);
            vv = *(const float4*)(sv + lane*16 + 4);
            unpack_bf2(q0.z, k0, k1); s = fmaf(k0, vv.x, s); s = fmaf(k1, vv.y, s);
            unpack_bf2(q0.w, k0, k1); s = fmaf(k0, vv.z, s); s = fmaf(k1, vv.w, s);
            vv = *(const float4*)(sv + lane*16 + 8);
            unpack_bf2(q1.x, k0, k1); s = fmaf(k0, vv.x, s); s = fmaf(k1, vv.y, s);
            unpack_bf2(q1.y, k0, k1); s = fmaf(k0, vv.z, s); s = fmaf(k1, vv.w, s);
            vv = *(const float4*)(sv + lane*16 + 12);
            unpack_bf2(q1.z, k0, k1); s = fmaf(k0, vv.x, s); s = fmaf(k1, vv.y, s);
            unpack_bf2(q1.w, k0, k1); s = fmaf(k0, vv.z, s); s = fmaf(k1, vv.w, s);
            #pragma unroll
            for (int off = 16; off; off >>= 1)
                s += __shfl_xor_sync(0xffffffffu, s, off);
            if (lane == 0) su[i] = (1.f/512.f) / s;
        }
        __syncthreads();
    }

    const float* relb = rel + (size_t)b*NN*NN;
    float lacc = 0.f;
    for (int t = 0; t < 32; t++) {
        int idx = tid + t*1024;
        int e = idx * 8;
        int i = e >> 9;
        int j = e & 511;
        uint4 kq = ((const uint4*)Kb)[idx];
        float kf[8];
        unpack_bf2(kq.x, kf[0], kf[1]);
        unpack_bf2(kq.y, kf[2], kf[3]);
        unpack_bf2(kq.z, kf[4], kf[5]);
        unpack_bf2(kq.w, kf[6], kf[7]);
        float4 rv0 = *(const float4*)(relb + e);
        float4 rv1 = *(const float4*)(relb + e + 4);
        float ui  = su[i] * 512.f;
        float pai = pa[b*NN + i];
        float4 vv0 = *(const float4*)(sv + j);
        float4 vv1 = *(const float4*)(sv + j + 4);
        float d0 = ui*kf[0]*vv0.x - rv0.x;
        float d1 = ui*kf[1]*vv0.y - rv0.y;
        float d2 = ui*kf[2]*vv0.z - rv0.z;
        float d3 = ui*kf[3]*vv0.w - rv0.w;
        float d4 = ui*kf[4]*vv1.x - rv1.x;
        float d5 = ui*kf[5]*vv1.y - rv1.y;
        float d6 = ui*kf[6]*vv1.z - rv1.z;
        float d7 = ui*kf[7]*vv1.w - rv1.w;
        lacc += pai * (d0*d0 + d1*d1 + d2*d2 + d3*d3
                     + d4*d4 + d5*d5 + d6*d6 + d7*d7);
    }
    #pragma unroll
    for (int off = 16; off; off >>= 1)
        lacc += __shfl_xor_sync(0xffffffffu, lacc, off);
    if (lane == 0) sred[warp] = lacc;
    __syncthreads();
    if (tid == 0) {
        float s = 0.f;
        #pragma unroll
        for (int w = 0; w < 32; w++) s += sred[w];
        atomicAdd(&g_acc[2], (double)s);
    }
}

__global__ void finalize_kernel(const float* __restrict__ pa, float* __restrict__ out)
{
    __shared__ float red[256];
    float s = 0.f;
    for (int i = threadIdx.x; i < BSZ*NN; i += 256) s += pa[i];
    red[threadIdx.x] = s;
    __syncthreads();
    for (int off = 128; off; off >>= 1) {
        if (threadIdx.x < off) red[threadIdx.x] += red[threadIdx.x + off];
        __syncthreads();
    }
    if (threadIdx.x == 0) {
        double M = (double)BSZ * (double)NN * (double)NN;
        out[0] = (float)(g_acc[0]/M - g_acc[1]/M + 10.0*(g_acc[2]/(double)red[0]));
    }
}

extern "C" void kernel_launch(void* const* d_in, const int* in_sizes, int n_in,
                              void* d_out, int out_size)
{
    const float* la  = (const float*)d_in[0];
    const float* lb  = (const float*)d_in[1];
    const float* xA  = (const float*)d_in[2];
    const float* xB  = (const float*)d_in[3];
    const float* rel = (const float*)d_in[4];
    const float* pa  = (const float*)d_in[5];
    const float* pb  = (const float*)d_in[6];
    const float* W1  = (const float*)d_in[7];
    const float* b1  = (const float*)d_in[8];
    const float* g1  = (const float*)d_in[9];
    const float* be1 = (const float*)d_in[10];
    const float* W2  = (const float*)d_in[11];
    const float* b2  = (const float*)d_in[12];
    const float* g2  = (const float*)d_in[13];
    const float* be2 = (const float*)d_in[14];
    float* out = (float*)d_out;

    cudaFuncSetAttribute(embed_kernel,
                         cudaFuncAttributeMaxDynamicSharedMemorySize, EMBED_SMEM);

    zero_acc_kernel<<<1, 32>>>();
    class_argmax_kernel<<<(BSZ*NN + 255)/256, 256>>>(la, lb);
    embed_kernel<<<dim3(BSZ*NN/64, 2), 512, EMBED_SMEM>>>(
        xA, xB, W1, b1, g1, be1, W2, b2, g2, be2);
    cost_kernel<<<dim3(4, 4, BSZ), 256>>>(pa, pb);
    sinkhorn_kernel<<<BSZ, 1024>>>(rel, pa);
    finalize_kernel<<<1, 256>>>(pa, out);
}

// round 11
// speedup vs baseline: 1.2089x; 1.2089x over previous
#include <cuda_runtime.h>
#include <cuda_bf16.h>
#include <stdint.h>
#include <math.h>

#define BSZ 64
#define NN 512
#define DD 256
#define BIGC 1.0e9f

__device__ float g_eA[BSZ*NN*DD];
__device__ float g_eB[BSZ*NN*DD];
__device__ float g_nA[BSZ*NN];
__device__ float g_nB[BSZ*NN];
__device__ __nv_bfloat16 g_K[(size_t)BSZ*NN*NN];
__device__ int   g_cA[BSZ*NN];
__device__ int   g_cB[BSZ*NN];
__device__ double g_acc[3];

// ---- helpers ----
__device__ __forceinline__ uint32_t pack_bf2(float a, float b) {
    __nv_bfloat162 h = __floats2bfloat162_rn(a, b);
    return *reinterpret_cast<uint32_t*>(&h);
}
__device__ __forceinline__ void unpack_bf2(uint32_t u, float& a, float& b) {
    a = __uint_as_float(u << 16);
    b = __uint_as_float(u & 0xffff0000u);
}
__device__ __forceinline__ void cp_async16(void* smem_dst, const void* gmem_src) {
    uint32_t s = (uint32_t)__cvta_generic_to_shared(smem_dst);
    asm volatile("cp.async.cg.shared.global [%0], [%1], 16;" :: "r"(s), "l"(gmem_src));
}
__device__ __forceinline__ void cp_commit() {
    asm volatile("cp.async.commit_group;");
}
__device__ __forceinline__ void cp_wait0() {
    asm volatile("cp.async.wait_group 0;");
}
__device__ __forceinline__ void mma_tf32(float* c,
    uint32_t a0, uint32_t a1, uint32_t a2, uint32_t a3,
    uint32_t b0, uint32_t b1)
{
    asm volatile(
        "mma.sync.aligned.m16n8k8.row.col.f32.tf32.tf32.f32 "
        "{%0,%1,%2,%3}, {%4,%5,%6,%7}, {%8,%9}, {%0,%1,%2,%3};"
        : "+f"(c[0]), "+f"(c[1]), "+f"(c[2]), "+f"(c[3])
        : "r"(a0), "r"(a1), "r"(a2), "r"(a3), "r"(b0), "r"(b1));
}
__device__ __forceinline__ void dsmem_st_f32(const void* local_smem, uint32_t trank, float v) {
    uint32_t laddr = (uint32_t)__cvta_generic_to_shared(local_smem);
    uint32_t raddr;
    asm volatile("mapa.shared::cluster.u32 %0, %1, %2;" : "=r"(raddr) : "r"(laddr), "r"(trank));
    asm volatile("st.shared::cluster.f32 [%0], %1;" :: "r"(raddr), "f"(v) : "memory");
}
#define CLUSTER_SYNC() do { \
    asm volatile("barrier.cluster.arrive.aligned;" ::: "memory"); \
    asm volatile("barrier.cluster.wait.aligned;" ::: "memory"); } while(0)

__global__ void zero_acc_kernel() {
    if (threadIdx.x < 3) g_acc[threadIdx.x] = 0.0;
}

__global__ void class_argmax_kernel(const float* __restrict__ la,
                                    const float* __restrict__ lb) {
    int t = blockIdx.x * blockDim.x + threadIdx.x;
    if (t >= BSZ*NN) return;
    float4 a = ((const float4*)la)[t];
    int ba = 0; float bv = a.x;
    if (a.y > bv) { bv = a.y; ba = 1; }
    if (a.z > bv) { bv = a.z; ba = 2; }
    if (a.w > bv) { bv = a.w; ba = 3; }
    g_cA[t] = ba;
    float4 b = ((const float4*)lb)[t];
    int bb = 0; bv = b.x;
    if (b.y > bv) { bv = b.y; bb = 1; }
    if (b.z > bv) { bv = b.z; bb = 2; }
    if (b.w > bv) { bv = b.w; bb = 3; }
    g_cB[t] = bb;
}

__device__ __forceinline__ void ln_row(float v[8],
    const float4& g0, const float4& g1, const float4& e0, const float4& e1,
    float* o)
{
    float s = 0.f, sq = 0.f;
    #pragma unroll
    for (int j = 0; j < 8; j++) {
        v[j] = v[j] > 0.f ? v[j] : 0.01f * v[j];
        s += v[j]; sq += v[j]*v[j];
    }
    #pragma unroll
    for (int off = 16; off; off >>= 1) {
        s  += __shfl_xor_sync(0xffffffffu, s, off);
        sq += __shfl_xor_sync(0xffffffffu, sq, off);
    }
    float mean = s * (1.f/256.f);
    float var  = sq * (1.f/256.f) - mean*mean;
    float rstd = rsqrtf(var + 1e-5f);
    o[0] = (v[0]-mean)*rstd*g0.x + e0.x;
    o[1] = (v[1]-mean)*rstd*g0.y + e0.y;
    o[2] = (v[2]-mean)*rstd*g0.z + e0.z;
    o[3] = (v[3]-mean)*rstd*g0.w + e0.w;
    o[4] = (v[4]-mean)*rstd*g1.x + e1.x;
    o[5] = (v[5]-mean)*rstd*g1.y + e1.y;
    o[6] = (v[6]-mean)*rstd*g1.z + e1.z;
    o[7] = (v[7]-mean)*rstd*g1.w + e1.w;
}

// Fused 2-layer MLP+LN embed with tf32 mma.sync (R9 winner, 256 threads).
#define EMBED_SMEM ((64*256 + 2*16*256 + 2*64*16) * 4)

__global__ __launch_bounds__(256, 2)
void embed_kernel(const float* __restrict__ xA, const float* __restrict__ xB,
                  const float* __restrict__ W1, const float* __restrict__ b1,
                  const float* __restrict__ g1, const float* __restrict__ be1,
                  const float* __restrict__ W2, const float* __restrict__ b2,
                  const float* __restrict__ g2, const float* __restrict__ be2)
{
    extern __shared__ float sm[];
    float* Hs = sm;                  // 64*256 (swizzled)
    float* Ws = sm + 64*256;         // 2 x 16*256 (swizzled)
    float* Xs = Ws + 2*16*256;       // 2 x 64*16 (swizzled)

    const float* X  = blockIdx.y ? xB   : xA;
    float* E        = blockIdx.y ? g_eB : g_eA;
    float* NRM      = blockIdx.y ? g_nB : g_nA;

    const int tid  = threadIdx.x;
    const int lane = tid & 31;
    const int warp = tid >> 5;
    const int wm   = warp & 3;
    const int wn   = warp >> 2;
    const int g    = lane >> 2;
    const int t    = lane & 3;
    const int row0 = blockIdx.x * 64;

    const int xr = tid >> 2, xkq = (tid & 3) << 2;
    const int xdst = xr*16 + (xkq ^ (((xr>>1)&3)<<2));

    float c[16][4];
    #pragma unroll
    for (int j = 0; j < 16; j++)
        #pragma unroll
        for (int q = 0; q < 4; q++) c[j][q] = 0.f;

    {
        #pragma unroll
        for (int i = 0; i < 4; i++) {
            int f = tid + i*256;
            int k = f >> 6, n4 = (f & 63) << 2;
            cp_async16(Ws + k*256 + (n4 ^ ((k&3)<<3)), W1 + (size_t)k*256 + n4);
        }
        cp_async16(Xs + xdst, X + (size_t)(row0 + xr)*DD + xkq);
        cp_commit(); cp_wait0();
    }
    __syncthreads();

    for (int kt = 0; kt < 16; kt++) {
        const int cur = kt & 1, nxt = cur ^ 1;
        if (kt < 15) {
            const float* Wsrc = W1 + (size_t)(kt+1)*16*DD;
            float* Wdst = Ws + nxt*4096;
            #pragma unroll
            for (int i = 0; i < 4; i++) {
                int f = tid + i*256;
                int k = f >> 6, n4 = (f & 63) << 2;
                cp_async16(Wdst + k*256 + (n4 ^ ((k&3)<<3)), Wsrc + (size_t)k*256 + n4);
            }
            cp_async16(Xs + nxt*1024 + xdst,
                       X + (size_t)(row0 + xr)*DD + (kt+1)*16 + xkq);
            cp_commit();
        }
        const float* Wc = Ws + cur*4096;
        const float* Xc = Xs + cur*1024;
        const int sA = ((g>>1)&3) << 2;
        const int sB = t << 3;
        #pragma unroll
        for (int h = 0; h < 2; h++) {
            int kl = h*8 + t;
            uint32_t a0 = __float_as_uint(Xc[(wm*16+g  )*16 + ((kl  ) ^ sA)]);
            uint32_t a1 = __float_as_uint(Xc[(wm*16+g+8)*16 + ((kl  ) ^ sA)]);
            uint32_t a2 = __float_as_uint(Xc[(wm*16+g  )*16 + ((kl+4) ^ sA)]);
            uint32_t a3 = __float_as_uint(Xc[(wm*16+g+8)*16 + ((kl+4) ^ sA)]);
            const float* Wr0 = Wc + (kl  )*256;
            const float* Wr1 = Wc + (kl+4)*256;
            #pragma unroll
            for (int j = 0; j < 16; j++) {
                int n = wn*128 + j*8 + g;
                uint32_t b0 = __float_as_uint(Wr0[n ^ sB]);
                uint32_t b1 = __float_as_uint(Wr1[n ^ sB]);
                mma_tf32(c[j], a0, a1, a2, a3, b0, b1);
            }
        }
        if (kt < 15) cp_wait0();
        __syncthreads();
    }

    {
        #pragma unroll
        for (int i = 0; i < 4; i++) {
            int f = tid + i*256;
            int k = f >> 6, n4 = (f & 63) << 2;
            cp_async16(Ws + k*256 + (n4 ^ ((k&3)<<3)), W2 + (size_t)k*256 + n4);
        }
        cp_commit();
    }

    #pragma unroll
    for (int j = 0; j < 16; j++) {
        int r  = wm*16 + g;
        int cc = wn*128 + j*8 + 2*t;
        *(float2*)&Hs[r*256 + (cc ^ ((r&7)<<2))] = make_float2(c[j][0], c[j][1]);
        int r2 = r + 8;
        *(float2*)&Hs[r2*256 + (cc ^ ((r2&7)<<2))] = make_float2(c[j][2], c[j][3]);
    }
    __syncthreads();

    {
        const int c0 = lane*4, c1 = 128 + lane*4;
        float4 bv0 = *(const float4*)(b1 + c0), bv1 = *(const float4*)(b1 + c1);
        float4 gv0 = *(const float4*)(g1 + c0), gv1 = *(const float4*)(g1 + c1);
        float4 ev0 = *(const float4*)(be1 + c0), ev1 = *(const float4*)(be1 + c1);
        #pragma unroll
        for (int r = 0; r < 8; r++) {
            int row = warp*8 + r;
            int sH = (row & 7) << 2;
            float4 x0 = *(const float4*)&Hs[row*256 + (c0 ^ sH)];
            float4 x1 = *(const float4*)&Hs[row*256 + (c1 ^ sH)];
            float v[8], o[8];
            v[0]=x0.x+bv0.x; v[1]=x0.y+bv0.y; v[2]=x0.z+bv0.z; v[3]=x0.w+bv0.w;
            v[4]=x1.x+bv1.x; v[5]=x1.y+bv1.y; v[6]=x1.z+bv1.z; v[7]=x1.w+bv1.w;
            ln_row(v, gv0, gv1, ev0, ev1, o);
            *(float4*)&Hs[row*256 + (c0 ^ sH)] = make_float4(o[0],o[1],o[2],o[3]);
            *(float4*)&Hs[row*256 + (c1 ^ sH)] = make_float4(o[4],o[5],o[6],o[7]);
        }
    }
    cp_wait0();
    __syncthreads();

    #pragma unroll
    for (int j = 0; j < 16; j++)
        #pragma unroll
        for (int q = 0; q < 4; q++) c[j][q] = 0.f;

    for (int kt = 0; kt < 16; kt++) {
        const int cur = kt & 1, nxt = cur ^ 1;
        if (kt < 15) {
            const float* Wsrc = W2 + (size_t)(kt+1)*16*DD;
            float* Wdst = Ws + nxt*4096;
            #pragma unroll
            for (int i = 0; i < 4; i++) {
                int f = tid + i*256;
                int k = f >> 6, n4 = (f & 63) << 2;
                cp_async16(Wdst + k*256 + (n4 ^ ((k&3)<<3)), Wsrc + (size_t)k*256 + n4);
            }
            cp_commit();
        }
        const float* Wc = Ws + cur*4096;
        const float* H0 = Hs + (wm*16 + g  )*256;
        const float* H1 = Hs + (wm*16 + g+8)*256;
        const int sH = g << 2;
        const int sB = t << 3;
        #pragma unroll
        for (int h = 0; h < 2; h++) {
            int k = kt*16 + h*8;
            uint32_t a0 = __float_as_uint(H0[(k+t  ) ^ sH]);
            uint32_t a1 = __float_as_uint(H1[(k+t  ) ^ sH]);
            uint32_t a2 = __float_as_uint(H0[(k+t+4) ^ sH]);
            uint32_t a3 = __float_as_uint(H1[(k+t+4) ^ sH]);
            const float* Wr0 = Wc + (h*8+t  )*256;
            const float* Wr1 = Wc + (h*8+t+4)*256;
            #pragma unroll
            for (int j = 0; j < 16; j++) {
                int n = wn*128 + j*8 + g;
                uint32_t b0 = __float_as_uint(Wr0[n ^ sB]);
                uint32_t b1 = __float_as_uint(Wr1[n ^ sB]);
                mma_tf32(c[j], a0, a1, a2, a3, b0, b1);
            }
        }
        if (kt < 15) cp_wait0();
        __syncthreads();
    }

    #pragma unroll
    for (int j = 0; j < 16; j++) {
        int r  = wm*16 + g;
        int cc = wn*128 + j*8 + 2*t;
        *(float2*)&Hs[r*256 + (cc ^ ((r&7)<<2))] = make_float2(c[j][0], c[j][1]);
        int r2 = r + 8;
        *(float2*)&Hs[r2*256 + (cc ^ ((r2&7)<<2))] = make_float2(c[j][2], c[j][3]);
    }
    __syncthreads();

    {
        const int c0 = lane*4, c1 = 128 + lane*4;
        float4 bv0 = *(const float4*)(b2 + c0), bv1 = *(const float4*)(b2 + c1);
        float4 gv0 = *(const float4*)(g2 + c0), gv1 = *(const float4*)(g2 + c1);
        float4 ev0 = *(const float4*)(be2 + c0), ev1 = *(const float4*)(be2 + c1);
        #pragma unroll
        for (int r = 0; r < 8; r++) {
            int row = warp*8 + r;
            int sH = (row & 7) << 2;
            float4 x0 = *(const float4*)&Hs[row*256 + (c0 ^ sH)];
            float4 x1 = *(const float4*)&Hs[row*256 + (c1 ^ sH)];
            float v[8], o[8];
            v[0]=x0.x+bv0.x; v[1]=x0.y+bv0.y; v[2]=x0.z+bv0.z; v[3]=x0.w+bv0.w;
            v[4]=x1.x+bv1.x; v[5]=x1.y+bv1.y; v[6]=x1.z+bv1.z; v[7]=x1.w+bv1.w;
            ln_row(v, gv0, gv1, ev0, ev1, o);
            float ns = o[0]*o[0]+o[1]*o[1]+o[2]*o[2]+o[3]*o[3]
                     + o[4]*o[4]+o[5]*o[5]+o[6]*o[6]+o[7]*o[7];
            #pragma unroll
            for (int off = 16; off; off >>= 1)
                ns += __shfl_xor_sync(0xffffffffu, ns, off);
            size_t grow = (size_t)(row0 + row);
            *(float4*)(E + grow*DD + c0) = make_float4(o[0],o[1],o[2],o[3]);
            *(float4*)(E + grow*DD + c1) = make_float4(o[4],o[5],o[6],o[7]);
            if (lane == 0) NRM[grow] = ns;
        }
    }
}

// cdist + cost_class + in/out loss + K(bf16) via tf32 mma (unchanged R9 winner).
__global__ __launch_bounds__(256, 2)
void cost_kernel(const float* __restrict__ pa, const float* __restrict__ pb)
{
    __shared__ __align__(16) float As[2][128*16];
    __shared__ __align__(16) float Bs[2][128*16];
    __shared__ float redi[8], redo[8];

    const int b  = blockIdx.z;
    const int ti = blockIdx.y;
    const int tj = blockIdx.x;
    const int tid = threadIdx.x;
    const int lane = tid & 31;
    const int warp = tid >> 5;
    const int wm   = warp & 3;
    const int wn   = warp >> 2;
    const int g    = lane >> 2;
    const int t    = lane & 3;

    const float* Ab = g_eA + (size_t)b*NN*DD + (size_t)ti*128*DD;
    const float* Bb = g_eB + (size_t)b*NN*DD + (size_t)tj*128*DD;

    const int lr  = tid >> 2;
    const int lkq = (tid & 3) << 2;

    float c[2][8][4];
    #pragma unroll
    for (int m = 0; m < 2; m++)
        #pragma unroll
        for (int j = 0; j < 8; j++)
            #pragma unroll
            for (int q = 0; q < 4; q++) c[m][j][q] = 0.f;

    {
        #pragma unroll
        for (int i = 0; i < 2; i++) {
            int row = lr + i*64;
            int dst = row*16 + (lkq ^ (((row>>1)&3)<<2));
            cp_async16(&As[0][dst], Ab + (size_t)row*DD + lkq);
            cp_async16(&Bs[0][dst], Bb + (size_t)row*DD + lkq);
        }
        cp_commit(); cp_wait0();
    }
    __syncthreads();

    const int sA = ((g>>1)&3) << 2;

    for (int kt = 0; kt < 16; kt++) {
        const int cur = kt & 1, nxt = cur ^ 1;
        if (kt < 15) {
            #pragma unroll
            for (int i = 0; i < 2; i++) {
                int row = lr + i*64;
                int dst = row*16 + (lkq ^ (((row>>1)&3)<<2));
                cp_async16(&As[nxt][dst], Ab + (size_t)row*DD + (kt+1)*16 + lkq);
                cp_async16(&Bs[nxt][dst], Bb + (size_t)row*DD + (kt+1)*16 + lkq);
            }
            cp_commit();
        }
        const float* Ac = As[cur];
        const float* Bc = Bs[cur];
        #pragma unroll
        for (int h = 0; h < 2; h++) {
            int kl = h*8 + t;
            #pragma unroll
            for (int m = 0; m < 2; m++) {
                int r = wm*32 + m*16 + g;
                uint32_t a0 = __float_as_uint(Ac[(r  )*16 + ((kl  ) ^ sA)]);
                uint32_t a1 = __float_as_uint(Ac[(r+8)*16 + ((kl  ) ^ sA)]);
                uint32_t a2 = __float_as_uint(Ac[(r  )*16 + ((kl+4) ^ sA)]);
                uint32_t a3 = __float_as_uint(Ac[(r+8)*16 + ((kl+4) ^ sA)]);
                #pragma unroll
                for (int j = 0; j < 8; j++) {
                    int n = wn*64 + j*8 + g;
                    uint32_t b0 = __float_as_uint(Bc[n*16 + ((kl  ) ^ sA)]);
                    uint32_t b1 = __float_as_uint(Bc[n*16 + ((kl+4) ^ sA)]);
                    mma_tf32(c[m][j], a0, a1, a2, a3, b0, b1);
                }
            }
        }
        if (kt < 15) cp_wait0();
        __syncthreads();
    }

    float sin = 0.f, sout = 0.f;
    #pragma unroll
    for (int m = 0; m < 2; m++) {
        int il1 = ti*128 + wm*32 + m*16 + g;
        int il2 = il1 + 8;
        int gi1 = b*NN + il1, gi2 = b*NN + il2;
        float ni1 = g_nA[gi1], ni2 = g_nA[gi2];
        float pa1 = pa[gi1],   pa2 = pa[gi2];
        int   ca1 = g_cA[gi1], ca2 = g_cA[gi2];
        size_t rb1 = (size_t)gi1 * NN;
        size_t rb2 = (size_t)gi2 * NN;
        #pragma unroll
        for (int j = 0; j < 8; j++) {
            int jl = tj*128 + wn*64 + j*8 + 2*t;
            int gj = b*NN + jl;
            float nj0 = g_nB[gj], nj1 = g_nB[gj+1];
            float pb0 = pb[gj],   pb1 = pb[gj+1];
            int   cb0 = g_cB[gj], cb1 = g_cB[gj+1];

            float sq, cost, pm, cc, w;
            float k00, k01, k10, k11;

            sq = ni1 + nj0 - 2.f*c[m][j][0];
            cost = sqrtf(fmaxf(sq, 0.f));
            pm = pa1*pb0; cc = cost + (BIGC - BIGC*pm); w = cc*pm;
            if (ca1 == cb0) sin += w; else sout += w;
            k00 = __expf(-2.f*cc);

            sq = ni1 + nj1 - 2.f*c[m][j][1];
            cost = sqrtf(fmaxf(sq, 0.f));
            pm = pa1*pb1; cc = cost + (BIGC - BIGC*pm); w = cc*pm;
            if (ca1 == cb1) sin += w; else sout += w;
            k01 = __expf(-2.f*cc);

            sq = ni2 + nj0 - 2.f*c[m][j][2];
            cost = sqrtf(fmaxf(sq, 0.f));
            pm = pa2*pb0; cc = cost + (BIGC - BIGC*pm); w = cc*pm;
            if (ca2 == cb0) sin += w; else sout += w;
            k10 = __expf(-2.f*cc);

            sq = ni2 + nj1 - 2.f*c[m][j][3];
            cost = sqrtf(fmaxf(sq, 0.f));
            pm = pa2*pb1; cc = cost + (BIGC - BIGC*pm); w = cc*pm;
            if (ca2 == cb1) sin += w; else sout += w;
            k11 = __expf(-2.f*cc);

            *(uint32_t*)(g_K + rb1 + jl) = pack_bf2(k00, k01);
            *(uint32_t*)(g_K + rb2 + jl) = pack_bf2(k10, k11);
        }
    }
    #pragma unroll
    for (int off = 16; off; off >>= 1) {
        sin  += __shfl_xor_sync(0xffffffffu, sin,  off);
        sout += __shfl_xor_sync(0xffffffffu, sout, off);
    }
    if (lane == 0) { redi[warp] = sin; redo[warp] = sout; }
    __syncthreads();
    if (tid == 0) {
        float a = 0.f, o2 = 0.f;
        #pragma unroll
        for (int w = 0; w < 8; w++) { a += redi[w]; o2 += redo[w]; }
        atomicAdd(&g_acc[0], (double)a);
        atomicAdd(&g_acc[1], (double)o2);
    }
}

// Sinkhorn + fused sup loss, 2-CTA cluster per batch.
// Rank r owns K rows [r*256, r*256+256). Only column-partials are exchanged
// (DSMEM), u halves stay local. 1 cluster sync per iteration.
__global__ __launch_bounds__(512) __cluster_dims__(2, 1, 1)
void sinkhorn_kernel(const float* __restrict__ rel, const float* __restrict__ pa)
{
    __shared__ __align__(16) float su[256];        // own-half u
    __shared__ __align__(16) float sv[NN];         // full v (identical in both CTAs)
    __shared__ __align__(16) float part[4][NN];
    __shared__ __align__(16) float pvp[2][NN];     // peer partial (dbl-buffered)
    __shared__ float sred[16];

    uint32_t rank;
    asm("mov.u32 %0, %%cluster_ctarank;" : "=r"(rank));
    const uint32_t peer = rank ^ 1;
    const int b = blockIdx.x >> 1;
    const __nv_bfloat16* Kb = g_K + (size_t)b*NN*NN + (size_t)rank*256*NN;

    const int tid  = threadIdx.x;
    const int lane = tid & 31;
    const int warp = tid >> 5;
    const int grp  = tid >> 7;          // 0..3: 64 local rows each
    const int jc   = (tid & 127) * 4;   // owned 4 columns (within grp's 128 threads)

    if (tid < 256) su[tid] = 1.f/512.f;
    __syncthreads();
    CLUSTER_SYNC();   // smem (pvp) initialized/owned before any peer write lands

    for (int it = 0; it < 10; it++) {
        // ---- phase 1: partial col sums over own 256 rows ----
        float a0 = 0.f, a1 = 0.f, a2 = 0.f, a3 = 0.f;
        const int i0 = grp * 64;
        const uint2* K2 = (const uint2*)Kb;
        #pragma unroll 8
        for (int i = 0; i < 64; i++) {
            uint2 kq = K2[(((size_t)(i0 + i))*NN + jc) >> 2];
            float k0,k1,k2,k3;
            unpack_bf2(kq.x, k0, k1);
            unpack_bf2(kq.y, k2, k3);
            float ui = su[i0 + i];
            a0 = fmaf(k0, ui, a0);
            a1 = fmaf(k1, ui, a1);
            a2 = fmaf(k2, ui, a2);
            a3 = fmaf(k3, ui, a3);
        }
        *(float4*)(&part[grp][jc]) = make_float4(a0,a1,a2,a3);
        __syncthreads();
        // combine own 4 groups for column `tid`; exchange with peer
        float mypart = part[0][tid] + part[1][tid] + part[2][tid] + part[3][tid];
        dsmem_st_f32(&pvp[it & 1][tid], peer, mypart);
        CLUSTER_SYNC();
        {
            float y = mypart + pvp[it & 1][tid];
            sv[tid] = (1.f/512.f) / y;
        }
        __syncthreads();
        // ---- phase 2: u = a / (K v) for own rows; warp per row, 16 rows/warp ----
        for (int rr = 0; rr < 16; rr++) {
            int i = warp*16 + rr;
            const uint4* kr = (const uint4*)(Kb + (size_t)i*NN);
            uint4 q0 = kr[lane*2];
            uint4 q1 = kr[lane*2 + 1];
            float s = 0.f;
            float k0,k1;
            float4 vv;
            vv = *(const float4*)(sv + lane*16 + 0);
            unpack_bf2(q0.x, k0, k1); s = fmaf(k0, vv.x, s); s = fmaf(k1, vv.y, s);
            unpack_bf2(q0.y, k0, k1); s = fmaf(k0, vv.z, s); s = fmaf(k1, vv.w, s);
            vv = *(const float4*)(sv + lane*16 + 4);
            unpack_bf2(q0.z, k0, k1); s = fmaf(k0, vv.x, s); s = fmaf(k1, vv.y, s);
            unpack_bf2(q0.w, k0, k1); s = fmaf(k0, vv.z, s); s = fmaf(k1, vv.w, s);
            vv = *(const float4*)(sv + lane*16 + 8);
            unpack_bf2(q1.x, k0, k1); s = fmaf(k0, vv.x, s); s = fmaf(k1, vv.y, s);
            unpack_bf2(q1.y, k0, k1); s = fmaf(k0, vv.z, s); s = fmaf(k1, vv.w, s);
            vv = *(const float4*)(sv + lane*16 + 12);
            unpack_bf2(q1.z, k0, k1); s = fmaf(k0, vv.x, s); s = fmaf(k1, vv.y, s);
            unpack_bf2(q1.w, k0, k1); s = fmaf(k0, vv.z, s); s = fmaf(k1, vv.w, s);
            #pragma unroll
            for (int off = 16; off; off >>= 1)
                s += __shfl_xor_sync(0xffffffffu, s, off);
            if (lane == 0) su[i] = (1.f/512.f) / s;
        }
        __syncthreads();
    }

    // ---- fused sup loss over own 256 rows (full v + own u are local) ----
    const float* relb = rel + (size_t)b*NN*NN + (size_t)rank*256*NN;
    const float* pab  = pa + b*NN + rank*256;
    float lacc = 0.f;
    // 256*512/8 = 16384 uint4 groups; 512 threads -> 32 each
    for (int t = 0; t < 32; t++) {
        int idx = tid + t*512;
        int e = idx * 8;
        int i = e >> 9;
        int j = e & 511;
        uint4 kq = ((const uint4*)Kb)[idx];
        float kf[8];
        unpack_bf2(kq.x, kf[0], kf[1]);
        unpack_bf2(kq.y, kf[2], kf[3]);
        unpack_bf2(kq.z, kf[4], kf[5]);
        unpack_bf2(kq.w, kf[6], kf[7]);
        float4 rv0 = *(const float4*)(relb + e);
        float4 rv1 = *(const float4*)(relb + e + 4);
        float ui  = su[i] * 512.f;
        float pai = pab[i];
        float4 vv0 = *(const float4*)(sv + j);
        float4 vv1 = *(const float4*)(sv + j + 4);
        float d0 = ui*kf[0]*vv0.x - rv0.x;
        float d1 = ui*kf[1]*vv0.y - rv0.y;
        float d2 = ui*kf[2]*vv0.z - rv0.z;
        float d3 = ui*kf[3]*vv0.w - rv0.w;
        float d4 = ui*kf[4]*vv1.x - rv1.x;
        float d5 = ui*kf[5]*vv1.y - rv1.y;
        float d6 = ui*kf[6]*vv1.z - rv1.z;
        float d7 = ui*kf[7]*vv1.w - rv1.w;
        lacc += pai * (d0*d0 + d1*d1 + d2*d2 + d3*d3
                     + d4*d4 + d5*d5 + d6*d6 + d7*d7);
    }
    #pragma unroll
    for (int off = 16; off; off >>= 1)
        lacc += __shfl_xor_sync(0xffffffffu, lacc, off);
    if (lane == 0) sred[warp] = lacc;
    __syncthreads();
    if (tid == 0) {
        float s = 0.f;
        #pragma unroll
        for (int w = 0; w < 16; w++) s += sred[w];
        atomicAdd(&g_acc[2], (double)s);
    }
    // no trailing cluster sync needed: after the last CLUSTER_SYNC both ranks
    // have stopped touching peer smem (sup phase is purely local).
    CLUSTER_SYNC();
}

__global__ void finalize_kernel(const float* __restrict__ pa, float* __restrict__ out)
{
    __shared__ float red[256];
    float s = 0.f;
    for (int i = threadIdx.x; i < BSZ*NN; i += 256) s += pa[i];
    red[threadIdx.x] = s;
    __syncthreads();
    for (int off = 128; off; off >>= 1) {
        if (threadIdx.x < off) red[threadIdx.x] += red[threadIdx.x + off];
        __syncthreads();
    }
    if (threadIdx.x == 0) {
        double M = (double)BSZ * (double)NN * (double)NN;
        out[0] = (float)(g_acc[0]/M - g_acc[1]/M + 10.0*(g_acc[2]/(double)red[0]));
    }
}

extern "C" void kernel_launch(void* const* d_in, const int* in_sizes, int n_in,
                              void* d_out, int out_size)
{
    const float* la  = (const float*)d_in[0];
    const float* lb  = (const float*)d_in[1];
    const float* xA  = (const float*)d_in[2];
    const float* xB  = (const float*)d_in[3];
    const float* rel = (const float*)d_in[4];
    const float* pa  = (const float*)d_in[5];
    const float* pb  = (const float*)d_in[6];
    const float* W1  = (const float*)d_in[7];
    const float* b1  = (const float*)d_in[8];
    const float* g1  = (const float*)d_in[9];
    const float* be1 = (const float*)d_in[10];
    const float* W2  = (const float*)d_in[11];
    const float* b2  = (const float*)d_in[12];
    const float* g2  = (const float*)d_in[13];
    const float* be2 = (const float*)d_in[14];
    float* out = (float*)d_out;

    cudaFuncSetAttribute(embed_kernel,
                         cudaFuncAttributeMaxDynamicSharedMemorySize, EMBED_SMEM);

    zero_acc_kernel<<<1, 32>>>();
    class_argmax_kernel<<<(BSZ*NN + 255)/256, 256>>>(la, lb);
    embed_kernel<<<dim3(BSZ*NN/64, 2), 256, EMBED_SMEM>>>(
        xA, xB, W1, b1, g1, be1, W2, b2, g2, be2);
    cost_kernel<<<dim3(4, 4, BSZ), 256>>>(pa, pb);
    sinkhorn_kernel<<<BSZ*2, 512>>>(rel, pa);
    finalize_kernel<<<1, 256>>>(pa, out);
}

// round 12
// speedup vs baseline: 1.3059x; 1.0802x over previous
#include <cuda_runtime.h>
#include <cuda_bf16.h>
#include <stdint.h>
#include <math.h>

#define BSZ 64
#define NN 512
#define DD 256
#define BIGC 1.0e9f

__device__ __align__(16) __nv_bfloat16 g_eAh[BSZ*NN*DD];
__device__ __align__(16) __nv_bfloat16 g_eBh[BSZ*NN*DD];
__device__ float g_nA[BSZ*NN];
__device__ float g_nB[BSZ*NN];
__device__ __nv_bfloat16 g_K[(size_t)BSZ*NN*NN];
__device__ int   g_cA[BSZ*NN];
__device__ int   g_cB[BSZ*NN];
__device__ double g_acc[3];

// ---- helpers ----
__device__ __forceinline__ uint32_t pack_bf2(float a, float b) {
    __nv_bfloat162 h = __floats2bfloat162_rn(a, b);
    return *reinterpret_cast<uint32_t*>(&h);
}
__device__ __forceinline__ void unpack_bf2(uint32_t u, float& a, float& b) {
    a = __uint_as_float(u << 16);
    b = __uint_as_float(u & 0xffff0000u);
}
__device__ __forceinline__ void cp_async16(void* smem_dst, const void* gmem_src) {
    uint32_t s = (uint32_t)__cvta_generic_to_shared(smem_dst);
    asm volatile("cp.async.cg.shared.global [%0], [%1], 16;" :: "r"(s), "l"(gmem_src));
}
__device__ __forceinline__ void cp_commit() {
    asm volatile("cp.async.commit_group;");
}
__device__ __forceinline__ void cp_wait0() {
    asm volatile("cp.async.wait_group 0;");
}
__device__ __forceinline__ void mma_tf32(float* c,
    uint32_t a0, uint32_t a1, uint32_t a2, uint32_t a3,
    uint32_t b0, uint32_t b1)
{
    asm volatile(
        "mma.sync.aligned.m16n8k8.row.col.f32.tf32.tf32.f32 "
        "{%0,%1,%2,%3}, {%4,%5,%6,%7}, {%8,%9}, {%0,%1,%2,%3};"
        : "+f"(c[0]), "+f"(c[1]), "+f"(c[2]), "+f"(c[3])
        : "r"(a0), "r"(a1), "r"(a2), "r"(a3), "r"(b0), "r"(b1));
}
__device__ __forceinline__ void mma_bf16(float* c,
    uint32_t a0, uint32_t a1, uint32_t a2, uint32_t a3,
    uint32_t b0, uint32_t b1)
{
    asm volatile(
        "mma.sync.aligned.m16n8k16.row.col.f32.bf16.bf16.f32 "
        "{%0,%1,%2,%3}, {%4,%5,%6,%7}, {%8,%9}, {%0,%1,%2,%3};"
        : "+f"(c[0]), "+f"(c[1]), "+f"(c[2]), "+f"(c[3])
        : "r"(a0), "r"(a1), "r"(a2), "r"(a3), "r"(b0), "r"(b1));
}
__device__ __forceinline__ void dsmem_st_f32(const void* local_smem, uint32_t trank, float v) {
    uint32_t laddr = (uint32_t)__cvta_generic_to_shared(local_smem);
    uint32_t raddr;
    asm volatile("mapa.shared::cluster.u32 %0, %1, %2;" : "=r"(raddr) : "r"(laddr), "r"(trank));
    asm volatile("st.shared::cluster.f32 [%0], %1;" :: "r"(raddr), "f"(v) : "memory");
}
#define CLUSTER_SYNC() do { \
    asm volatile("barrier.cluster.arrive.aligned;" ::: "memory"); \
    asm volatile("barrier.cluster.wait.aligned;" ::: "memory"); } while(0)

__global__ void zero_acc_kernel() {
    if (threadIdx.x < 3) g_acc[threadIdx.x] = 0.0;
}

__global__ void class_argmax_kernel(const float* __restrict__ la,
                                    const float* __restrict__ lb) {
    int t = blockIdx.x * blockDim.x + threadIdx.x;
    if (t >= BSZ*NN) return;
    float4 a = ((const float4*)la)[t];
    int ba = 0; float bv = a.x;
    if (a.y > bv) { bv = a.y; ba = 1; }
    if (a.z > bv) { bv = a.z; ba = 2; }
    if (a.w > bv) { bv = a.w; ba = 3; }
    g_cA[t] = ba;
    float4 b = ((const float4*)lb)[t];
    int bb = 0; bv = b.x;
    if (b.y > bv) { bv = b.y; bb = 1; }
    if (b.z > bv) { bv = b.z; bb = 2; }
    if (b.w > bv) { bv = b.w; bb = 3; }
    g_cB[t] = bb;
}

__device__ __forceinline__ void ln_row(float v[8],
    const float4& g0, const float4& g1, const float4& e0, const float4& e1,
    float* o)
{
    float s = 0.f, sq = 0.f;
    #pragma unroll
    for (int j = 0; j < 8; j++) {
        v[j] = v[j] > 0.f ? v[j] : 0.01f * v[j];
        s += v[j]; sq += v[j]*v[j];
    }
    #pragma unroll
    for (int off = 16; off; off >>= 1) {
        s  += __shfl_xor_sync(0xffffffffu, s, off);
        sq += __shfl_xor_sync(0xffffffffu, sq, off);
    }
    float mean = s * (1.f/256.f);
    float var  = sq * (1.f/256.f) - mean*mean;
    float rstd = rsqrtf(var + 1e-5f);
    o[0] = (v[0]-mean)*rstd*g0.x + e0.x;
    o[1] = (v[1]-mean)*rstd*g0.y + e0.y;
    o[2] = (v[2]-mean)*rstd*g0.z + e0.z;
    o[3] = (v[3]-mean)*rstd*g0.w + e0.w;
    o[4] = (v[4]-mean)*rstd*g1.x + e1.x;
    o[5] = (v[5]-mean)*rstd*g1.y + e1.y;
    o[6] = (v[6]-mean)*rstd*g1.z + e1.z;
    o[7] = (v[7]-mean)*rstd*g1.w + e1.w;
}

// Fused 2-layer MLP+LN embed with tf32 mma.sync (R9/R11 winner); final
// embeddings now stored as bf16 (norms stay fp32, computed pre-conversion).
#define EMBED_SMEM ((64*256 + 2*16*256 + 2*64*16) * 4)

__global__ __launch_bounds__(256, 2)
void embed_kernel(const float* __restrict__ xA, const float* __restrict__ xB,
                  const float* __restrict__ W1, const float* __restrict__ b1,
                  const float* __restrict__ g1, const float* __restrict__ be1,
                  const float* __restrict__ W2, const float* __restrict__ b2,
                  const float* __restrict__ g2, const float* __restrict__ be2)
{
    extern __shared__ float sm[];
    float* Hs = sm;                  // 64*256 (swizzled)
    float* Ws = sm + 64*256;         // 2 x 16*256 (swizzled)
    float* Xs = Ws + 2*16*256;       // 2 x 64*16 (swizzled)

    const float* X      = blockIdx.y ? xB    : xA;
    __nv_bfloat16* E    = blockIdx.y ? g_eBh : g_eAh;
    float* NRM          = blockIdx.y ? g_nB  : g_nA;

    const int tid  = threadIdx.x;
    const int lane = tid & 31;
    const int warp = tid >> 5;
    const int wm   = warp & 3;
    const int wn   = warp >> 2;
    const int g    = lane >> 2;
    const int t    = lane & 3;
    const int row0 = blockIdx.x * 64;

    const int xr = tid >> 2, xkq = (tid & 3) << 2;
    const int xdst = xr*16 + (xkq ^ (((xr>>1)&3)<<2));

    float c[16][4];
    #pragma unroll
    for (int j = 0; j < 16; j++)
        #pragma unroll
        for (int q = 0; q < 4; q++) c[j][q] = 0.f;

    {
        #pragma unroll
        for (int i = 0; i < 4; i++) {
            int f = tid + i*256;
            int k = f >> 6, n4 = (f & 63) << 2;
            cp_async16(Ws + k*256 + (n4 ^ ((k&3)<<3)), W1 + (size_t)k*256 + n4);
        }
        cp_async16(Xs + xdst, X + (size_t)(row0 + xr)*DD + xkq);
        cp_commit(); cp_wait0();
    }
    __syncthreads();

    for (int kt = 0; kt < 16; kt++) {
        const int cur = kt & 1, nxt = cur ^ 1;
        if (kt < 15) {
            const float* Wsrc = W1 + (size_t)(kt+1)*16*DD;
            float* Wdst = Ws + nxt*4096;
            #pragma unroll
            for (int i = 0; i < 4; i++) {
                int f = tid + i*256;
                int k = f >> 6, n4 = (f & 63) << 2;
                cp_async16(Wdst + k*256 + (n4 ^ ((k&3)<<3)), Wsrc + (size_t)k*256 + n4);
            }
            cp_async16(Xs + nxt*1024 + xdst,
                       X + (size_t)(row0 + xr)*DD + (kt+1)*16 + xkq);
            cp_commit();
        }
        const float* Wc = Ws + cur*4096;
        const float* Xc = Xs + cur*1024;
        const int sA = ((g>>1)&3) << 2;
        const int sB = t << 3;
        #pragma unroll
        for (int h = 0; h < 2; h++) {
            int kl = h*8 + t;
            uint32_t a0 = __float_as_uint(Xc[(wm*16+g  )*16 + ((kl  ) ^ sA)]);
            uint32_t a1 = __float_as_uint(Xc[(wm*16+g+8)*16 + ((kl  ) ^ sA)]);
            uint32_t a2 = __float_as_uint(Xc[(wm*16+g  )*16 + ((kl+4) ^ sA)]);
            uint32_t a3 = __float_as_uint(Xc[(wm*16+g+8)*16 + ((kl+4) ^ sA)]);
            const float* Wr0 = Wc + (kl  )*256;
            const float* Wr1 = Wc + (kl+4)*256;
            #pragma unroll
            for (int j = 0; j < 16; j++) {
                int n = wn*128 + j*8 + g;
                uint32_t b0 = __float_as_uint(Wr0[n ^ sB]);
                uint32_t b1 = __float_as_uint(Wr1[n ^ sB]);
                mma_tf32(c[j], a0, a1, a2, a3, b0, b1);
            }
        }
        if (kt < 15) cp_wait0();
        __syncthreads();
    }

    {
        #pragma unroll
        for (int i = 0; i < 4; i++) {
            int f = tid + i*256;
            int k = f >> 6, n4 = (f & 63) << 2;
            cp_async16(Ws + k*256 + (n4 ^ ((k&3)<<3)), W2 + (size_t)k*256 + n4);
        }
        cp_commit();
    }

    #pragma unroll
    for (int j = 0; j < 16; j++) {
        int r  = wm*16 + g;
        int cc = wn*128 + j*8 + 2*t;
        *(float2*)&Hs[r*256 + (cc ^ ((r&7)<<2))] = make_float2(c[j][0], c[j][1]);
        int r2 = r + 8;
        *(float2*)&Hs[r2*256 + (cc ^ ((r2&7)<<2))] = make_float2(c[j][2], c[j][3]);
    }
    __syncthreads();

    {
        const int c0 = lane*4, c1 = 128 + lane*4;
        float4 bv0 = *(const float4*)(b1 + c0), bv1 = *(const float4*)(b1 + c1);
        float4 gv0 = *(const float4*)(g1 + c0), gv1 = *(const float4*)(g1 + c1);
        float4 ev0 = *(const float4*)(be1 + c0), ev1 = *(const float4*)(be1 + c1);
        #pragma unroll
        for (int r = 0; r < 8; r++) {
            int row = warp*8 + r;
            int sH = (row & 7) << 2;
            float4 x0 = *(const float4*)&Hs[row*256 + (c0 ^ sH)];
            float4 x1 = *(const float4*)&Hs[row*256 + (c1 ^ sH)];
            float v[8], o[8];
            v[0]=x0.x+bv0.x; v[1]=x0.y+bv0.y; v[2]=x0.z+bv0.z; v[3]=x0.w+bv0.w;
            v[4]=x1.x+bv1.x; v[5]=x1.y+bv1.y; v[6]=x1.z+bv1.z; v[7]=x1.w+bv1.w;
            ln_row(v, gv0, gv1, ev0, ev1, o);
            *(float4*)&Hs[row*256 + (c0 ^ sH)] = make_float4(o[0],o[1],o[2],o[3]);
            *(float4*)&Hs[row*256 + (c1 ^ sH)] = make_float4(o[4],o[5],o[6],o[7]);
        }
    }
    cp_wait0();
    __syncthreads();

    #pragma unroll
    for (int j = 0; j < 16; j++)
        #pragma unroll
        for (int q = 0; q < 4; q++) c[j][q] = 0.f;

    for (int kt = 0; kt < 16; kt++) {
        const int cur = kt & 1, nxt = cur ^ 1;
        if (kt < 15) {
            const float* Wsrc = W2 + (size_t)(kt+1)*16*DD;
            float* Wdst = Ws + nxt*4096;
            #pragma unroll
            for (int i = 0; i < 4; i++) {
                int f = tid + i*256;
                int k = f >> 6, n4 = (f & 63) << 2;
                cp_async16(Wdst + k*256 + (n4 ^ ((k&3)<<3)), Wsrc + (size_t)k*256 + n4);
            }
            cp_commit();
        }
        const float* Wc = Ws + cur*4096;
        const float* H0 = Hs + (wm*16 + g  )*256;
        const float* H1 = Hs + (wm*16 + g+8)*256;
        const int sH = g << 2;
        const int sB = t << 3;
        #pragma unroll
        for (int h = 0; h < 2; h++) {
            int k = kt*16 + h*8;
            uint32_t a0 = __float_as_uint(H0[(k+t  ) ^ sH]);
            uint32_t a1 = __float_as_uint(H1[(k+t  ) ^ sH]);
            uint32_t a2 = __float_as_uint(H0[(k+t+4) ^ sH]);
            uint32_t a3 = __float_as_uint(H1[(k+t+4) ^ sH]);
            const float* Wr0 = Wc + (h*8+t  )*256;
            const float* Wr1 = Wc + (h*8+t+4)*256;
            #pragma unroll
            for (int j = 0; j < 16; j++) {
                int n = wn*128 + j*8 + g;
                uint32_t b0 = __float_as_uint(Wr0[n ^ sB]);
                uint32_t b1 = __float_as_uint(Wr1[n ^ sB]);
                mma_tf32(c[j], a0, a1, a2, a3, b0, b1);
            }
        }
        if (kt < 15) cp_wait0();
        __syncthreads();
    }

    #pragma unroll
    for (int j = 0; j < 16; j++) {
        int r  = wm*16 + g;
        int cc = wn*128 + j*8 + 2*t;
        *(float2*)&Hs[r*256 + (cc ^ ((r&7)<<2))] = make_float2(c[j][0], c[j][1]);
        int r2 = r + 8;
        *(float2*)&Hs[r2*256 + (cc ^ ((r2&7)<<2))] = make_float2(c[j][2], c[j][3]);
    }
    __syncthreads();

    {
        const int c0 = lane*4, c1 = 128 + lane*4;
        float4 bv0 = *(const float4*)(b2 + c0), bv1 = *(const float4*)(b2 + c1);
        float4 gv0 = *(const float4*)(g2 + c0), gv1 = *(const float4*)(g2 + c1);
        float4 ev0 = *(const float4*)(be2 + c0), ev1 = *(const float4*)(be2 + c1);
        #pragma unroll
        for (int r = 0; r < 8; r++) {
            int row = warp*8 + r;
            int sH = (row & 7) << 2;
            float4 x0 = *(const float4*)&Hs[row*256 + (c0 ^ sH)];
            float4 x1 = *(const float4*)&Hs[row*256 + (c1 ^ sH)];
            float v[8], o[8];
            v[0]=x0.x+bv0.x; v[1]=x0.y+bv0.y; v[2]=x0.z+bv0.z; v[3]=x0.w+bv0.w;
            v[4]=x1.x+bv1.x; v[5]=x1.y+bv1.y; v[6]=x1.z+bv1.z; v[7]=x1.w+bv1.w;
            ln_row(v, gv0, gv1, ev0, ev1, o);
            float ns = o[0]*o[0]+o[1]*o[1]+o[2]*o[2]+o[3]*o[3]
                     + o[4]*o[4]+o[5]*o[5]+o[6]*o[6]+o[7]*o[7];
            #pragma unroll
            for (int off = 16; off; off >>= 1)
                ns += __shfl_xor_sync(0xffffffffu, ns, off);
            size_t grow = (size_t)(row0 + row);
            uint2 p0, p1;
            p0.x = pack_bf2(o[0], o[1]); p0.y = pack_bf2(o[2], o[3]);
            p1.x = pack_bf2(o[4], o[5]); p1.y = pack_bf2(o[6], o[7]);
            *(uint2*)(E + grow*DD + c0) = p0;
            *(uint2*)(E + grow*DD + c1) = p1;
            if (lane == 0) NRM[grow] = ns;
        }
    }
}

// cdist + cost_class + in/out loss + K(bf16) via bf16 mma.sync m16n8k16.
// 128x128 tile, 8 warps (4x2), warp tile 32x64, K-chunk 32, double-buffered.
// Smem: [128 rows][16 granules(=32 bf16)] per buffer; granule swizzle
// kg -> kg ^ (((row>>1)&3)<<2)  (conflict-free for all fragment classes).
__global__ __launch_bounds__(256, 2)
void cost_kernel(const float* __restrict__ pa, const float* __restrict__ pb)
{
    __shared__ __align__(16) uint32_t As[2][128*16];
    __shared__ __align__(16) uint32_t Bs[2][128*16];
    __shared__ float redi[8], redo[8];

    const int b  = blockIdx.z;
    const int ti = blockIdx.y;
    const int tj = blockIdx.x;
    const int tid = threadIdx.x;
    const int lane = tid & 31;
    const int warp = tid >> 5;
    const int wm   = warp & 3;
    const int wn   = warp >> 2;
    const int g    = lane >> 2;
    const int t    = lane & 3;

    const __nv_bfloat16* Ab = g_eAh + (size_t)b*NN*DD + (size_t)ti*128*DD;
    const __nv_bfloat16* Bb = g_eBh + (size_t)b*NN*DD + (size_t)tj*128*DD;

    float c[2][8][4];
    #pragma unroll
    for (int m = 0; m < 2; m++)
        #pragma unroll
        for (int j = 0; j < 8; j++)
            #pragma unroll
            for (int q = 0; q < 4; q++) c[m][j][q] = 0.f;

    // loader: 512 16B-chunks per tile, 2 per thread; chunk ch -> row=ch>>2, q=ch&3
    {
        #pragma unroll
        for (int i = 0; i < 2; i++) {
            int ch = tid + i*256;
            int row = ch >> 2, q = ch & 3;
            int dstg = row*16 + ((q*4) ^ (((row>>1)&3)<<2));
            cp_async16(&As[0][dstg], Ab + (size_t)row*DD + q*8);
            cp_async16(&Bs[0][dstg], Bb + (size_t)row*DD + q*8);
        }
        cp_commit(); cp_wait0();
    }
    __syncthreads();

    const int sw = ((g>>1)&3) << 2;   // granule swizzle (same for all our rows/cols)

    for (int kt = 0; kt < 8; kt++) {      // K-chunk = 32
        const int cur = kt & 1, nxt = cur ^ 1;
        if (kt < 7) {
            #pragma unroll
            for (int i = 0; i < 2; i++) {
                int ch = tid + i*256;
                int row = ch >> 2, q = ch & 3;
                int dstg = row*16 + ((q*4) ^ (((row>>1)&3)<<2));
                cp_async16(&As[nxt][dstg], Ab + (size_t)row*DD + (kt+1)*32 + q*8);
                cp_async16(&Bs[nxt][dstg], Bb + (size_t)row*DD + (kt+1)*32 + q*8);
            }
            cp_commit();
        }
        const uint32_t* Ac = As[cur];
        const uint32_t* Bc = Bs[cur];
        #pragma unroll
        for (int h = 0; h < 2; h++) {     // two k16 sub-chunks
            const int gb = h*8;
            uint32_t a[2][4];
            #pragma unroll
            for (int m = 0; m < 2; m++) {
                int r = wm*32 + m*16 + g;
                a[m][0] = Ac[(r  )*16 + ((gb+t  ) ^ sw)];
                a[m][1] = Ac[(r+8)*16 + ((gb+t  ) ^ sw)];
                a[m][2] = Ac[(r  )*16 + ((gb+t+4) ^ sw)];
                a[m][3] = Ac[(r+8)*16 + ((gb+t+4) ^ sw)];
            }
            #pragma unroll
            for (int j = 0; j < 8; j++) {
                int n = wn*64 + j*8 + g;
                uint32_t b0 = Bc[n*16 + ((gb+t  ) ^ sw)];
                uint32_t b1 = Bc[n*16 + ((gb+t+4) ^ sw)];
                mma_bf16(c[0][j], a[0][0], a[0][1], a[0][2], a[0][3], b0, b1);
                mma_bf16(c[1][j], a[1][0], a[1][1], a[1][2], a[1][3], b0, b1);
            }
        }
        if (kt < 7) cp_wait0();
        __syncthreads();
    }

    // epilogue from fragments (layout identical to m16n8k8 case)
    float sin = 0.f, sout = 0.f;
    #pragma unroll
    for (int m = 0; m < 2; m++) {
        int il1 = ti*128 + wm*32 + m*16 + g;
        int il2 = il1 + 8;
        int gi1 = b*NN + il1, gi2 = b*NN + il2;
        float ni1 = g_nA[gi1], ni2 = g_nA[gi2];
        float pa1 = pa[gi1],   pa2 = pa[gi2];
        int   ca1 = g_cA[gi1], ca2 = g_cA[gi2];
        size_t rb1 = (size_t)gi1 * NN;
        size_t rb2 = (size_t)gi2 * NN;
        #pragma unroll
        for (int j = 0; j < 8; j++) {
            int jl = tj*128 + wn*64 + j*8 + 2*t;
            int gj = b*NN + jl;
            float nj0 = g_nB[gj], nj1 = g_nB[gj+1];
            float pb0 = pb[gj],   pb1 = pb[gj+1];
            int   cb0 = g_cB[gj], cb1 = g_cB[gj+1];

            float sq, cost, pm, cc, w;
            float k00, k01, k10, k11;

            sq = ni1 + nj0 - 2.f*c[m][j][0];
            cost = sqrtf(fmaxf(sq, 0.f));
            pm = pa1*pb0; cc = cost + (BIGC - BIGC*pm); w = cc*pm;
            if (ca1 == cb0) sin += w; else sout += w;
            k00 = __expf(-2.f*cc);

            sq = ni1 + nj1 - 2.f*c[m][j][1];
            cost = sqrtf(fmaxf(sq, 0.f));
            pm = pa1*pb1; cc = cost + (BIGC - BIGC*pm); w = cc*pm;
            if (ca1 == cb1) sin += w; else sout += w;
            k01 = __expf(-2.f*cc);

            sq = ni2 + nj0 - 2.f*c[m][j][2];
            cost = sqrtf(fmaxf(sq, 0.f));
            pm = pa2*pb0; cc = cost + (BIGC - BIGC*pm); w = cc*pm;
            if (ca2 == cb0) sin += w; else sout += w;
            k10 = __expf(-2.f*cc);

            sq = ni2 + nj1 - 2.f*c[m][j][3];
            cost = sqrtf(fmaxf(sq, 0.f));
            pm = pa2*pb1; cc = cost + (BIGC - BIGC*pm); w = cc*pm;
            if (ca2 == cb1) sin += w; else sout += w;
            k11 = __expf(-2.f*cc);

            *(uint32_t*)(g_K + rb1 + jl) = pack_bf2(k00, k01);
            *(uint32_t*)(g_K + rb2 + jl) = pack_bf2(k10, k11);
        }
    }
    #pragma unroll
    for (int off = 16; off; off >>= 1) {
        sin  += __shfl_xor_sync(0xffffffffu, sin,  off);
        sout += __shfl_xor_sync(0xffffffffu, sout, off);
    }
    if (lane == 0) { redi[warp] = sin; redo[warp] = sout; }
    __syncthreads();
    if (tid == 0) {
        float a = 0.f, o2 = 0.f;
        #pragma unroll
        for (int w = 0; w < 8; w++) { a += redi[w]; o2 += redo[w]; }
        atomicAdd(&g_acc[0], (double)a);
        atomicAdd(&g_acc[1], (double)o2);
    }
}

// Sinkhorn + fused sup loss, 2-CTA cluster per batch (unchanged R11 winner).
__global__ __launch_bounds__(512) __cluster_dims__(2, 1, 1)
void sinkhorn_kernel(const float* __restrict__ rel, const float* __restrict__ pa)
{
    __shared__ __align__(16) float su[256];
    __shared__ __align__(16) float sv[NN];
    __shared__ __align__(16) float part[4][NN];
    __shared__ __align__(16) float pvp[2][NN];
    __shared__ float sred[16];

    uint32_t rank;
    asm("mov.u32 %0, %%cluster_ctarank;" : "=r"(rank));
    const uint32_t peer = rank ^ 1;
    const int b = blockIdx.x >> 1;
    const __nv_bfloat16* Kb = g_K + (size_t)b*NN*NN + (size_t)rank*256*NN;

    const int tid  = threadIdx.x;
    const int lane = tid & 31;
    const int warp = tid >> 5;
    const int grp  = tid >> 7;
    const int jc   = (tid & 127) * 4;

    if (tid < 256) su[tid] = 1.f/512.f;
    __syncthreads();
    CLUSTER_SYNC();

    for (int it = 0; it < 10; it++) {
        float a0 = 0.f, a1 = 0.f, a2 = 0.f, a3 = 0.f;
        const int i0 = grp * 64;
        const uint2* K2 = (const uint2*)Kb;
        #pragma unroll 8
        for (int i = 0; i < 64; i++) {
            uint2 kq = K2[(((size_t)(i0 + i))*NN + jc) >> 2];
            float k0,k1,k2,k3;
            unpack_bf2(kq.x, k0, k1);
            unpack_bf2(kq.y, k2, k3);
            float ui = su[i0 + i];
            a0 = fmaf(k0, ui, a0);
            a1 = fmaf(k1, ui, a1);
            a2 = fmaf(k2, ui, a2);
            a3 = fmaf(k3, ui, a3);
        }
        *(float4*)(&part[grp][jc]) = make_float4(a0,a1,a2,a3);
        __syncthreads();
        float mypart = part[0][tid] + part[1][tid] + part[2][tid] + part[3][tid];
        dsmem_st_f32(&pvp[it & 1][tid], peer, mypart);
        CLUSTER_SYNC();
        {
            float y = mypart + pvp[it & 1][tid];
            sv[tid] = (1.f/512.f) / y;
        }
        __syncthreads();
        for (int rr = 0; rr < 16; rr++) {
            int i = warp*16 + rr;
            const uint4* kr = (const uint4*)(Kb + (size_t)i*NN);
            uint4 q0 = kr[lane*2];
            uint4 q1 = kr[lane*2 + 1];
            float s = 0.f;
            float k0,k1;
            float4 vv;
            vv = *(const float4*)(sv + lane*16 + 0);
            unpack_bf2(q0.x, k0, k1); s = fmaf(k0, vv.x, s); s = fmaf(k1, vv.y, s);
            unpack_bf2(q0.y, k0, k1); s = fmaf(k0, vv.z, s); s = fmaf(k1, vv.w, s);
            vv = *(const float4*)(sv + lane*16 + 4);
            unpack_bf2(q0.z, k0, k1); s = fmaf(k0, vv.x, s); s = fmaf(k1, vv.y, s);
            unpack_bf2(q0.w, k0, k1); s = fmaf(k0, vv.z, s); s = fmaf(k1, vv.w, s);
            vv = *(const float4*)(sv + lane*16 + 8);
            unpack_bf2(q1.x, k0, k1); s = fmaf(k0, vv.x, s); s = fmaf(k1, vv.y, s);
            unpack_bf2(q1.y, k0, k1); s = fmaf(k0, vv.z, s); s = fmaf(k1, vv.w, s);
            vv = *(const float4*)(sv + lane*16 + 12);
            unpack_bf2(q1.z, k0, k1); s = fmaf(k0, vv.x, s); s = fmaf(k1, vv.y, s);
            unpack_bf2(q1.w, k0, k1); s = fmaf(k0, vv.z, s); s = fmaf(k1, vv.w, s);
            #pragma unroll
            for (int off = 16; off; off >>= 1)
                s += __shfl_xor_sync(0xffffffffu, s, off);
            if (lane == 0) su[i] = (1.f/512.f) / s;
        }
        __syncthreads();
    }

    const float* relb = rel + (size_t)b*NN*NN + (size_t)rank*256*NN;
    const float* pab  = pa + b*NN + rank*256;
    float lacc = 0.f;
    for (int t = 0; t < 32; t++) {
        int idx = tid + t*512;
        int e = idx * 8;
        int i = e >> 9;
        int j = e & 511;
        uint4 kq = ((const uint4*)Kb)[idx];
        float kf[8];
        unpack_bf2(kq.x, kf[0], kf[1]);
        unpack_bf2(kq.y, kf[2], kf[3]);
        unpack_bf2(kq.z, kf[4], kf[5]);
        unpack_bf2(kq.w, kf[6], kf[7]);
        float4 rv0 = *(const float4*)(relb + e);
        float4 rv1 = *(const float4*)(relb + e + 4);
        float ui  = su[i] * 512.f;
        float pai = pab[i];
        float4 vv0 = *(const float4*)(sv + j);
        float4 vv1 = *(const float4*)(sv + j + 4);
        float d0 = ui*kf[0]*vv0.x - rv0.x;
        float d1 = ui*kf[1]*vv0.y - rv0.y;
        float d2 = ui*kf[2]*vv0.z - rv0.z;
        float d3 = ui*kf[3]*vv0.w - rv0.w;
        float d4 = ui*kf[4]*vv1.x - rv1.x;
        float d5 = ui*kf[5]*vv1.y - rv1.y;
        float d6 = ui*kf[6]*vv1.z - rv1.z;
        float d7 = ui*kf[7]*vv1.w - rv1.w;
        lacc += pai * (d0*d0 + d1*d1 + d2*d2 + d3*d3
                     + d4*d4 + d5*d5 + d6*d6 + d7*d7);
    }
    #pragma unroll
    for (int off = 16; off; off >>= 1)
        lacc += __shfl_xor_sync(0xffffffffu, lacc, off);
    if (lane == 0) sred[warp] = lacc;
    __syncthreads();
    if (tid == 0) {
        float s = 0.f;
        #pragma unroll
        for (int w = 0; w < 16; w++) s += sred[w];
        atomicAdd(&g_acc[2], (double)s);
    }
    CLUSTER_SYNC();
}

__global__ void finalize_kernel(const float* __restrict__ pa, float* __restrict__ out)
{
    __shared__ float red[256];
    float s = 0.f;
    for (int i = threadIdx.x; i < BSZ*NN; i += 256) s += pa[i];
    red[threadIdx.x] = s;
    __syncthreads();
    for (int off = 128; off; off >>= 1) {
        if (threadIdx.x < off) red[threadIdx.x] += red[threadIdx.x + off];
        __syncthreads();
    }
    if (threadIdx.x == 0) {
        double M = (double)BSZ * (double)NN * (double)NN;
        out[0] = (float)(g_acc[0]/M - g_acc[1]/M + 10.0*(g_acc[2]/(double)red[0]));
    }
}

extern "C" void kernel_launch(void* const* d_in, const int* in_sizes, int n_in,
                              void* d_out, int out_size)
{
    const float* la  = (const float*)d_in[0];
    const float* lb  = (const float*)d_in[1];
    const float* xA  = (const float*)d_in[2];
    const float* xB  = (const float*)d_in[3];
    const float* rel = (const float*)d_in[4];
    const float* pa  = (const float*)d_in[5];
    const float* pb  = (const float*)d_in[6];
    const float* W1  = (const float*)d_in[7];
    const float* b1  = (const float*)d_in[8];
    const float* g1  = (const float*)d_in[9];
    const float* be1 = (const float*)d_in[10];
    const float* W2  = (const float*)d_in[11];
    const float* b2  = (const float*)d_in[12];
    const float* g2  = (const float*)d_in[13];
    const float* be2 = (const float*)d_in[14];
    float* out = (float*)d_out;

    cudaFuncSetAttribute(embed_kernel,
                         cudaFuncAttributeMaxDynamicSharedMemorySize, EMBED_SMEM);

    zero_acc_kernel<<<1, 32>>>();
    class_argmax_kernel<<<(BSZ*NN + 255)/256, 256>>>(la, lb);
    embed_kernel<<<dim3(BSZ*NN/64, 2), 256, EMBED_SMEM>>>(
        xA, xB, W1, b1, g1, be1, W2, b2, g2, be2);
    cost_kernel<<<dim3(4, 4, BSZ), 256>>>(pa, pb);
    sinkhorn_kernel<<<BSZ*2, 512>>>(rel, pa);
    finalize_kernel<<<1, 256>>>(pa, out);
}

// round 13
// speedup vs baseline: 1.3433x; 1.0286x over previous
#include <cuda_runtime.h>
#include <cuda_bf16.h>
#include <stdint.h>
#include <math.h>

#define BSZ 64
#define NN 512
#define DD 256
#define BIGC 1.0e9f

__device__ __align__(16) __nv_bfloat16 g_eAh[BSZ*NN*DD];
__device__ __align__(16) __nv_bfloat16 g_eBh[BSZ*NN*DD];
__device__ __align__(16) __nv_bfloat16 g_xh[(size_t)2*BSZ*NN*DD];
__device__ __align__(16) __nv_bfloat16 g_W1t[DD*DD];
__device__ __align__(16) __nv_bfloat16 g_W2t[DD*DD];
__device__ float g_nA[BSZ*NN];
__device__ float g_nB[BSZ*NN];
__device__ __nv_bfloat16 g_K[(size_t)BSZ*NN*NN];
__device__ int   g_cA[BSZ*NN];
__device__ int   g_cB[BSZ*NN];
__device__ double g_acc[3];

// ---- helpers ----
__device__ __forceinline__ uint32_t pack_bf2(float a, float b) {
    __nv_bfloat162 h = __floats2bfloat162_rn(a, b);
    return *reinterpret_cast<uint32_t*>(&h);
}
__device__ __forceinline__ void unpack_bf2(uint32_t u, float& a, float& b) {
    a = __uint_as_float(u << 16);
    b = __uint_as_float(u & 0xffff0000u);
}
__device__ __forceinline__ void cp_async16(void* smem_dst, const void* gmem_src) {
    uint32_t s = (uint32_t)__cvta_generic_to_shared(smem_dst);
    asm volatile("cp.async.cg.shared.global [%0], [%1], 16;" :: "r"(s), "l"(gmem_src));
}
__device__ __forceinline__ void cp_commit() {
    asm volatile("cp.async.commit_group;");
}
__device__ __forceinline__ void cp_wait0() {
    asm volatile("cp.async.wait_group 0;");
}
__device__ __forceinline__ void mma_bf16(float* c,
    uint32_t a0, uint32_t a1, uint32_t a2, uint32_t a3,
    uint32_t b0, uint32_t b1)
{
    asm volatile(
        "mma.sync.aligned.m16n8k16.row.col.f32.bf16.bf16.f32 "
        "{%0,%1,%2,%3}, {%4,%5,%6,%7}, {%8,%9}, {%0,%1,%2,%3};"
        : "+f"(c[0]), "+f"(c[1]), "+f"(c[2]), "+f"(c[3])
        : "r"(a0), "r"(a1), "r"(a2), "r"(a3), "r"(b0), "r"(b1));
}
__device__ __forceinline__ void dsmem_st_f32(const void* local_smem, uint32_t trank, float v) {
    uint32_t laddr = (uint32_t)__cvta_generic_to_shared(local_smem);
    uint32_t raddr;
    asm volatile("mapa.shared::cluster.u32 %0, %1, %2;" : "=r"(raddr) : "r"(laddr), "r"(trank));
    asm volatile("st.shared::cluster.f32 [%0], %1;" :: "r"(raddr), "f"(v) : "memory");
}
#define CLUSTER_SYNC() do { \
    asm volatile("barrier.cluster.arrive.aligned;" ::: "memory"); \
    asm volatile("barrier.cluster.wait.aligned;" ::: "memory"); } while(0)

__global__ void zero_acc_kernel() {
    if (threadIdx.x < 3) g_acc[threadIdx.x] = 0.0;
}

__global__ void class_argmax_kernel(const float* __restrict__ la,
                                    const float* __restrict__ lb) {
    int t = blockIdx.x * blockDim.x + threadIdx.x;
    if (t >= BSZ*NN) return;
    float4 a = ((const float4*)la)[t];
    int ba = 0; float bv = a.x;
    if (a.y > bv) { bv = a.y; ba = 1; }
    if (a.z > bv) { bv = a.z; ba = 2; }
    if (a.w > bv) { bv = a.w; ba = 3; }
    g_cA[t] = ba;
    float4 b = ((const float4*)lb)[t];
    int bb = 0; bv = b.x;
    if (b.y > bv) { bv = b.y; bb = 1; }
    if (b.z > bv) { bv = b.z; bb = 2; }
    if (b.w > bv) { bv = b.w; bb = 3; }
    g_cB[t] = bb;
}

// x (A then B) -> bf16, 8 elems/thread
__global__ void convert_x_kernel(const float* __restrict__ xA,
                                 const float* __restrict__ xB) {
    const size_t half = (size_t)BSZ*NN*DD;
    size_t i = ((size_t)blockIdx.x*256 + threadIdx.x) * 8;
    const float* src = (i < half) ? (xA + i) : (xB + (i - half));
    float4 f0 = *(const float4*)src;
    float4 f1 = *(const float4*)(src + 4);
    uint4 o;
    o.x = pack_bf2(f0.x, f0.y); o.y = pack_bf2(f0.z, f0.w);
    o.z = pack_bf2(f1.x, f1.y); o.w = pack_bf2(f1.z, f1.w);
    *(uint4*)(g_xh + i) = o;
}

// W[k][n] fp32 -> Wt[n][k] bf16 (writes coalesced)
__global__ void convert_w_kernel(const float* __restrict__ W1,
                                 const float* __restrict__ W2) {
    const float* W = blockIdx.x ? W2 : W1;
    __nv_bfloat16* Wt = blockIdx.x ? g_W2t : g_W1t;
    for (int n = 0; n < DD; n++)
        Wt[(size_t)n*DD + threadIdx.x] = __float2bfloat16(W[(size_t)threadIdx.x*DD + n]);
}

__device__ __forceinline__ void ln_row(float v[8],
    const float4& g0, const float4& g1, const float4& e0, const float4& e1,
    float* o)
{
    float s = 0.f, sq = 0.f;
    #pragma unroll
    for (int j = 0; j < 8; j++) {
        v[j] = v[j] > 0.f ? v[j] : 0.01f * v[j];
        s += v[j]; sq += v[j]*v[j];
    }
    #pragma unroll
    for (int off = 16; off; off >>= 1) {
        s  += __shfl_xor_sync(0xffffffffu, s, off);
        sq += __shfl_xor_sync(0xffffffffu, sq, off);
    }
    float mean = s * (1.f/256.f);
    float var  = sq * (1.f/256.f) - mean*mean;
    float rstd = rsqrtf(var + 1e-5f);
    o[0] = (v[0]-mean)*rstd*g0.x + e0.x;
    o[1] = (v[1]-mean)*rstd*g0.y + e0.y;
    o[2] = (v[2]-mean)*rstd*g0.z + e0.z;
    o[3] = (v[3]-mean)*rstd*g0.w + e0.w;
    o[4] = (v[4]-mean)*rstd*g1.x + e1.x;
    o[5] = (v[5]-mean)*rstd*g1.y + e1.y;
    o[6] = (v[6]-mean)*rstd*g1.z + e1.z;
    o[7] = (v[7]-mean)*rstd*g1.w + e1.w;
}

// Fused 2-layer MLP+LN embed, bf16 m16n8k16 mma, K-chunk 32.
// Block 256 thr (8 warps, 4x2): warp tile 16 rows x 128 cols (16 frags).
// Tiles: X [64 rows][16 gran], Wt [256 n][16 gran]; swizzle q^(((row>>1)&3)<<2).
// H (bf16): [64 rows][128 gran]; swizzle gidx ^ f(r), f(r)=((r&1)<<4)|(((r>>1)&3)<<2).
#define EMBED_SMEM ((64*128 + 2*256*16 + 2*64*16) * 4)

__global__ __launch_bounds__(256, 2)
void embed_kernel(const float* __restrict__ b1,
                  const float* __restrict__ g1, const float* __restrict__ be1,
                  const float* __restrict__ b2,
                  const float* __restrict__ g2, const float* __restrict__ be2)
{
    extern __shared__ uint32_t smu[];
    uint32_t* Hg = smu;             // 64*128
    uint32_t* Wg = smu + 64*128;    // 2*4096
    uint32_t* Xg = Wg + 2*4096;     // 2*1024

    const __nv_bfloat16* X = g_xh + (size_t)blockIdx.y*BSZ*NN*DD;
    __nv_bfloat16* E       = blockIdx.y ? g_eBh : g_eAh;
    float* NRM             = blockIdx.y ? g_nB  : g_nA;

    const int tid  = threadIdx.x;
    const int lane = tid & 31;
    const int warp = tid >> 5;
    const int wm   = warp & 3;
    const int wn   = warp >> 2;
    const int g    = lane >> 2;
    const int t    = lane & 3;
    const int row0 = blockIdx.x * 64;

    const int sw = ((g>>1)&3) << 2;                    // tile swizzle
    const int fA = sw | ((g&1) << 4);                  // H swizzle for r=wm*16+g (+8)

    // X loader (1 chunk/thread): row=tid>>2, q=tid&3
    const int xrow = tid >> 2, xq = tid & 3;
    const int xdst = xrow*16 + ((xq*4) ^ (((xrow>>1)&3)<<2));

    float c[16][4];
    #pragma unroll
    for (int j = 0; j < 16; j++)
        #pragma unroll
        for (int q = 0; q < 4; q++) c[j][q] = 0.f;

    // ---------------- stage 1: pre1 = x @ W1 ----------------
    {
        #pragma unroll
        for (int i = 0; i < 4; i++) {
            int ch = tid + i*256;
            int row = ch >> 2, q = ch & 3;
            cp_async16(&Wg[row*16 + ((q*4) ^ (((row>>1)&3)<<2))],
                       g_W1t + (size_t)row*DD + q*8);
        }
        cp_async16(&Xg[xdst], X + (size_t)(row0 + xrow)*DD + xq*8);
        cp_commit(); cp_wait0();
    }
    __syncthreads();

    for (int kt = 0; kt < 8; kt++) {
        const int cur = kt & 1, nxt = cur ^ 1;
        if (kt < 7) {
            #pragma unroll
            for (int i = 0; i < 4; i++) {
                int ch = tid + i*256;
                int row = ch >> 2, q = ch & 3;
                cp_async16(&Wg[nxt*4096 + row*16 + ((q*4) ^ (((row>>1)&3)<<2))],
                           g_W1t + (size_t)row*DD + (kt+1)*32 + q*8);
            }
            cp_async16(&Xg[nxt*1024 + xdst],
                       X + (size_t)(row0 + xrow)*DD + (kt+1)*32 + xq*8);
            cp_commit();
        }
        const uint32_t* Wc = Wg + cur*4096;
        const uint32_t* Xc = Xg + cur*1024;
        #pragma unroll
        for (int h = 0; h < 2; h++) {
            const int gb = h*8;
            int r = wm*16 + g;
            uint32_t a0 = Xc[(r  )*16 + ((gb+t  ) ^ sw)];
            uint32_t a1 = Xc[(r+8)*16 + ((gb+t  ) ^ sw)];
            uint32_t a2 = Xc[(r  )*16 + ((gb+t+4) ^ sw)];
            uint32_t a3 = Xc[(r+8)*16 + ((gb+t+4) ^ sw)];
            #pragma unroll
            for (int j = 0; j < 16; j++) {
                int n = wn*128 + j*8 + g;
                uint32_t b0 = Wc[n*16 + ((gb+t  ) ^ sw)];
                uint32_t b1 = Wc[n*16 + ((gb+t+4) ^ sw)];
                mma_bf16(c[j], a0, a1, a2, a3, b0, b1);
            }
        }
        if (kt < 7) cp_wait0();
        __syncthreads();
    }

    // stage-2 W prologue overlaps the LN pass
    {
        #pragma unroll
        for (int i = 0; i < 4; i++) {
            int ch = tid + i*256;
            int row = ch >> 2, q = ch & 3;
            cp_async16(&Wg[row*16 + ((q*4) ^ (((row>>1)&3)<<2))],
                       g_W2t + (size_t)row*DD + q*8);
        }
        cp_commit();
    }

    // dump frags to Hg (bf16)
    {
        int r = wm*16 + g;
        #pragma unroll
        for (int j = 0; j < 16; j++) {
            int gidx = wn*64 + j*4 + t;
            Hg[(r  )*128 + (gidx ^ fA)] = pack_bf2(c[j][0], c[j][1]);
            Hg[(r+8)*128 + (gidx ^ fA)] = pack_bf2(c[j][2], c[j][3]);
        }
    }
    __syncthreads();

    // LN pass 1 (rows warp*8..+7, lane cols lane*4 & 128+lane*4)
    {
        const int c0 = lane*4, c1 = 128 + lane*4;
        float4 bv0 = *(const float4*)(b1 + c0), bv1 = *(const float4*)(b1 + c1);
        float4 gv0 = *(const float4*)(g1 + c0), gv1 = *(const float4*)(g1 + c1);
        float4 ev0 = *(const float4*)(be1 + c0), ev1 = *(const float4*)(be1 + c1);
        #pragma unroll
        for (int r = 0; r < 8; r++) {
            int row = warp*8 + r;
            int f = ((row&1)<<4) | (((row>>1)&3)<<2);
            uint2 u0 = *(uint2*)&Hg[row*128 + ((lane*2)      ^ f)];
            uint2 u1 = *(uint2*)&Hg[row*128 + ((64 + lane*2) ^ f)];
            float v[8], o[8];
            unpack_bf2(u0.x, v[0], v[1]); unpack_bf2(u0.y, v[2], v[3]);
            unpack_bf2(u1.x, v[4], v[5]); unpack_bf2(u1.y, v[6], v[7]);
            v[0]+=bv0.x; v[1]+=bv0.y; v[2]+=bv0.z; v[3]+=bv0.w;
            v[4]+=bv1.x; v[5]+=bv1.y; v[6]+=bv1.z; v[7]+=bv1.w;
            ln_row(v, gv0, gv1, ev0, ev1, o);
            uint2 w0, w1;
            w0.x = pack_bf2(o[0], o[1]); w0.y = pack_bf2(o[2], o[3]);
            w1.x = pack_bf2(o[4], o[5]); w1.y = pack_bf2(o[6], o[7]);
            *(uint2*)&Hg[row*128 + ((lane*2)      ^ f)] = w0;
            *(uint2*)&Hg[row*128 + ((64 + lane*2) ^ f)] = w1;
        }
    }
    cp_wait0();
    __syncthreads();

    // ---------------- stage 2: pre2 = h @ W2 ----------------
    #pragma unroll
    for (int j = 0; j < 16; j++)
        #pragma unroll
        for (int q = 0; q < 4; q++) c[j][q] = 0.f;

    for (int kt = 0; kt < 8; kt++) {
        const int cur = kt & 1, nxt = cur ^ 1;
        if (kt < 7) {
            #pragma unroll
            for (int i = 0; i < 4; i++) {
                int ch = tid + i*256;
                int row = ch >> 2, q = ch & 3;
                cp_async16(&Wg[nxt*4096 + row*16 + ((q*4) ^ (((row>>1)&3)<<2))],
                           g_W2t + (size_t)row*DD + (kt+1)*32 + q*8);
            }
            cp_commit();
        }
        const uint32_t* Wc = Wg + cur*4096;
        const uint32_t* H0 = Hg + (wm*16 + g    )*128;
        const uint32_t* H1 = Hg + (wm*16 + g + 8)*128;
        #pragma unroll
        for (int h = 0; h < 2; h++) {
            const int gb = kt*16 + h*8;
            uint32_t a0 = H0[(gb+t  ) ^ fA];
            uint32_t a1 = H1[(gb+t  ) ^ fA];
            uint32_t a2 = H0[(gb+t+4) ^ fA];
            uint32_t a3 = H1[(gb+t+4) ^ fA];
            const int gs = h*8;
            #pragma unroll
            for (int j = 0; j < 16; j++) {
                int n = wn*128 + j*8 + g;
                uint32_t b0 = Wc[n*16 + ((gs+t  ) ^ sw)];
                uint32_t b1 = Wc[n*16 + ((gs+t+4) ^ sw)];
                mma_bf16(c[j], a0, a1, a2, a3, b0, b1);
            }
        }
        if (kt < 7) cp_wait0();
        __syncthreads();
    }

    // dump frags
    {
        int r = wm*16 + g;
        #pragma unroll
        for (int j = 0; j < 16; j++) {
            int gidx = wn*64 + j*4 + t;
            Hg[(r  )*128 + (gidx ^ fA)] = pack_bf2(c[j][0], c[j][1]);
            Hg[(r+8)*128 + (gidx ^ fA)] = pack_bf2(c[j][2], c[j][3]);
        }
    }
    __syncthreads();

    // LN pass 2 + store e (bf16) + norms (fp32)
    {
        const int c0 = lane*4, c1 = 128 + lane*4;
        float4 bv0 = *(const float4*)(b2 + c0), bv1 = *(const float4*)(b2 + c1);
        float4 gv0 = *(const float4*)(g2 + c0), gv1 = *(const float4*)(g2 + c1);
        float4 ev0 = *(const float4*)(be2 + c0), ev1 = *(const float4*)(be2 + c1);
        #pragma unroll
        for (int r = 0; r < 8; r++) {
            int row = warp*8 + r;
            int f = ((row&1)<<4) | (((row>>1)&3)<<2);
            uint2 u0 = *(uint2*)&Hg[row*128 + ((lane*2)      ^ f)];
            uint2 u1 = *(uint2*)&Hg[row*128 + ((64 + lane*2) ^ f)];
            float v[8], o[8];
            unpack_bf2(u0.x, v[0], v[1]); unpack_bf2(u0.y, v[2], v[3]);
            unpack_bf2(u1.x, v[4], v[5]); unpack_bf2(u1.y, v[6], v[7]);
            v[0]+=bv0.x; v[1]+=bv0.y; v[2]+=bv0.z; v[3]+=bv0.w;
            v[4]+=bv1.x; v[5]+=bv1.y; v[6]+=bv1.z; v[7]+=bv1.w;
            ln_row(v, gv0, gv1, ev0, ev1, o);
            float ns = o[0]*o[0]+o[1]*o[1]+o[2]*o[2]+o[3]*o[3]
                     + o[4]*o[4]+o[5]*o[5]+o[6]*o[6]+o[7]*o[7];
            #pragma unroll
            for (int off = 16; off; off >>= 1)
                ns += __shfl_xor_sync(0xffffffffu, ns, off);
            size_t grow = (size_t)(row0 + row);
            uint2 p0, p1;
            p0.x = pack_bf2(o[0], o[1]); p0.y = pack_bf2(o[2], o[3]);
            p1.x = pack_bf2(o[4], o[5]); p1.y = pack_bf2(o[6], o[7]);
            *(uint2*)(E + grow*DD + c0) = p0;
            *(uint2*)(E + grow*DD + c1) = p1;
            if (lane == 0) NRM[grow] = ns;
        }
    }
}

// cdist + cost_class + in/out loss + K(bf16) via bf16 mma (unchanged R12 winner).
__global__ __launch_bounds__(256, 2)
void cost_kernel(const float* __restrict__ pa, const float* __restrict__ pb)
{
    __shared__ __align__(16) uint32_t As[2][128*16];
    __shared__ __align__(16) uint32_t Bs[2][128*16];
    __shared__ float redi[8], redo[8];

    const int b  = blockIdx.z;
    const int ti = blockIdx.y;
    const int tj = blockIdx.x;
    const int tid = threadIdx.x;
    const int lane = tid & 31;
    const int warp = tid >> 5;
    const int wm   = warp & 3;
    const int wn   = warp >> 2;
    const int g    = lane >> 2;
    const int t    = lane & 3;

    const __nv_bfloat16* Ab = g_eAh + (size_t)b*NN*DD + (size_t)ti*128*DD;
    const __nv_bfloat16* Bb = g_eBh + (size_t)b*NN*DD + (size_t)tj*128*DD;

    float c[2][8][4];
    #pragma unroll
    for (int m = 0; m < 2; m++)
        #pragma unroll
        for (int j = 0; j < 8; j++)
            #pragma unroll
            for (int q = 0; q < 4; q++) c[m][j][q] = 0.f;

    {
        #pragma unroll
        for (int i = 0; i < 2; i++) {
            int ch = tid + i*256;
            int row = ch >> 2, q = ch & 3;
            int dstg = row*16 + ((q*4) ^ (((row>>1)&3)<<2));
            cp_async16(&As[0][dstg], Ab + (size_t)row*DD + q*8);
            cp_async16(&Bs[0][dstg], Bb + (size_t)row*DD + q*8);
        }
        cp_commit(); cp_wait0();
    }
    __syncthreads();

    const int sw = ((g>>1)&3) << 2;

    for (int kt = 0; kt < 8; kt++) {
        const int cur = kt & 1, nxt = cur ^ 1;
        if (kt < 7) {
            #pragma unroll
            for (int i = 0; i < 2; i++) {
                int ch = tid + i*256;
                int row = ch >> 2, q = ch & 3;
                int dstg = row*16 + ((q*4) ^ (((row>>1)&3)<<2));
                cp_async16(&As[nxt][dstg], Ab + (size_t)row*DD + (kt+1)*32 + q*8);
                cp_async16(&Bs[nxt][dstg], Bb + (size_t)row*DD + (kt+1)*32 + q*8);
            }
            cp_commit();
        }
        const uint32_t* Ac = As[cur];
        const uint32_t* Bc = Bs[cur];
        #pragma unroll
        for (int h = 0; h < 2; h++) {
            const int gb = h*8;
            uint32_t a[2][4];
            #pragma unroll
            for (int m = 0; m < 2; m++) {
                int r = wm*32 + m*16 + g;
                a[m][0] = Ac[(r  )*16 + ((gb+t  ) ^ sw)];
                a[m][1] = Ac[(r+8)*16 + ((gb+t  ) ^ sw)];
                a[m][2] = Ac[(r  )*16 + ((gb+t+4) ^ sw)];
                a[m][3] = Ac[(r+8)*16 + ((gb+t+4) ^ sw)];
            }
            #pragma unroll
            for (int j = 0; j < 8; j++) {
                int n = wn*64 + j*8 + g;
                uint32_t b0 = Bc[n*16 + ((gb+t  ) ^ sw)];
                uint32_t b1 = Bc[n*16 + ((gb+t+4) ^ sw)];
                mma_bf16(c[0][j], a[0][0], a[0][1], a[0][2], a[0][3], b0, b1);
                mma_bf16(c[1][j], a[1][0], a[1][1], a[1][2], a[1][3], b0, b1);
            }
        }
        if (kt < 7) cp_wait0();
        __syncthreads();
    }

    float sin = 0.f, sout = 0.f;
    #pragma unroll
    for (int m = 0; m < 2; m++) {
        int il1 = ti*128 + wm*32 + m*16 + g;
        int il2 = il1 + 8;
        int gi1 = b*NN + il1, gi2 = b*NN + il2;
        float ni1 = g_nA[gi1], ni2 = g_nA[gi2];
        float pa1 = pa[gi1],   pa2 = pa[gi2];
        int   ca1 = g_cA[gi1], ca2 = g_cA[gi2];
        size_t rb1 = (size_t)gi1 * NN;
        size_t rb2 = (size_t)gi2 * NN;
        #pragma unroll
        for (int j = 0; j < 8; j++) {
            int jl = tj*128 + wn*64 + j*8 + 2*t;
            int gj = b*NN + jl;
            float nj0 = g_nB[gj], nj1 = g_nB[gj+1];
            float pb0 = pb[gj],   pb1 = pb[gj+1];
            int   cb0 = g_cB[gj], cb1 = g_cB[gj+1];

            float sq, cost, pm, cc, w;
            float k00, k01, k10, k11;

            sq = ni1 + nj0 - 2.f*c[m][j][0];
            cost = sqrtf(fmaxf(sq, 0.f));
            pm = pa1*pb0; cc = cost + (BIGC - BIGC*pm); w = cc*pm;
            if (ca1 == cb0) sin += w; else sout += w;
            k00 = __expf(-2.f*cc);

            sq = ni1 + nj1 - 2.f*c[m][j][1];
            cost = sqrtf(fmaxf(sq, 0.f));
            pm = pa1*pb1; cc = cost + (BIGC - BIGC*pm); w = cc*pm;
            if (ca1 == cb1) sin += w; else sout += w;
            k01 = __expf(-2.f*cc);

            sq = ni2 + nj0 - 2.f*c[m][j][2];
            cost = sqrtf(fmaxf(sq, 0.f));
            pm = pa2*pb0; cc = cost + (BIGC - BIGC*pm); w = cc*pm;
            if (ca2 == cb0) sin += w; else sout += w;
            k10 = __expf(-2.f*cc);

            sq = ni2 + nj1 - 2.f*c[m][j][3];
            cost = sqrtf(fmaxf(sq, 0.f));
            pm = pa2*pb1; cc = cost + (BIGC - BIGC*pm); w = cc*pm;
            if (ca2 == cb1) sin += w; else sout += w;
            k11 = __expf(-2.f*cc);

            *(uint32_t*)(g_K + rb1 + jl) = pack_bf2(k00, k01);
            *(uint32_t*)(g_K + rb2 + jl) = pack_bf2(k10, k11);
        }
    }
    #pragma unroll
    for (int off = 16; off; off >>= 1) {
        sin  += __shfl_xor_sync(0xffffffffu, sin,  off);
        sout += __shfl_xor_sync(0xffffffffu, sout, off);
    }
    if (lane == 0) { redi[warp] = sin; redo[warp] = sout; }
    __syncthreads();
    if (tid == 0) {
        float a = 0.f, o2 = 0.f;
        #pragma unroll
        for (int w = 0; w < 8; w++) { a += redi[w]; o2 += redo[w]; }
        atomicAdd(&g_acc[0], (double)a);
        atomicAdd(&g_acc[1], (double)o2);
    }
}

// Sinkhorn + fused sup loss, 2-CTA cluster per batch (unchanged R11 winner).
__global__ __launch_bounds__(512) __cluster_dims__(2, 1, 1)
void sinkhorn_kernel(const float* __restrict__ rel, const float* __restrict__ pa)
{
    __shared__ __align__(16) float su[256];
    __shared__ __align__(16) float sv[NN];
    __shared__ __align__(16) float part[4][NN];
    __shared__ __align__(16) float pvp[2][NN];
    __shared__ float sred[16];

    uint32_t rank;
    asm("mov.u32 %0, %%cluster_ctarank;" : "=r"(rank));
    const uint32_t peer = rank ^ 1;
    const int b = blockIdx.x >> 1;
    const __nv_bfloat16* Kb = g_K + (size_t)b*NN*NN + (size_t)rank*256*NN;

    const int tid  = threadIdx.x;
    const int lane = tid & 31;
    const int warp = tid >> 5;
    const int grp  = tid >> 7;
    const int jc   = (tid & 127) * 4;

    if (tid < 256) su[tid] = 1.f/512.f;
    __syncthreads();
    CLUSTER_SYNC();

    for (int it = 0; it < 10; it++) {
        float a0 = 0.f, a1 = 0.f, a2 = 0.f, a3 = 0.f;
        const int i0 = grp * 64;
        const uint2* K2 = (const uint2*)Kb;
        #pragma unroll 8
        for (int i = 0; i < 64; i++) {
            uint2 kq = K2[(((size_t)(i0 + i))*NN + jc) >> 2];
            float k0,k1,k2,k3;
            unpack_bf2(kq.x, k0, k1);
            unpack_bf2(kq.y, k2, k3);
            float ui = su[i0 + i];
            a0 = fmaf(k0, ui, a0);
            a1 = fmaf(k1, ui, a1);
            a2 = fmaf(k2, ui, a2);
            a3 = fmaf(k3, ui, a3);
        }
        *(float4*)(&part[grp][jc]) = make_float4(a0,a1,a2,a3);
        __syncthreads();
        float mypart = part[0][tid] + part[1][tid] + part[2][tid] + part[3][tid];
        dsmem_st_f32(&pvp[it & 1][tid], peer, mypart);
        CLUSTER_SYNC();
        {
            float y = mypart + pvp[it & 1][tid];
            sv[tid] = (1.f/512.f) / y;
        }
        __syncthreads();
        for (int rr = 0; rr < 16; rr++) {
            int i = warp*16 + rr;
            const uint4* kr = (const uint4*)(Kb + (size_t)i*NN);
            uint4 q0 = kr[lane*2];
            uint4 q1 = kr[lane*2 + 1];
            float s = 0.f;
            float k0,k1;
            float4 vv;
            vv = *(const float4*)(sv + lane*16 + 0);
            unpack_bf2(q0.x, k0, k1); s = fmaf(k0, vv.x, s); s = fmaf(k1, vv.y, s);
            unpack_bf2(q0.y, k0, k1); s = fmaf(k0, vv.z, s); s = fmaf(k1, vv.w, s);
            vv = *(const float4*)(sv + lane*16 + 4);
            unpack_bf2(q0.z, k0, k1); s = fmaf(k0, vv.x, s); s = fmaf(k1, vv.y, s);
            unpack_bf2(q0.w, k0, k1); s = fmaf(k0, vv.z, s); s = fmaf(k1, vv.w, s);
            vv = *(const float4*)(sv + lane*16 + 8);
            unpack_bf2(q1.x, k0, k1); s = fmaf(k0, vv.x, s); s = fmaf(k1, vv.y, s);
            unpack_bf2(q1.y, k0, k1); s = fmaf(k0, vv.z, s); s = fmaf(k1, vv.w, s);
            vv = *(const float4*)(sv + lane*16 + 12);
            unpack_bf2(q1.z, k0, k1); s = fmaf(k0, vv.x, s); s = fmaf(k1, vv.y, s);
            unpack_bf2(q1.w, k0, k1); s = fmaf(k0, vv.z, s); s = fmaf(k1, vv.w, s);
            #pragma unroll
            for (int off = 16; off; off >>= 1)
                s += __shfl_xor_sync(0xffffffffu, s, off);
            if (lane == 0) su[i] = (1.f/512.f) / s;
        }
        __syncthreads();
    }

    const float* relb = rel + (size_t)b*NN*NN + (size_t)rank*256*NN;
    const float* pab  = pa + b*NN + rank*256;
    float lacc = 0.f;
    for (int t = 0; t < 32; t++) {
        int idx = tid + t*512;
        int e = idx * 8;
        int i = e >> 9;
        int j = e & 511;
        uint4 kq = ((const uint4*)Kb)[idx];
        float kf[8];
        unpack_bf2(kq.x, kf[0], kf[1]);
        unpack_bf2(kq.y, kf[2], kf[3]);
        unpack_bf2(kq.z, kf[4], kf[5]);
        unpack_bf2(kq.w, kf[6], kf[7]);
        float4 rv0 = *(const float4*)(relb + e);
        float4 rv1 = *(const float4*)(relb + e + 4);
        float ui  = su[i] * 512.f;
        float pai = pab[i];
        float4 vv0 = *(const float4*)(sv + j);
        float4 vv1 = *(const float4*)(sv + j + 4);
        float d0 = ui*kf[0]*vv0.x - rv0.x;
        float d1 = ui*kf[1]*vv0.y - rv0.y;
        float d2 = ui*kf[2]*vv0.z - rv0.z;
        float d3 = ui*kf[3]*vv0.w - rv0.w;
        float d4 = ui*kf[4]*vv1.x - rv1.x;
        float d5 = ui*kf[5]*vv1.y - rv1.y;
        float d6 = ui*kf[6]*vv1.z - rv1.z;
        float d7 = ui*kf[7]*vv1.w - rv1.w;
        lacc += pai * (d0*d0 + d1*d1 + d2*d2 + d3*d3
                     + d4*d4 + d5*d5 + d6*d6 + d7*d7);
    }
    #pragma unroll
    for (int off = 16; off; off >>= 1)
        lacc += __shfl_xor_sync(0xffffffffu, lacc, off);
    if (lane == 0) sred[warp] = lacc;
    __syncthreads();
    if (tid == 0) {
        float s = 0.f;
        #pragma unroll
        for (int w = 0; w < 16; w++) s += sred[w];
        atomicAdd(&g_acc[2], (double)s);
    }
    CLUSTER_SYNC();
}

__global__ void finalize_kernel(const float* __restrict__ pa, float* __restrict__ out)
{
    __shared__ float red[256];
    float s = 0.f;
    for (int i = threadIdx.x; i < BSZ*NN; i += 256) s += pa[i];
    red[threadIdx.x] = s;
    __syncthreads();
    for (int off = 128; off; off >>= 1) {
        if (threadIdx.x < off) red[threadIdx.x] += red[threadIdx.x + off];
        __syncthreads();
    }
    if (threadIdx.x == 0) {
        double M = (double)BSZ * (double)NN * (double)NN;
        out[0] = (float)(g_acc[0]/M - g_acc[1]/M + 10.0*(g_acc[2]/(double)red[0]));
    }
}

extern "C" void kernel_launch(void* const* d_in, const int* in_sizes, int n_in,
                              void* d_out, int out_size)
{
    const float* la  = (const float*)d_in[0];
    const float* lb  = (const float*)d_in[1];
    const float* xA  = (const float*)d_in[2];
    const float* xB  = (const float*)d_in[3];
    const float* rel = (const float*)d_in[4];
    const float* pa  = (const float*)d_in[5];
    const float* pb  = (const float*)d_in[6];
    const float* W1  = (const float*)d_in[7];
    const float* b1  = (const float*)d_in[8];
    const float* g1  = (const float*)d_in[9];
    const float* be1 = (const float*)d_in[10];
    const float* W2  = (const float*)d_in[11];
    const float* b2  = (const float*)d_in[12];
    const float* g2  = (const float*)d_in[13];
    const float* be2 = (const float*)d_in[14];
    float* out = (float*)d_out;

    cudaFuncSetAttribute(embed_kernel,
                         cudaFuncAttributeMaxDynamicSharedMemorySize, EMBED_SMEM);

    zero_acc_kernel<<<1, 32>>>();
    class_argmax_kernel<<<(BSZ*NN + 255)/256, 256>>>(la, lb);
    convert_x_kernel<<<(int)((size_t)2*BSZ*NN*DD/(256*8)), 256>>>(xA, xB);
    convert_w_kernel<<<2, 256>>>(W1, W2);
    embed_kernel<<<dim3(BSZ*NN/64, 2), 256, EMBED_SMEM>>>(b1, g1, be1, b2, g2, be2);
    cost_kernel<<<dim3(4, 4, BSZ), 256>>>(pa, pb);
    sinkhorn_kernel<<<BSZ*2, 512>>>(rel, pa);
    finalize_kernel<<<1, 256>>>(pa, out);
}

// round 14
// speedup vs baseline: 1.4976x; 1.1149x over previous
#include <cuda_runtime.h>
#include <cuda_bf16.h>
#include <stdint.h>
#include <math.h>

#define BSZ 64
#define NN 512
#define DD 256
#define BIGC 1.0e9f

__device__ __align__(16) __nv_bfloat16 g_eAh[BSZ*NN*DD];
__device__ __align__(16) __nv_bfloat16 g_eBh[BSZ*NN*DD];
__device__ __align__(16) __nv_bfloat16 g_xh[(size_t)2*BSZ*NN*DD];
__device__ __align__(16) __nv_bfloat16 g_W1t[DD*DD];
__device__ __align__(16) __nv_bfloat16 g_W2t[DD*DD];
__device__ float g_nA[BSZ*NN];
__device__ float g_nB[BSZ*NN];
__device__ __nv_bfloat16 g_K[(size_t)BSZ*NN*NN];
__device__ int   g_cA[BSZ*NN];
__device__ int   g_cB[BSZ*NN];
__device__ double g_acc[3];

// ---- helpers ----
__device__ __forceinline__ uint32_t pack_bf2(float a, float b) {
    __nv_bfloat162 h = __floats2bfloat162_rn(a, b);
    return *reinterpret_cast<uint32_t*>(&h);
}
__device__ __forceinline__ void unpack_bf2(uint32_t u, float& a, float& b) {
    a = __uint_as_float(u << 16);
    b = __uint_as_float(u & 0xffff0000u);
}
__device__ __forceinline__ void cp_async16(void* smem_dst, const void* gmem_src) {
    uint32_t s = (uint32_t)__cvta_generic_to_shared(smem_dst);
    asm volatile("cp.async.cg.shared.global [%0], [%1], 16;" :: "r"(s), "l"(gmem_src));
}
__device__ __forceinline__ void cp_commit() {
    asm volatile("cp.async.commit_group;");
}
__device__ __forceinline__ void cp_wait0() {
    asm volatile("cp.async.wait_group 0;");
}
__device__ __forceinline__ void mma_bf16(float* c,
    uint32_t a0, uint32_t a1, uint32_t a2, uint32_t a3,
    uint32_t b0, uint32_t b1)
{
    asm volatile(
        "mma.sync.aligned.m16n8k16.row.col.f32.bf16.bf16.f32 "
        "{%0,%1,%2,%3}, {%4,%5,%6,%7}, {%8,%9}, {%0,%1,%2,%3};"
        : "+f"(c[0]), "+f"(c[1]), "+f"(c[2]), "+f"(c[3])
        : "r"(a0), "r"(a1), "r"(a2), "r"(a3), "r"(b0), "r"(b1));
}
__device__ __forceinline__ void dsmem_st_f32(const void* local_smem, uint32_t trank, float v) {
    uint32_t laddr = (uint32_t)__cvta_generic_to_shared(local_smem);
    uint32_t raddr;
    asm volatile("mapa.shared::cluster.u32 %0, %1, %2;" : "=r"(raddr) : "r"(laddr), "r"(trank));
    asm volatile("st.shared::cluster.f32 [%0], %1;" :: "r"(raddr), "f"(v) : "memory");
}
#define CLUSTER_SYNC() do { \
    asm volatile("barrier.cluster.arrive.aligned;" ::: "memory"); \
    asm volatile("barrier.cluster.wait.aligned;" ::: "memory"); } while(0)

__global__ void zero_acc_kernel() {
    if (threadIdx.x < 3) g_acc[threadIdx.x] = 0.0;
}

__global__ void class_argmax_kernel(const float* __restrict__ la,
                                    const float* __restrict__ lb) {
    int t = blockIdx.x * blockDim.x + threadIdx.x;
    if (t >= BSZ*NN) return;
    float4 a = ((const float4*)la)[t];
    int ba = 0; float bv = a.x;
    if (a.y > bv) { bv = a.y; ba = 1; }
    if (a.z > bv) { bv = a.z; ba = 2; }
    if (a.w > bv) { bv = a.w; ba = 3; }
    g_cA[t] = ba;
    float4 b = ((const float4*)lb)[t];
    int bb = 0; bv = b.x;
    if (b.y > bv) { bv = b.y; bb = 1; }
    if (b.z > bv) { bv = b.z; bb = 2; }
    if (b.w > bv) { bv = b.w; bb = 3; }
    g_cB[t] = bb;
}

// x (A then B) -> bf16, 8 elems/thread
__global__ void convert_x_kernel(const float* __restrict__ xA,
                                 const float* __restrict__ xB) {
    const size_t half = (size_t)BSZ*NN*DD;
    size_t i = ((size_t)blockIdx.x*256 + threadIdx.x) * 8;
    const float* src = (i < half) ? (xA + i) : (xB + (i - half));
    float4 f0 = *(const float4*)src;
    float4 f1 = *(const float4*)(src + 4);
    uint4 o;
    o.x = pack_bf2(f0.x, f0.y); o.y = pack_bf2(f0.z, f0.w);
    o.z = pack_bf2(f1.x, f1.y); o.w = pack_bf2(f1.z, f1.w);
    *(uint4*)(g_xh + i) = o;
}

// W[k][n] fp32 -> Wt[n][k] bf16, fully parallel: one element per thread.
// Coalesced reads; writes group into 512B lines per warp-quarter.
__global__ void convert_w_kernel(const float* __restrict__ W1,
                                 const float* __restrict__ W2) {
    int idx = blockIdx.x * 256 + threadIdx.x;     // 0 .. 2*DD*DD-1
    const float* W = (idx < DD*DD) ? W1 : W2;
    __nv_bfloat16* Wt = (idx < DD*DD) ? g_W1t : g_W2t;
    int e = idx & (DD*DD - 1);
    int k = e >> 8;          // row in W
    int n = e & 255;         // col in W
    Wt[n*DD + k] = __float2bfloat16(W[e]);
}

__device__ __forceinline__ void ln_row(float v[8],
    const float4& g0, const float4& g1, const float4& e0, const float4& e1,
    float* o)
{
    float s = 0.f, sq = 0.f;
    #pragma unroll
    for (int j = 0; j < 8; j++) {
        v[j] = v[j] > 0.f ? v[j] : 0.01f * v[j];
        s += v[j]; sq += v[j]*v[j];
    }
    #pragma unroll
    for (int off = 16; off; off >>= 1) {
        s  += __shfl_xor_sync(0xffffffffu, s, off);
        sq += __shfl_xor_sync(0xffffffffu, sq, off);
    }
    float mean = s * (1.f/256.f);
    float var  = sq * (1.f/256.f) - mean*mean;
    float rstd = rsqrtf(var + 1e-5f);
    o[0] = (v[0]-mean)*rstd*g0.x + e0.x;
    o[1] = (v[1]-mean)*rstd*g0.y + e0.y;
    o[2] = (v[2]-mean)*rstd*g0.z + e0.z;
    o[3] = (v[3]-mean)*rstd*g0.w + e0.w;
    o[4] = (v[4]-mean)*rstd*g1.x + e1.x;
    o[5] = (v[5]-mean)*rstd*g1.y + e1.y;
    o[6] = (v[6]-mean)*rstd*g1.z + e1.z;
    o[7] = (v[7]-mean)*rstd*g1.w + e1.w;
}

// Fused 2-layer MLP+LN embed, bf16 m16n8k16 mma, K-chunk 32 (R13 winner).
#define EMBED_SMEM ((64*128 + 2*256*16 + 2*64*16) * 4)

__global__ __launch_bounds__(256, 2)
void embed_kernel(const float* __restrict__ b1,
                  const float* __restrict__ g1, const float* __restrict__ be1,
                  const float* __restrict__ b2,
                  const float* __restrict__ g2, const float* __restrict__ be2)
{
    extern __shared__ uint32_t smu[];
    uint32_t* Hg = smu;             // 64*128
    uint32_t* Wg = smu + 64*128;    // 2*4096
    uint32_t* Xg = Wg + 2*4096;     // 2*1024

    const __nv_bfloat16* X = g_xh + (size_t)blockIdx.y*BSZ*NN*DD;
    __nv_bfloat16* E       = blockIdx.y ? g_eBh : g_eAh;
    float* NRM             = blockIdx.y ? g_nB  : g_nA;

    const int tid  = threadIdx.x;
    const int lane = tid & 31;
    const int warp = tid >> 5;
    const int wm   = warp & 3;
    const int wn   = warp >> 2;
    const int g    = lane >> 2;
    const int t    = lane & 3;
    const int row0 = blockIdx.x * 64;

    const int sw = ((g>>1)&3) << 2;
    const int fA = sw | ((g&1) << 4);

    const int xrow = tid >> 2, xq = tid & 3;
    const int xdst = xrow*16 + ((xq*4) ^ (((xrow>>1)&3)<<2));

    float c[16][4];
    #pragma unroll
    for (int j = 0; j < 16; j++)
        #pragma unroll
        for (int q = 0; q < 4; q++) c[j][q] = 0.f;

    // ---------------- stage 1: pre1 = x @ W1 ----------------
    {
        #pragma unroll
        for (int i = 0; i < 4; i++) {
            int ch = tid + i*256;
            int row = ch >> 2, q = ch & 3;
            cp_async16(&Wg[row*16 + ((q*4) ^ (((row>>1)&3)<<2))],
                       g_W1t + (size_t)row*DD + q*8);
        }
        cp_async16(&Xg[xdst], X + (size_t)(row0 + xrow)*DD + xq*8);
        cp_commit(); cp_wait0();
    }
    __syncthreads();

    for (int kt = 0; kt < 8; kt++) {
        const int cur = kt & 1, nxt = cur ^ 1;
        if (kt < 7) {
            #pragma unroll
            for (int i = 0; i < 4; i++) {
                int ch = tid + i*256;
                int row = ch >> 2, q = ch & 3;
                cp_async16(&Wg[nxt*4096 + row*16 + ((q*4) ^ (((row>>1)&3)<<2))],
                           g_W1t + (size_t)row*DD + (kt+1)*32 + q*8);
            }
            cp_async16(&Xg[nxt*1024 + xdst],
                       X + (size_t)(row0 + xrow)*DD + (kt+1)*32 + xq*8);
            cp_commit();
        }
        const uint32_t* Wc = Wg + cur*4096;
        const uint32_t* Xc = Xg + cur*1024;
        #pragma unroll
        for (int h = 0; h < 2; h++) {
            const int gb = h*8;
            int r = wm*16 + g;
            uint32_t a0 = Xc[(r  )*16 + ((gb+t  ) ^ sw)];
            uint32_t a1 = Xc[(r+8)*16 + ((gb+t  ) ^ sw)];
            uint32_t a2 = Xc[(r  )*16 + ((gb+t+4) ^ sw)];
            uint32_t a3 = Xc[(r+8)*16 + ((gb+t+4) ^ sw)];
            #pragma unroll
            for (int j = 0; j < 16; j++) {
                int n = wn*128 + j*8 + g;
                uint32_t b0 = Wc[n*16 + ((gb+t  ) ^ sw)];
                uint32_t b1 = Wc[n*16 + ((gb+t+4) ^ sw)];
                mma_bf16(c[j], a0, a1, a2, a3, b0, b1);
            }
        }
        if (kt < 7) cp_wait0();
        __syncthreads();
    }

    {
        #pragma unroll
        for (int i = 0; i < 4; i++) {
            int ch = tid + i*256;
            int row = ch >> 2, q = ch & 3;
            cp_async16(&Wg[row*16 + ((q*4) ^ (((row>>1)&3)<<2))],
                       g_W2t + (size_t)row*DD + q*8);
        }
        cp_commit();
    }

    {
        int r = wm*16 + g;
        #pragma unroll
        for (int j = 0; j < 16; j++) {
            int gidx = wn*64 + j*4 + t;
            Hg[(r  )*128 + (gidx ^ fA)] = pack_bf2(c[j][0], c[j][1]);
            Hg[(r+8)*128 + (gidx ^ fA)] = pack_bf2(c[j][2], c[j][3]);
        }
    }
    __syncthreads();

    {
        const int c0 = lane*4, c1 = 128 + lane*4;
        float4 bv0 = *(const float4*)(b1 + c0), bv1 = *(const float4*)(b1 + c1);
        float4 gv0 = *(const float4*)(g1 + c0), gv1 = *(const float4*)(g1 + c1);
        float4 ev0 = *(const float4*)(be1 + c0), ev1 = *(const float4*)(be1 + c1);
        #pragma unroll
        for (int r = 0; r < 8; r++) {
            int row = warp*8 + r;
            int f = ((row&1)<<4) | (((row>>1)&3)<<2);
            uint2 u0 = *(uint2*)&Hg[row*128 + ((lane*2)      ^ f)];
            uint2 u1 = *(uint2*)&Hg[row*128 + ((64 + lane*2) ^ f)];
            float v[8], o[8];
            unpack_bf2(u0.x, v[0], v[1]); unpack_bf2(u0.y, v[2], v[3]);
            unpack_bf2(u1.x, v[4], v[5]); unpack_bf2(u1.y, v[6], v[7]);
            v[0]+=bv0.x; v[1]+=bv0.y; v[2]+=bv0.z; v[3]+=bv0.w;
            v[4]+=bv1.x; v[5]+=bv1.y; v[6]+=bv1.z; v[7]+=bv1.w;
            ln_row(v, gv0, gv1, ev0, ev1, o);
            uint2 w0, w1;
            w0.x = pack_bf2(o[0], o[1]); w0.y = pack_bf2(o[2], o[3]);
            w1.x = pack_bf2(o[4], o[5]); w1.y = pack_bf2(o[6], o[7]);
            *(uint2*)&Hg[row*128 + ((lane*2)      ^ f)] = w0;
            *(uint2*)&Hg[row*128 + ((64 + lane*2) ^ f)] = w1;
        }
    }
    cp_wait0();
    __syncthreads();

    // ---------------- stage 2: pre2 = h @ W2 ----------------
    #pragma unroll
    for (int j = 0; j < 16; j++)
        #pragma unroll
        for (int q = 0; q < 4; q++) c[j][q] = 0.f;

    for (int kt = 0; kt < 8; kt++) {
        const int cur = kt & 1, nxt = cur ^ 1;
        if (kt < 7) {
            #pragma unroll
            for (int i = 0; i < 4; i++) {
                int ch = tid + i*256;
                int row = ch >> 2, q = ch & 3;
                cp_async16(&Wg[nxt*4096 + row*16 + ((q*4) ^ (((row>>1)&3)<<2))],
                           g_W2t + (size_t)row*DD + (kt+1)*32 + q*8);
            }
            cp_commit();
        }
        const uint32_t* Wc = Wg + cur*4096;
        const uint32_t* H0 = Hg + (wm*16 + g    )*128;
        const uint32_t* H1 = Hg + (wm*16 + g + 8)*128;
        #pragma unroll
        for (int h = 0; h < 2; h++) {
            const int gb = kt*16 + h*8;
            uint32_t a0 = H0[(gb+t  ) ^ fA];
            uint32_t a1 = H1[(gb+t  ) ^ fA];
            uint32_t a2 = H0[(gb+t+4) ^ fA];
            uint32_t a3 = H1[(gb+t+4) ^ fA];
            const int gs = h*8;
            #pragma unroll
            for (int j = 0; j < 16; j++) {
                int n = wn*128 + j*8 + g;
                uint32_t b0 = Wc[n*16 + ((gs+t  ) ^ sw)];
                uint32_t b1 = Wc[n*16 + ((gs+t+4) ^ sw)];
                mma_bf16(c[j], a0, a1, a2, a3, b0, b1);
            }
        }
        if (kt < 7) cp_wait0();
        __syncthreads();
    }

    {
        int r = wm*16 + g;
        #pragma unroll
        for (int j = 0; j < 16; j++) {
            int gidx = wn*64 + j*4 + t;
            Hg[(r  )*128 + (gidx ^ fA)] = pack_bf2(c[j][0], c[j][1]);
            Hg[(r+8)*128 + (gidx ^ fA)] = pack_bf2(c[j][2], c[j][3]);
        }
    }
    __syncthreads();

    {
        const int c0 = lane*4, c1 = 128 + lane*4;
        float4 bv0 = *(const float4*)(b2 + c0), bv1 = *(const float4*)(b2 + c1);
        float4 gv0 = *(const float4*)(g2 + c0), gv1 = *(const float4*)(g2 + c1);
        float4 ev0 = *(const float4*)(be2 + c0), ev1 = *(const float4*)(be2 + c1);
        #pragma unroll
        for (int r = 0; r < 8; r++) {
            int row = warp*8 + r;
            int f = ((row&1)<<4) | (((row>>1)&3)<<2);
            uint2 u0 = *(uint2*)&Hg[row*128 + ((lane*2)      ^ f)];
            uint2 u1 = *(uint2*)&Hg[row*128 + ((64 + lane*2) ^ f)];
            float v[8], o[8];
            unpack_bf2(u0.x, v[0], v[1]); unpack_bf2(u0.y, v[2], v[3]);
            unpack_bf2(u1.x, v[4], v[5]); unpack_bf2(u1.y, v[6], v[7]);
            v[0]+=bv0.x; v[1]+=bv0.y; v[2]+=bv0.z; v[3]+=bv0.w;
            v[4]+=bv1.x; v[5]+=bv1.y; v[6]+=bv1.z; v[7]+=bv1.w;
            ln_row(v, gv0, gv1, ev0, ev1, o);
            float ns = o[0]*o[0]+o[1]*o[1]+o[2]*o[2]+o[3]*o[3]
                     + o[4]*o[4]+o[5]*o[5]+o[6]*o[6]+o[7]*o[7];
            #pragma unroll
            for (int off = 16; off; off >>= 1)
                ns += __shfl_xor_sync(0xffffffffu, ns, off);
            size_t grow = (size_t)(row0 + row);
            uint2 p0, p1;
            p0.x = pack_bf2(o[0], o[1]); p0.y = pack_bf2(o[2], o[3]);
            p1.x = pack_bf2(o[4], o[5]); p1.y = pack_bf2(o[6], o[7]);
            *(uint2*)(E + grow*DD + c0) = p0;
            *(uint2*)(E + grow*DD + c1) = p1;
            if (lane == 0) NRM[grow] = ns;
        }
    }
}

// cdist + cost_class + in/out loss + K(bf16) via bf16 mma (unchanged).
__global__ __launch_bounds__(256, 2)
void cost_kernel(const float* __restrict__ pa, const float* __restrict__ pb)
{
    __shared__ __align__(16) uint32_t As[2][128*16];
    __shared__ __align__(16) uint32_t Bs[2][128*16];
    __shared__ float redi[8], redo[8];

    const int b  = blockIdx.z;
    const int ti = blockIdx.y;
    const int tj = blockIdx.x;
    const int tid = threadIdx.x;
    const int lane = tid & 31;
    const int warp = tid >> 5;
    const int wm   = warp & 3;
    const int wn   = warp >> 2;
    const int g    = lane >> 2;
    const int t    = lane & 3;

    const __nv_bfloat16* Ab = g_eAh + (size_t)b*NN*DD + (size_t)ti*128*DD;
    const __nv_bfloat16* Bb = g_eBh + (size_t)b*NN*DD + (size_t)tj*128*DD;

    float c[2][8][4];
    #pragma unroll
    for (int m = 0; m < 2; m++)
        #pragma unroll
        for (int j = 0; j < 8; j++)
            #pragma unroll
            for (int q = 0; q < 4; q++) c[m][j][q] = 0.f;

    {
        #pragma unroll
        for (int i = 0; i < 2; i++) {
            int ch = tid + i*256;
            int row = ch >> 2, q = ch & 3;
            int dstg = row*16 + ((q*4) ^ (((row>>1)&3)<<2));
            cp_async16(&As[0][dstg], Ab + (size_t)row*DD + q*8);
            cp_async16(&Bs[0][dstg], Bb + (size_t)row*DD + q*8);
        }
        cp_commit(); cp_wait0();
    }
    __syncthreads();

    const int sw = ((g>>1)&3) << 2;

    for (int kt = 0; kt < 8; kt++) {
        const int cur = kt & 1, nxt = cur ^ 1;
        if (kt < 7) {
            #pragma unroll
            for (int i = 0; i < 2; i++) {
                int ch = tid + i*256;
                int row = ch >> 2, q = ch & 3;
                int dstg = row*16 + ((q*4) ^ (((row>>1)&3)<<2));
                cp_async16(&As[nxt][dstg], Ab + (size_t)row*DD + (kt+1)*32 + q*8);
                cp_async16(&Bs[nxt][dstg], Bb + (size_t)row*DD + (kt+1)*32 + q*8);
            }
            cp_commit();
        }
        const uint32_t* Ac = As[cur];
        const uint32_t* Bc = Bs[cur];
        #pragma unroll
        for (int h = 0; h < 2; h++) {
            const int gb = h*8;
            uint32_t a[2][4];
            #pragma unroll
            for (int m = 0; m < 2; m++) {
                int r = wm*32 + m*16 + g;
                a[m][0] = Ac[(r  )*16 + ((gb+t  ) ^ sw)];
                a[m][1] = Ac[(r+8)*16 + ((gb+t  ) ^ sw)];
                a[m][2] = Ac[(r  )*16 + ((gb+t+4) ^ sw)];
                a[m][3] = Ac[(r+8)*16 + ((gb+t+4) ^ sw)];
            }
            #pragma unroll
            for (int j = 0; j < 8; j++) {
                int n = wn*64 + j*8 + g;
                uint32_t b0 = Bc[n*16 + ((gb+t  ) ^ sw)];
                uint32_t b1 = Bc[n*16 + ((gb+t+4) ^ sw)];
                mma_bf16(c[0][j], a[0][0], a[0][1], a[0][2], a[0][3], b0, b1);
                mma_bf16(c[1][j], a[1][0], a[1][1], a[1][2], a[1][3], b0, b1);
            }
        }
        if (kt < 7) cp_wait0();
        __syncthreads();
    }

    float sin = 0.f, sout = 0.f;
    #pragma unroll
    for (int m = 0; m < 2; m++) {
        int il1 = ti*128 + wm*32 + m*16 + g;
        int il2 = il1 + 8;
        int gi1 = b*NN + il1, gi2 = b*NN + il2;
        float ni1 = g_nA[gi1], ni2 = g_nA[gi2];
        float pa1 = pa[gi1],   pa2 = pa[gi2];
        int   ca1 = g_cA[gi1], ca2 = g_cA[gi2];
        size_t rb1 = (size_t)gi1 * NN;
        size_t rb2 = (size_t)gi2 * NN;
        #pragma unroll
        for (int j = 0; j < 8; j++) {
            int jl = tj*128 + wn*64 + j*8 + 2*t;
            int gj = b*NN + jl;
            float nj0 = g_nB[gj], nj1 = g_nB[gj+1];
            float pb0 = pb[gj],   pb1 = pb[gj+1];
            int   cb0 = g_cB[gj], cb1 = g_cB[gj+1];

            float sq, cost, pm, cc, w;
            float k00, k01, k10, k11;

            sq = ni1 + nj0 - 2.f*c[m][j][0];
            cost = sqrtf(fmaxf(sq, 0.f));
            pm = pa1*pb0; cc = cost + (BIGC - BIGC*pm); w = cc*pm;
            if (ca1 == cb0) sin += w; else sout += w;
            k00 = __expf(-2.f*cc);

            sq = ni1 + nj1 - 2.f*c[m][j][1];
            cost = sqrtf(fmaxf(sq, 0.f));
            pm = pa1*pb1; cc = cost + (BIGC - BIGC*pm); w = cc*pm;
            if (ca1 == cb1) sin += w; else sout += w;
            k01 = __expf(-2.f*cc);

            sq = ni2 + nj0 - 2.f*c[m][j][2];
            cost = sqrtf(fmaxf(sq, 0.f));
            pm = pa2*pb0; cc = cost + (BIGC - BIGC*pm); w = cc*pm;
            if (ca2 == cb0) sin += w; else sout += w;
            k10 = __expf(-2.f*cc);

            sq = ni2 + nj1 - 2.f*c[m][j][3];
            cost = sqrtf(fmaxf(sq, 0.f));
            pm = pa2*pb1; cc = cost + (BIGC - BIGC*pm); w = cc*pm;
            if (ca2 == cb1) sin += w; else sout += w;
            k11 = __expf(-2.f*cc);

            *(uint32_t*)(g_K + rb1 + jl) = pack_bf2(k00, k01);
            *(uint32_t*)(g_K + rb2 + jl) = pack_bf2(k10, k11);
        }
    }
    #pragma unroll
    for (int off = 16; off; off >>= 1) {
        sin  += __shfl_xor_sync(0xffffffffu, sin,  off);
        sout += __shfl_xor_sync(0xffffffffu, sout, off);
    }
    if (lane == 0) { redi[warp] = sin; redo[warp] = sout; }
    __syncthreads();
    if (tid == 0) {
        float a = 0.f, o2 = 0.f;
        #pragma unroll
        for (int w = 0; w < 8; w++) { a += redi[w]; o2 += redo[w]; }
        atomicAdd(&g_acc[0], (double)a);
        atomicAdd(&g_acc[1], (double)o2);
    }
}

// Sinkhorn + fused sup loss, 2-CTA cluster per batch (unchanged).
__global__ __launch_bounds__(512) __cluster_dims__(2, 1, 1)
void sinkhorn_kernel(const float* __restrict__ rel, const float* __restrict__ pa)
{
    __shared__ __align__(16) float su[256];
    __shared__ __align__(16) float sv[NN];
    __shared__ __align__(16) float part[4][NN];
    __shared__ __align__(16) float pvp[2][NN];
    __shared__ float sred[16];

    uint32_t rank;
    asm("mov.u32 %0, %%cluster_ctarank;" : "=r"(rank));
    const uint32_t peer = rank ^ 1;
    const int b = blockIdx.x >> 1;
    const __nv_bfloat16* Kb = g_K + (size_t)b*NN*NN + (size_t)rank*256*NN;

    const int tid  = threadIdx.x;
    const int lane = tid & 31;
    const int warp = tid >> 5;
    const int grp  = tid >> 7;
    const int jc   = (tid & 127) * 4;

    if (tid < 256) su[tid] = 1.f/512.f;
    __syncthreads();
    CLUSTER_SYNC();

    for (int it = 0; it < 10; it++) {
        float a0 = 0.f, a1 = 0.f, a2 = 0.f, a3 = 0.f;
        const int i0 = grp * 64;
        const uint2* K2 = (const uint2*)Kb;
        #pragma unroll 8
        for (int i = 0; i < 64; i++) {
            uint2 kq = K2[(((size_t)(i0 + i))*NN + jc) >> 2];
            float k0,k1,k2,k3;
            unpack_bf2(kq.x, k0, k1);
            unpack_bf2(kq.y, k2, k3);
            float ui = su[i0 + i];
            a0 = fmaf(k0, ui, a0);
            a1 = fmaf(k1, ui, a1);
            a2 = fmaf(k2, ui, a2);
            a3 = fmaf(k3, ui, a3);
        }
        *(float4*)(&part[grp][jc]) = make_float4(a0,a1,a2,a3);
        __syncthreads();
        float mypart = part[0][tid] + part[1][tid] + part[2][tid] + part[3][tid];
        dsmem_st_f32(&pvp[it & 1][tid], peer, mypart);
        CLUSTER_SYNC();
        {
            float y = mypart + pvp[it & 1][tid];
            sv[tid] = (1.f/512.f) / y;
        }
        __syncthreads();
        for (int rr = 0; rr < 16; rr++) {
            int i = warp*16 + rr;
            const uint4* kr = (const uint4*)(Kb + (size_t)i*NN);
            uint4 q0 = kr[lane*2];
            uint4 q1 = kr[lane*2 + 1];
            float s = 0.f;
            float k0,k1;
            float4 vv;
            vv = *(const float4*)(sv + lane*16 + 0);
            unpack_bf2(q0.x, k0, k1); s = fmaf(k0, vv.x, s); s = fmaf(k1, vv.y, s);
            unpack_bf2(q0.y, k0, k1); s = fmaf(k0, vv.z, s); s = fmaf(k1, vv.w, s);
            vv = *(const float4*)(sv + lane*16 + 4);
            unpack_bf2(q0.z, k0, k1); s = fmaf(k0, vv.x, s); s = fmaf(k1, vv.y, s);
            unpack_bf2(q0.w, k0, k1); s = fmaf(k0, vv.z, s); s = fmaf(k1, vv.w, s);
            vv = *(const float4*)(sv + lane*16 + 8);
            unpack_bf2(q1.x, k0, k1); s = fmaf(k0, vv.x, s); s = fmaf(k1, vv.y, s);
            unpack_bf2(q1.y, k0, k1); s = fmaf(k0, vv.z, s); s = fmaf(k1, vv.w, s);
            vv = *(const float4*)(sv + lane*16 + 12);
            unpack_bf2(q1.z, k0, k1); s = fmaf(k0, vv.x, s); s = fmaf(k1, vv.y, s);
            unpack_bf2(q1.w, k0, k1); s = fmaf(k0, vv.z, s); s = fmaf(k1, vv.w, s);
            #pragma unroll
            for (int off = 16; off; off >>= 1)
                s += __shfl_xor_sync(0xffffffffu, s, off);
            if (lane == 0) su[i] = (1.f/512.f) / s;
        }
        __syncthreads();
    }

    const float* relb = rel + (size_t)b*NN*NN + (size_t)rank*256*NN;
    const float* pab  = pa + b*NN + rank*256;
    float lacc = 0.f;
    for (int t = 0; t < 32; t++) {
        int idx = tid + t*512;
        int e = idx * 8;
        int i = e >> 9;
        int j = e & 511;
        uint4 kq = ((const uint4*)Kb)[idx];
        float kf[8];
        unpack_bf2(kq.x, kf[0], kf[1]);
        unpack_bf2(kq.y, kf[2], kf[3]);
        unpack_bf2(kq.z, kf[4], kf[5]);
        unpack_bf2(kq.w, kf[6], kf[7]);
        float4 rv0 = *(const float4*)(relb + e);
        float4 rv1 = *(const float4*)(relb + e + 4);
        float ui  = su[i] * 512.f;
        float pai = pab[i];
        float4 vv0 = *(const float4*)(sv + j);
        float4 vv1 = *(const float4*)(sv + j + 4);
        float d0 = ui*kf[0]*vv0.x - rv0.x;
        float d1 = ui*kf[1]*vv0.y - rv0.y;
        float d2 = ui*kf[2]*vv0.z - rv0.z;
        float d3 = ui*kf[3]*vv0.w - rv0.w;
        float d4 = ui*kf[4]*vv1.x - rv1.x;
        float d5 = ui*kf[5]*vv1.y - rv1.y;
        float d6 = ui*kf[6]*vv1.z - rv1.z;
        float d7 = ui*kf[7]*vv1.w - rv1.w;
        lacc += pai * (d0*d0 + d1*d1 + d2*d2 + d3*d3
                     + d4*d4 + d5*d5 + d6*d6 + d7*d7);
    }
    #pragma unroll
    for (int off = 16; off; off >>= 1)
        lacc += __shfl_xor_sync(0xffffffffu, lacc, off);
    if (lane == 0) sred[warp] = lacc;
    __syncthreads();
    if (tid == 0) {
        float s = 0.f;
        #pragma unroll
        for (int w = 0; w < 16; w++) s += sred[w];
        atomicAdd(&g_acc[2], (double)s);
    }
    CLUSTER_SYNC();
}

__global__ void finalize_kernel(const float* __restrict__ pa, float* __restrict__ out)
{
    __shared__ float red[256];
    float s = 0.f;
    for (int i = threadIdx.x; i < BSZ*NN; i += 256) s += pa[i];
    red[threadIdx.x] = s;
    __syncthreads();
    for (int off = 128; off; off >>= 1) {
        if (threadIdx.x < off) red[threadIdx.x] += red[threadIdx.x + off];
        __syncthreads();
    }
    if (threadIdx.x == 0) {
        double M = (double)BSZ * (double)NN * (double)NN;
        out[0] = (float)(g_acc[0]/M - g_acc[1]/M + 10.0*(g_acc[2]/(double)red[0]));
    }
}

extern "C" void kernel_launch(void* const* d_in, const int* in_sizes, int n_in,
                              void* d_out, int out_size)
{
    const float* la  = (const float*)d_in[0];
    const float* lb  = (const float*)d_in[1];
    const float* xA  = (const float*)d_in[2];
    const float* xB  = (const float*)d_in[3];
    const float* rel = (const float*)d_in[4];
    const float* pa  = (const float*)d_in[5];
    const float* pb  = (const float*)d_in[6];
    const float* W1  = (const float*)d_in[7];
    const float* b1  = (const float*)d_in[8];
    const float* g1  = (const float*)d_in[9];
    const float* be1 = (const float*)d_in[10];
    const float* W2  = (const float*)d_in[11];
    const float* b2  = (const float*)d_in[12];
    const float* g2  = (const float*)d_in[13];
    const float* be2 = (const float*)d_in[14];
    float* out = (float*)d_out;

    cudaFuncSetAttribute(embed_kernel,
                         cudaFuncAttributeMaxDynamicSharedMemorySize, EMBED_SMEM);

    zero_acc_kernel<<<1, 32>>>();
    class_argmax_kernel<<<(BSZ*NN + 255)/256, 256>>>(la, lb);
    convert_x_kernel<<<(int)((size_t)2*BSZ*NN*DD/(256*8)), 256>>>(xA, xB);
    convert_w_kernel<<<2*DD*DD/256, 256>>>(W1, W2);
    embed_kernel<<<dim3(BSZ*NN/64, 2), 256, EMBED_SMEM>>>(b1, g1, be1, b2, g2, be2);
    cost_kernel<<<dim3(4, 4, BSZ), 256>>>(pa, pb);
    sinkhorn_kernel<<<BSZ*2, 512>>>(rel, pa);
    finalize_kernel<<<1, 256>>>(pa, out);
}

// round 15
// speedup vs baseline: 1.5371x; 1.0264x over previous
#include <cuda_runtime.h>
#include <cuda_bf16.h>
#include <stdint.h>
#include <math.h>

#define BSZ 64
#define NN 512
#define DD 256
#define BIGC 1.0e9f

__device__ __align__(16) __nv_bfloat16 g_eAh[BSZ*NN*DD];
__device__ __align__(16) __nv_bfloat16 g_eBh[BSZ*NN*DD];
__device__ __align__(16) __nv_bfloat16 g_W1t[DD*DD];
__device__ __align__(16) __nv_bfloat16 g_W2t[DD*DD];
__device__ float g_nA[BSZ*NN];
__device__ float g_nB[BSZ*NN];
__device__ __nv_bfloat16 g_K[(size_t)BSZ*NN*NN];
__device__ int   g_cA[BSZ*NN];
__device__ int   g_cB[BSZ*NN];
__device__ double g_acc[3];

// ---- helpers ----
__device__ __forceinline__ uint32_t pack_bf2(float a, float b) {
    __nv_bfloat162 h = __floats2bfloat162_rn(a, b);
    return *reinterpret_cast<uint32_t*>(&h);
}
__device__ __forceinline__ void unpack_bf2(uint32_t u, float& a, float& b) {
    a = __uint_as_float(u << 16);
    b = __uint_as_float(u & 0xffff0000u);
}
__device__ __forceinline__ void cp_async16(void* smem_dst, const void* gmem_src) {
    uint32_t s = (uint32_t)__cvta_generic_to_shared(smem_dst);
    asm volatile("cp.async.cg.shared.global [%0], [%1], 16;" :: "r"(s), "l"(gmem_src));
}
__device__ __forceinline__ void cp_commit() {
    asm volatile("cp.async.commit_group;");
}
__device__ __forceinline__ void cp_wait0() {
    asm volatile("cp.async.wait_group 0;");
}
__device__ __forceinline__ void mma_bf16(float* c,
    uint32_t a0, uint32_t a1, uint32_t a2, uint32_t a3,
    uint32_t b0, uint32_t b1)
{
    asm volatile(
        "mma.sync.aligned.m16n8k16.row.col.f32.bf16.bf16.f32 "
        "{%0,%1,%2,%3}, {%4,%5,%6,%7}, {%8,%9}, {%0,%1,%2,%3};"
        : "+f"(c[0]), "+f"(c[1]), "+f"(c[2]), "+f"(c[3])
        : "r"(a0), "r"(a1), "r"(a2), "r"(a3), "r"(b0), "r"(b1));
}
__device__ __forceinline__ void dsmem_st_f32(const void* local_smem, uint32_t trank, float v) {
    uint32_t laddr = (uint32_t)__cvta_generic_to_shared(local_smem);
    uint32_t raddr;
    asm volatile("mapa.shared::cluster.u32 %0, %1, %2;" : "=r"(raddr) : "r"(laddr), "r"(trank));
    asm volatile("st.shared::cluster.f32 [%0], %1;" :: "r"(raddr), "f"(v) : "memory");
}
#define CLUSTER_SYNC() do { \
    asm volatile("barrier.cluster.arrive.aligned;" ::: "memory"); \
    asm volatile("barrier.cluster.wait.aligned;" ::: "memory"); } while(0)

// Merged prologue: zero accumulators + class argmax + W transpose->bf16.
// Blocks [0,128): argmax over BSZ*NN rows. Blocks [128,640): W1/W2 transpose.
__global__ void prep_kernel(const float* __restrict__ la,
                            const float* __restrict__ lb,
                            const float* __restrict__ W1,
                            const float* __restrict__ W2) {
    const int bid = blockIdx.x, tid = threadIdx.x;
    if (bid == 0 && tid < 3) g_acc[tid] = 0.0;
    if (bid < 128) {
        int t = bid*256 + tid;
        float4 a = ((const float4*)la)[t];
        int ba = 0; float bv = a.x;
        if (a.y > bv) { bv = a.y; ba = 1; }
        if (a.z > bv) { bv = a.z; ba = 2; }
        if (a.w > bv) { bv = a.w; ba = 3; }
        g_cA[t] = ba;
        float4 b = ((const float4*)lb)[t];
        int bb = 0; bv = b.x;
        if (b.y > bv) { bv = b.y; bb = 1; }
        if (b.z > bv) { bv = b.z; bb = 2; }
        if (b.w > bv) { bv = b.w; bb = 3; }
        g_cB[t] = bb;
    } else {
        int idx = (bid - 128)*256 + tid;              // 0 .. 2*DD*DD-1
        const float* W = (idx < DD*DD) ? W1 : W2;
        __nv_bfloat16* Wt = (idx < DD*DD) ? g_W1t : g_W2t;
        int e = idx & (DD*DD - 1);
        int k = e >> 8, n = e & 255;
        Wt[n*DD + k] = __float2bfloat16(W[e]);
    }
}

__device__ __forceinline__ void ln_row(float v[8],
    const float4& g0, const float4& g1, const float4& e0, const float4& e1,
    float* o)
{
    float s = 0.f, sq = 0.f;
    #pragma unroll
    for (int j = 0; j < 8; j++) {
        v[j] = v[j] > 0.f ? v[j] : 0.01f * v[j];
        s += v[j]; sq += v[j]*v[j];
    }
    #pragma unroll
    for (int off = 16; off; off >>= 1) {
        s  += __shfl_xor_sync(0xffffffffu, s, off);
        sq += __shfl_xor_sync(0xffffffffu, sq, off);
    }
    float mean = s * (1.f/256.f);
    float var  = sq * (1.f/256.f) - mean*mean;
    float rstd = rsqrtf(var + 1e-5f);
    o[0] = (v[0]-mean)*rstd*g0.x + e0.x;
    o[1] = (v[1]-mean)*rstd*g0.y + e0.y;
    o[2] = (v[2]-mean)*rstd*g0.z + e0.z;
    o[3] = (v[3]-mean)*rstd*g0.w + e0.w;
    o[4] = (v[4]-mean)*rstd*g1.x + e1.x;
    o[5] = (v[5]-mean)*rstd*g1.y + e1.y;
    o[6] = (v[6]-mean)*rstd*g1.z + e1.z;
    o[7] = (v[7]-mean)*rstd*g1.w + e1.w;
}

// Fused 2-layer MLP+LN embed, bf16 m16n8k16 mma, K-chunk 32.
// x is read as fp32 directly (staged in smem, converted in-kernel).
// Smem: Hg 64x128 gran (32KB), Wg 2x4096 gran (32KB), Xg 1024 gran (4KB),
//       Xf 2x 64x32 fp32 (16KB)  -> 86KB total, 2 CTAs/SM.
#define EMBED_SMEM ((64*128 + 2*256*16 + 64*16 + 2*64*32) * 4)

__global__ __launch_bounds__(256, 2)
void embed_kernel(const float* __restrict__ xA, const float* __restrict__ xB,
                  const float* __restrict__ b1,
                  const float* __restrict__ g1, const float* __restrict__ be1,
                  const float* __restrict__ b2,
                  const float* __restrict__ g2, const float* __restrict__ be2)
{
    extern __shared__ uint32_t smu[];
    uint32_t* Hg = smu;              // 8192
    uint32_t* Wg = smu + 8192;       // 2*4096
    uint32_t* Xg = smu + 16384;      // 1024 (single buffer, converted JIT)
    float*    Xf = (float*)(smu + 17408); // 2 * 64*32 fp32

    const float* X   = blockIdx.y ? xB    : xA;
    __nv_bfloat16* E = blockIdx.y ? g_eBh : g_eAh;
    float* NRM       = blockIdx.y ? g_nB  : g_nA;

    const int tid  = threadIdx.x;
    const int lane = tid & 31;
    const int warp = tid >> 5;
    const int wm   = warp & 3;
    const int wn   = warp >> 2;
    const int g    = lane >> 2;
    const int t    = lane & 3;
    const int row0 = blockIdx.x * 64;

    const int sw = ((g>>1)&3) << 2;
    const int fA = sw | ((g&1) << 4);

    float c[16][4];
    #pragma unroll
    for (int j = 0; j < 16; j++)
        #pragma unroll
        for (int q = 0; q < 4; q++) c[j][q] = 0.f;

    // ---------------- stage 1: pre1 = x @ W1 ----------------
    {   // prologue: W chunk 0 (bf16) + X fp32 chunk 0
        #pragma unroll
        for (int i = 0; i < 4; i++) {
            int ch = tid + i*256;
            int row = ch >> 2, q = ch & 3;
            cp_async16(&Wg[row*16 + ((q*4) ^ (((row>>1)&3)<<2))],
                       g_W1t + (size_t)row*DD + q*8);
        }
        #pragma unroll
        for (int i = 0; i < 2; i++) {
            int ch = tid + i*256;
            int row = ch >> 3, q = ch & 7;
            cp_async16(Xf + row*32 + q*4, X + (size_t)(row0 + row)*DD + q*4);
        }
        cp_commit(); cp_wait0();
    }
    __syncthreads();

    for (int kt = 0; kt < 8; kt++) {
        const int cur = kt & 1, nxt = cur ^ 1;
        // convert staged fp32 X chunk -> bf16 swizzled Xg
        {
            const float* Xs = Xf + cur*2048;
            #pragma unroll
            for (int i = 0; i < 4; i++) {
                int gi = tid + i*256;
                int r = gi >> 4, gx = gi & 15;
                float2 v = *(const float2*)(Xs + r*32 + gx*2);
                Xg[r*16 + (gx ^ (((r>>1)&3)<<2))] = pack_bf2(v.x, v.y);
            }
        }
        __syncthreads();
        if (kt < 7) {
            #pragma unroll
            for (int i = 0; i < 4; i++) {
                int ch = tid + i*256;
                int row = ch >> 2, q = ch & 3;
                cp_async16(&Wg[nxt*4096 + row*16 + ((q*4) ^ (((row>>1)&3)<<2))],
                           g_W1t + (size_t)row*DD + (kt+1)*32 + q*8);
            }
            #pragma unroll
            for (int i = 0; i < 2; i++) {
                int ch = tid + i*256;
                int row = ch >> 3, q = ch & 7;
                cp_async16(Xf + nxt*2048 + row*32 + q*4,
                           X + (size_t)(row0 + row)*DD + (kt+1)*32 + q*4);
            }
            cp_commit();
        }
        const uint32_t* Wc = Wg + cur*4096;
        #pragma unroll
        for (int h = 0; h < 2; h++) {
            const int gb = h*8;
            int r = wm*16 + g;
            uint32_t a0 = Xg[(r  )*16 + ((gb+t  ) ^ sw)];
            uint32_t a1 = Xg[(r+8)*16 + ((gb+t  ) ^ sw)];
            uint32_t a2 = Xg[(r  )*16 + ((gb+t+4) ^ sw)];
            uint32_t a3 = Xg[(r+8)*16 + ((gb+t+4) ^ sw)];
            #pragma unroll
            for (int j = 0; j < 16; j++) {
                int n = wn*128 + j*8 + g;
                uint32_t b0 = Wc[n*16 + ((gb+t  ) ^ sw)];
                uint32_t b1 = Wc[n*16 + ((gb+t+4) ^ sw)];
                mma_bf16(c[j], a0, a1, a2, a3, b0, b1);
            }
        }
        if (kt < 7) cp_wait0();
        __syncthreads();
    }

    // stage-2 W prologue overlaps the LN pass
    {
        #pragma unroll
        for (int i = 0; i < 4; i++) {
            int ch = tid + i*256;
            int row = ch >> 2, q = ch & 3;
            cp_async16(&Wg[row*16 + ((q*4) ^ (((row>>1)&3)<<2))],
                       g_W2t + (size_t)row*DD + q*8);
        }
        cp_commit();
    }

    {
        int r = wm*16 + g;
        #pragma unroll
        for (int j = 0; j < 16; j++) {
            int gidx = wn*64 + j*4 + t;
            Hg[(r  )*128 + (gidx ^ fA)] = pack_bf2(c[j][0], c[j][1]);
            Hg[(r+8)*128 + (gidx ^ fA)] = pack_bf2(c[j][2], c[j][3]);
        }
    }
    __syncthreads();

    {
        const int c0 = lane*4, c1 = 128 + lane*4;
        float4 bv0 = *(const float4*)(b1 + c0), bv1 = *(const float4*)(b1 + c1);
        float4 gv0 = *(const float4*)(g1 + c0), gv1 = *(const float4*)(g1 + c1);
        float4 ev0 = *(const float4*)(be1 + c0), ev1 = *(const float4*)(be1 + c1);
        #pragma unroll
        for (int r = 0; r < 8; r++) {
            int row = warp*8 + r;
            int f = ((row&1)<<4) | (((row>>1)&3)<<2);
            uint2 u0 = *(uint2*)&Hg[row*128 + ((lane*2)      ^ f)];
            uint2 u1 = *(uint2*)&Hg[row*128 + ((64 + lane*2) ^ f)];
            float v[8], o[8];
            unpack_bf2(u0.x, v[0], v[1]); unpack_bf2(u0.y, v[2], v[3]);
            unpack_bf2(u1.x, v[4], v[5]); unpack_bf2(u1.y, v[6], v[7]);
            v[0]+=bv0.x; v[1]+=bv0.y; v[2]+=bv0.z; v[3]+=bv0.w;
            v[4]+=bv1.x; v[5]+=bv1.y; v[6]+=bv1.z; v[7]+=bv1.w;
            ln_row(v, gv0, gv1, ev0, ev1, o);
            uint2 w0, w1;
            w0.x = pack_bf2(o[0], o[1]); w0.y = pack_bf2(o[2], o[3]);
            w1.x = pack_bf2(o[4], o[5]); w1.y = pack_bf2(o[6], o[7]);
            *(uint2*)&Hg[row*128 + ((lane*2)      ^ f)] = w0;
            *(uint2*)&Hg[row*128 + ((64 + lane*2) ^ f)] = w1;
        }
    }
    cp_wait0();
    __syncthreads();

    // ---------------- stage 2: pre2 = h @ W2 ----------------
    #pragma unroll
    for (int j = 0; j < 16; j++)
        #pragma unroll
        for (int q = 0; q < 4; q++) c[j][q] = 0.f;

    for (int kt = 0; kt < 8; kt++) {
        const int cur = kt & 1, nxt = cur ^ 1;
        if (kt < 7) {
            #pragma unroll
            for (int i = 0; i < 4; i++) {
                int ch = tid + i*256;
                int row = ch >> 2, q = ch & 3;
                cp_async16(&Wg[nxt*4096 + row*16 + ((q*4) ^ (((row>>1)&3)<<2))],
                           g_W2t + (size_t)row*DD + (kt+1)*32 + q*8);
            }
            cp_commit();
        }
        const uint32_t* Wc = Wg + cur*4096;
        const uint32_t* H0 = Hg + (wm*16 + g    )*128;
        const uint32_t* H1 = Hg + (wm*16 + g + 8)*128;
        #pragma unroll
        for (int h = 0; h < 2; h++) {
            const int gb = kt*16 + h*8;
            uint32_t a0 = H0[(gb+t  ) ^ fA];
            uint32_t a1 = H1[(gb+t  ) ^ fA];
            uint32_t a2 = H0[(gb+t+4) ^ fA];
            uint32_t a3 = H1[(gb+t+4) ^ fA];
            const int gs = h*8;
            #pragma unroll
            for (int j = 0; j < 16; j++) {
                int n = wn*128 + j*8 + g;
                uint32_t b0 = Wc[n*16 + ((gs+t  ) ^ sw)];
                uint32_t b1 = Wc[n*16 + ((gs+t+4) ^ sw)];
                mma_bf16(c[j], a0, a1, a2, a3, b0, b1);
            }
        }
        if (kt < 7) cp_wait0();
        __syncthreads();
    }

    {
        int r = wm*16 + g;
        #pragma unroll
        for (int j = 0; j < 16; j++) {
            int gidx = wn*64 + j*4 + t;
            Hg[(r  )*128 + (gidx ^ fA)] = pack_bf2(c[j][0], c[j][1]);
            Hg[(r+8)*128 + (gidx ^ fA)] = pack_bf2(c[j][2], c[j][3]);
        }
    }
    __syncthreads();

    {
        const int c0 = lane*4, c1 = 128 + lane*4;
        float4 bv0 = *(const float4*)(b2 + c0), bv1 = *(const float4*)(b2 + c1);
        float4 gv0 = *(const float4*)(g2 + c0), gv1 = *(const float4*)(g2 + c1);
        float4 ev0 = *(const float4*)(be2 + c0), ev1 = *(const float4*)(be2 + c1);
        #pragma unroll
        for (int r = 0; r < 8; r++) {
            int row = warp*8 + r;
            int f = ((row&1)<<4) | (((row>>1)&3)<<2);
            uint2 u0 = *(uint2*)&Hg[row*128 + ((lane*2)      ^ f)];
            uint2 u1 = *(uint2*)&Hg[row*128 + ((64 + lane*2) ^ f)];
            float v[8], o[8];
            unpack_bf2(u0.x, v[0], v[1]); unpack_bf2(u0.y, v[2], v[3]);
            unpack_bf2(u1.x, v[4], v[5]); unpack_bf2(u1.y, v[6], v[7]);
            v[0]+=bv0.x; v[1]+=bv0.y; v[2]+=bv0.z; v[3]+=bv0.w;
            v[4]+=bv1.x; v[5]+=bv1.y; v[6]+=bv1.z; v[7]+=bv1.w;
            ln_row(v, gv0, gv1, ev0, ev1, o);
            float ns = o[0]*o[0]+o[1]*o[1]+o[2]*o[2]+o[3]*o[3]
                     + o[4]*o[4]+o[5]*o[5]+o[6]*o[6]+o[7]*o[7];
            #pragma unroll
            for (int off = 16; off; off >>= 1)
                ns += __shfl_xor_sync(0xffffffffu, ns, off);
            size_t grow = (size_t)(row0 + row);
            uint2 p0, p1;
            p0.x = pack_bf2(o[0], o[1]); p0.y = pack_bf2(o[2], o[3]);
            p1.x = pack_bf2(o[4], o[5]); p1.y = pack_bf2(o[6], o[7]);
            *(uint2*)(E + grow*DD + c0) = p0;
            *(uint2*)(E + grow*DD + c1) = p1;
            if (lane == 0) NRM[grow] = ns;
        }
    }
}

// cdist + cost_class + in/out loss + K(bf16) via bf16 mma (unchanged).
__global__ __launch_bounds__(256, 2)
void cost_kernel(const float* __restrict__ pa, const float* __restrict__ pb)
{
    __shared__ __align__(16) uint32_t As[2][128*16];
    __shared__ __align__(16) uint32_t Bs[2][128*16];
    __shared__ float redi[8], redo[8];

    const int b  = blockIdx.z;
    const int ti = blockIdx.y;
    const int tj = blockIdx.x;
    const int tid = threadIdx.x;
    const int lane = tid & 31;
    const int warp = tid >> 5;
    const int wm   = warp & 3;
    const int wn   = warp >> 2;
    const int g    = lane >> 2;
    const int t    = lane & 3;

    const __nv_bfloat16* Ab = g_eAh + (size_t)b*NN*DD + (size_t)ti*128*DD;
    const __nv_bfloat16* Bb = g_eBh + (size_t)b*NN*DD + (size_t)tj*128*DD;

    float c[2][8][4];
    #pragma unroll
    for (int m = 0; m < 2; m++)
        #pragma unroll
        for (int j = 0; j < 8; j++)
            #pragma unroll
            for (int q = 0; q < 4; q++) c[m][j][q] = 0.f;

    {
        #pragma unroll
        for (int i = 0; i < 2; i++) {
            int ch = tid + i*256;
            int row = ch >> 2, q = ch & 3;
            int dstg = row*16 + ((q*4) ^ (((row>>1)&3)<<2));
            cp_async16(&As[0][dstg], Ab + (size_t)row*DD + q*8);
            cp_async16(&Bs[0][dstg], Bb + (size_t)row*DD + q*8);
        }
        cp_commit(); cp_wait0();
    }
    __syncthreads();

    const int sw = ((g>>1)&3) << 2;

    for (int kt = 0; kt < 8; kt++) {
        const int cur = kt & 1, nxt = cur ^ 1;
        if (kt < 7) {
            #pragma unroll
            for (int i = 0; i < 2; i++) {
                int ch = tid + i*256;
                int row = ch >> 2, q = ch & 3;
                int dstg = row*16 + ((q*4) ^ (((row>>1)&3)<<2));
                cp_async16(&As[nxt][dstg], Ab + (size_t)row*DD + (kt+1)*32 + q*8);
                cp_async16(&Bs[nxt][dstg], Bb + (size_t)row*DD + (kt+1)*32 + q*8);
            }
            cp_commit();
        }
        const uint32_t* Ac = As[cur];
        const uint32_t* Bc = Bs[cur];
        #pragma unroll
        for (int h = 0; h < 2; h++) {
            const int gb = h*8;
            uint32_t a[2][4];
            #pragma unroll
            for (int m = 0; m < 2; m++) {
                int r = wm*32 + m*16 + g;
                a[m][0] = Ac[(r  )*16 + ((gb+t  ) ^ sw)];
                a[m][1] = Ac[(r+8)*16 + ((gb+t  ) ^ sw)];
                a[m][2] = Ac[(r  )*16 + ((gb+t+4) ^ sw)];
                a[m][3] = Ac[(r+8)*16 + ((gb+t+4) ^ sw)];
            }
            #pragma unroll
            for (int j = 0; j < 8; j++) {
                int n = wn*64 + j*8 + g;
                uint32_t b0 = Bc[n*16 + ((gb+t  ) ^ sw)];
                uint32_t b1 = Bc[n*16 + ((gb+t+4) ^ sw)];
                mma_bf16(c[0][j], a[0][0], a[0][1], a[0][2], a[0][3], b0, b1);
                mma_bf16(c[1][j], a[1][0], a[1][1], a[1][2], a[1][3], b0, b1);
            }
        }
        if (kt < 7) cp_wait0();
        __syncthreads();
    }

    float sin = 0.f, sout = 0.f;
    #pragma unroll
    for (int m = 0; m < 2; m++) {
        int il1 = ti*128 + wm*32 + m*16 + g;
        int il2 = il1 + 8;
        int gi1 = b*NN + il1, gi2 = b*NN + il2;
        float ni1 = g_nA[gi1], ni2 = g_nA[gi2];
        float pa1 = pa[gi1],   pa2 = pa[gi2];
        int   ca1 = g_cA[gi1], ca2 = g_cA[gi2];
        size_t rb1 = (size_t)gi1 * NN;
        size_t rb2 = (size_t)gi2 * NN;
        #pragma unroll
        for (int j = 0; j < 8; j++) {
            int jl = tj*128 + wn*64 + j*8 + 2*t;
            int gj = b*NN + jl;
            float nj0 = g_nB[gj], nj1 = g_nB[gj+1];
            float pb0 = pb[gj],   pb1 = pb[gj+1];
            int   cb0 = g_cB[gj], cb1 = g_cB[gj+1];

            float sq, cost, pm, cc, w;
            float k00, k01, k10, k11;

            sq = ni1 + nj0 - 2.f*c[m][j][0];
            cost = sqrtf(fmaxf(sq, 0.f));
            pm = pa1*pb0; cc = cost + (BIGC - BIGC*pm); w = cc*pm;
            if (ca1 == cb0) sin += w; else sout += w;
            k00 = __expf(-2.f*cc);

            sq = ni1 + nj1 - 2.f*c[m][j][1];
            cost = sqrtf(fmaxf(sq, 0.f));
            pm = pa1*pb1; cc = cost + (BIGC - BIGC*pm); w = cc*pm;
            if (ca1 == cb1) sin += w; else sout += w;
            k01 = __expf(-2.f*cc);

            sq = ni2 + nj0 - 2.f*c[m][j][2];
            cost = sqrtf(fmaxf(sq, 0.f));
            pm = pa2*pb0; cc = cost + (BIGC - BIGC*pm); w = cc*pm;
            if (ca2 == cb0) sin += w; else sout += w;
            k10 = __expf(-2.f*cc);

            sq = ni2 + nj1 - 2.f*c[m][j][3];
            cost = sqrtf(fmaxf(sq, 0.f));
            pm = pa2*pb1; cc = cost + (BIGC - BIGC*pm); w = cc*pm;
            if (ca2 == cb1) sin += w; else sout += w;
            k11 = __expf(-2.f*cc);

            *(uint32_t*)(g_K + rb1 + jl) = pack_bf2(k00, k01);
            *(uint32_t*)(g_K + rb2 + jl) = pack_bf2(k10, k11);
        }
    }
    #pragma unroll
    for (int off = 16; off; off >>= 1) {
        sin  += __shfl_xor_sync(0xffffffffu, sin,  off);
        sout += __shfl_xor_sync(0xffffffffu, sout, off);
    }
    if (lane == 0) { redi[warp] = sin; redo[warp] = sout; }
    __syncthreads();
    if (tid == 0) {
        float a = 0.f, o2 = 0.f;
        #pragma unroll
        for (int w = 0; w < 8; w++) { a += redi[w]; o2 += redo[w]; }
        atomicAdd(&g_acc[0], (double)a);
        atomicAdd(&g_acc[1], (double)o2);
    }
}

// Sinkhorn + fused sup loss, 2-CTA cluster per batch (unchanged).
__global__ __launch_bounds__(512) __cluster_dims__(2, 1, 1)
void sinkhorn_kernel(const float* __restrict__ rel, const float* __restrict__ pa)
{
    __shared__ __align__(16) float su[256];
    __shared__ __align__(16) float sv[NN];
    __shared__ __align__(16) float part[4][NN];
    __shared__ __align__(16) float pvp[2][NN];
    __shared__ float sred[16];

    uint32_t rank;
    asm("mov.u32 %0, %%cluster_ctarank;" : "=r"(rank));
    const uint32_t peer = rank ^ 1;
    const int b = blockIdx.x >> 1;
    const __nv_bfloat16* Kb = g_K + (size_t)b*NN*NN + (size_t)rank*256*NN;

    const int tid  = threadIdx.x;
    const int lane = tid & 31;
    const int warp = tid >> 5;
    const int grp  = tid >> 7;
    const int jc   = (tid & 127) * 4;

    if (tid < 256) su[tid] = 1.f/512.f;
    __syncthreads();
    CLUSTER_SYNC();

    for (int it = 0; it < 10; it++) {
        float a0 = 0.f, a1 = 0.f, a2 = 0.f, a3 = 0.f;
        const int i0 = grp * 64;
        const uint2* K2 = (const uint2*)Kb;
        #pragma unroll 8
        for (int i = 0; i < 64; i++) {
            uint2 kq = K2[(((size_t)(i0 + i))*NN + jc) >> 2];
            float k0,k1,k2,k3;
            unpack_bf2(kq.x, k0, k1);
            unpack_bf2(kq.y, k2, k3);
            float ui = su[i0 + i];
            a0 = fmaf(k0, ui, a0);
            a1 = fmaf(k1, ui, a1);
            a2 = fmaf(k2, ui, a2);
            a3 = fmaf(k3, ui, a3);
        }
        *(float4*)(&part[grp][jc]) = make_float4(a0,a1,a2,a3);
        __syncthreads();
        float mypart = part[0][tid] + part[1][tid] + part[2][tid] + part[3][tid];
        dsmem_st_f32(&pvp[it & 1][tid], peer, mypart);
        CLUSTER_SYNC();
        {
            float y = mypart + pvp[it & 1][tid];
            sv[tid] = (1.f/512.f) / y;
        }
        __syncthreads();
        for (int rr = 0; rr < 16; rr++) {
            int i = warp*16 + rr;
            const uint4* kr = (const uint4*)(Kb + (size_t)i*NN);
            uint4 q0 = kr[lane*2];
            uint4 q1 = kr[lane*2 + 1];
            float s = 0.f;
            float k0,k1;
            float4 vv;
            vv = *(const float4*)(sv + lane*16 + 0);
            unpack_bf2(q0.x, k0, k1); s = fmaf(k0, vv.x, s); s = fmaf(k1, vv.y, s);
            unpack_bf2(q0.y, k0, k1); s = fmaf(k0, vv.z, s); s = fmaf(k1, vv.w, s);
            vv = *(const float4*)(sv + lane*16 + 4);
            unpack_bf2(q0.z, k0, k1); s = fmaf(k0, vv.x, s); s = fmaf(k1, vv.y, s);
            unpack_bf2(q0.w, k0, k1); s = fmaf(k0, vv.z, s); s = fmaf(k1, vv.w, s);
            vv = *(const float4*)(sv + lane*16 + 8);
            unpack_bf2(q1.x, k0, k1); s = fmaf(k0, vv.x, s); s = fmaf(k1, vv.y, s);
            unpack_bf2(q1.y, k0, k1); s = fmaf(k0, vv.z, s); s = fmaf(k1, vv.w, s);
            vv = *(const float4*)(sv + lane*16 + 12);
            unpack_bf2(q1.z, k0, k1); s = fmaf(k0, vv.x, s); s = fmaf(k1, vv.y, s);
            unpack_bf2(q1.w, k0, k1); s = fmaf(k0, vv.z, s); s = fmaf(k1, vv.w, s);
            #pragma unroll
            for (int off = 16; off; off >>= 1)
                s += __shfl_xor_sync(0xffffffffu, s, off);
            if (lane == 0) su[i] = (1.f/512.f) / s;
        }
        __syncthreads();
    }

    const float* relb = rel + (size_t)b*NN*NN + (size_t)rank*256*NN;
    const float* pab  = pa + b*NN + rank*256;
    float lacc = 0.f;
    for (int t = 0; t < 32; t++) {
        int idx = tid + t*512;
        int e = idx * 8;
        int i = e >> 9;
        int j = e & 511;
        uint4 kq = ((const uint4*)Kb)[idx];
        float kf[8];
        unpack_bf2(kq.x, kf[0], kf[1]);
        unpack_bf2(kq.y, kf[2], kf[3]);
        unpack_bf2(kq.z, kf[4], kf[5]);
        unpack_bf2(kq.w, kf[6], kf[7]);
        float4 rv0 = *(const float4*)(relb + e);
        float4 rv1 = *(const float4*)(relb + e + 4);
        float ui  = su[i] * 512.f;
        float pai = pab[i];
        float4 vv0 = *(const float4*)(sv + j);
        float4 vv1 = *(const float4*)(sv + j + 4);
        float d0 = ui*kf[0]*vv0.x - rv0.x;
        float d1 = ui*kf[1]*vv0.y - rv0.y;
        float d2 = ui*kf[2]*vv0.z - rv0.z;
        float d3 = ui*kf[3]*vv0.w - rv0.w;
        float d4 = ui*kf[4]*vv1.x - rv1.x;
        float d5 = ui*kf[5]*vv1.y - rv1.y;
        float d6 = ui*kf[6]*vv1.z - rv1.z;
        float d7 = ui*kf[7]*vv1.w - rv1.w;
        lacc += pai * (d0*d0 + d1*d1 + d2*d2 + d3*d3
                     + d4*d4 + d5*d5 + d6*d6 + d7*d7);
    }
    #pragma unroll
    for (int off = 16; off; off >>= 1)
        lacc += __shfl_xor_sync(0xffffffffu, lacc, off);
    if (lane == 0) sred[warp] = lacc;
    __syncthreads();
    if (tid == 0) {
        float s = 0.f;
        #pragma unroll
        for (int w = 0; w < 16; w++) s += sred[w];
        atomicAdd(&g_acc[2], (double)s);
    }
    CLUSTER_SYNC();
}

__global__ void finalize_kernel(const float* __restrict__ pa, float* __restrict__ out)
{
    __shared__ float red[256];
    float s = 0.f;
    for (int i = threadIdx.x; i < BSZ*NN; i += 256) s += pa[i];
    red[threadIdx.x] = s;
    __syncthreads();
    for (int off = 128; off; off >>= 1) {
        if (threadIdx.x < off) red[threadIdx.x] += red[threadIdx.x + off];
        __syncthreads();
    }
    if (threadIdx.x == 0) {
        double M = (double)BSZ * (double)NN * (double)NN;
        out[0] = (float)(g_acc[0]/M - g_acc[1]/M + 10.0*(g_acc[2]/(double)red[0]));
    }
}

extern "C" void kernel_launch(void* const* d_in, const int* in_sizes, int n_in,
                              void* d_out, int out_size)
{
    const float* la  = (const float*)d_in[0];
    const float* lb  = (const float*)d_in[1];
    const float* xA  = (const float*)d_in[2];
    const float* xB  = (const float*)d_in[3];
    const float* rel = (const float*)d_in[4];
    const float* pa  = (const float*)d_in[5];
    const float* pb  = (const float*)d_in[6];
    const float* W1  = (const float*)d_in[7];
    const float* b1  = (const float*)d_in[8];
    const float* g1  = (const float*)d_in[9];
    const float* be1 = (const float*)d_in[10];
    const float* W2  = (const float*)d_in[11];
    const float* b2  = (const float*)d_in[12];
    const float* g2  = (const float*)d_in[13];
    const float* be2 = (const float*)d_in[14];
    float* out = (float*)d_out;

    cudaFuncSetAttribute(embed_kernel,
                         cudaFuncAttributeMaxDynamicSharedMemorySize, EMBED_SMEM);

    prep_kernel<<<640, 256>>>(la, lb, W1, W2);
    embed_kernel<<<dim3(BSZ*NN/64, 2), 256, EMBED_SMEM>>>(
        xA, xB, b1, g1, be1, b2, g2, be2);
    cost_kernel<<<dim3(4, 4, BSZ), 256>>>(pa, pb);
    sinkhorn_kernel<<<BSZ*2, 512>>>(rel, pa);
    finalize_kernel<<<1, 256>>>(pa, out);
}

// round 16
// speedup vs baseline: 1.6023x; 1.0424x over previous
#include <cuda_runtime.h>
#include <cuda_bf16.h>
#include <stdint.h>
#include <math.h>

#define BSZ 64
#define NN 512
#define DD 256
#define BIGC 1.0e9f
#define SK_ROWS 64
#define SK_WPR 260   // padded words per K row (512 bf16 = 256 words + 4 pad)

__device__ __align__(16) __nv_bfloat16 g_eAh[BSZ*NN*DD];
__device__ __align__(16) __nv_bfloat16 g_eBh[BSZ*NN*DD];
__device__ __align__(16) __nv_bfloat16 g_W1t[DD*DD];
__device__ __align__(16) __nv_bfloat16 g_W2t[DD*DD];
__device__ float g_nA[BSZ*NN];
__device__ float g_nB[BSZ*NN];
__device__ __nv_bfloat16 g_K[(size_t)BSZ*NN*NN];
__device__ int   g_cA[BSZ*NN];
__device__ int   g_cB[BSZ*NN];
__device__ double g_acc[3];

// ---- helpers ----
__device__ __forceinline__ uint32_t pack_bf2(float a, float b) {
    __nv_bfloat162 h = __floats2bfloat162_rn(a, b);
    return *reinterpret_cast<uint32_t*>(&h);
}
__device__ __forceinline__ void unpack_bf2(uint32_t u, float& a, float& b) {
    a = __uint_as_float(u << 16);
    b = __uint_as_float(u & 0xffff0000u);
}
__device__ __forceinline__ void cp_async16(void* smem_dst, const void* gmem_src) {
    uint32_t s = (uint32_t)__cvta_generic_to_shared(smem_dst);
    asm volatile("cp.async.cg.shared.global [%0], [%1], 16;" :: "r"(s), "l"(gmem_src));
}
__device__ __forceinline__ void cp_commit() {
    asm volatile("cp.async.commit_group;");
}
__device__ __forceinline__ void cp_wait0() {
    asm volatile("cp.async.wait_group 0;");
}
__device__ __forceinline__ void mma_bf16(float* c,
    uint32_t a0, uint32_t a1, uint32_t a2, uint32_t a3,
    uint32_t b0, uint32_t b1)
{
    asm volatile(
        "mma.sync.aligned.m16n8k16.row.col.f32.bf16.bf16.f32 "
        "{%0,%1,%2,%3}, {%4,%5,%6,%7}, {%8,%9}, {%0,%1,%2,%3};"
        : "+f"(c[0]), "+f"(c[1]), "+f"(c[2]), "+f"(c[3])
        : "r"(a0), "r"(a1), "r"(a2), "r"(a3), "r"(b0), "r"(b1));
}
__device__ __forceinline__ void dsmem_st_f32(const void* local_smem, uint32_t trank, float v) {
    uint32_t laddr = (uint32_t)__cvta_generic_to_shared(local_smem);
    uint32_t raddr;
    asm volatile("mapa.shared::cluster.u32 %0, %1, %2;" : "=r"(raddr) : "r"(laddr), "r"(trank));
    asm volatile("st.shared::cluster.f32 [%0], %1;" :: "r"(raddr), "f"(v) : "memory");
}
#define CLUSTER_SYNC() do { \
    asm volatile("barrier.cluster.arrive.aligned;" ::: "memory"); \
    asm volatile("barrier.cluster.wait.aligned;" ::: "memory"); } while(0)

// Merged prologue: zero accumulators + class argmax + W transpose->bf16.
__global__ void prep_kernel(const float* __restrict__ la,
                            const float* __restrict__ lb,
                            const float* __restrict__ W1,
                            const float* __restrict__ W2) {
    const int bid = blockIdx.x, tid = threadIdx.x;
    if (bid == 0 && tid < 3) g_acc[tid] = 0.0;
    if (bid < 128) {
        int t = bid*256 + tid;
        float4 a = ((const float4*)la)[t];
        int ba = 0; float bv = a.x;
        if (a.y > bv) { bv = a.y; ba = 1; }
        if (a.z > bv) { bv = a.z; ba = 2; }
        if (a.w > bv) { bv = a.w; ba = 3; }
        g_cA[t] = ba;
        float4 b = ((const float4*)lb)[t];
        int bb = 0; bv = b.x;
        if (b.y > bv) { bv = b.y; bb = 1; }
        if (b.z > bv) { bv = b.z; bb = 2; }
        if (b.w > bv) { bv = b.w; bb = 3; }
        g_cB[t] = bb;
    } else {
        int idx = (bid - 128)*256 + tid;
        const float* W = (idx < DD*DD) ? W1 : W2;
        __nv_bfloat16* Wt = (idx < DD*DD) ? g_W1t : g_W2t;
        int e = idx & (DD*DD - 1);
        int k = e >> 8, n = e & 255;
        Wt[n*DD + k] = __float2bfloat16(W[e]);
    }
}

__device__ __forceinline__ void ln_row(float v[8],
    const float4& g0, const float4& g1, const float4& e0, const float4& e1,
    float* o)
{
    float s = 0.f, sq = 0.f;
    #pragma unroll
    for (int j = 0; j < 8; j++) {
        v[j] = v[j] > 0.f ? v[j] : 0.01f * v[j];
        s += v[j]; sq += v[j]*v[j];
    }
    #pragma unroll
    for (int off = 16; off; off >>= 1) {
        s  += __shfl_xor_sync(0xffffffffu, s, off);
        sq += __shfl_xor_sync(0xffffffffu, sq, off);
    }
    float mean = s * (1.f/256.f);
    float var  = sq * (1.f/256.f) - mean*mean;
    float rstd = rsqrtf(var + 1e-5f);
    o[0] = (v[0]-mean)*rstd*g0.x + e0.x;
    o[1] = (v[1]-mean)*rstd*g0.y + e0.y;
    o[2] = (v[2]-mean)*rstd*g0.z + e0.z;
    o[3] = (v[3]-mean)*rstd*g0.w + e0.w;
    o[4] = (v[4]-mean)*rstd*g1.x + e1.x;
    o[5] = (v[5]-mean)*rstd*g1.y + e1.y;
    o[6] = (v[6]-mean)*rstd*g1.z + e1.z;
    o[7] = (v[7]-mean)*rstd*g1.w + e1.w;
}

// Fused 2-layer MLP+LN embed, bf16 mma, fp32 x staged+converted in-kernel
// (byte-identical to R15 winner).
#define EMBED_SMEM ((64*128 + 2*256*16 + 64*16 + 2*64*32) * 4)

__global__ __launch_bounds__(256, 2)
void embed_kernel(const float* __restrict__ xA, const float* __restrict__ xB,
                  const float* __restrict__ b1,
                  const float* __restrict__ g1, const float* __restrict__ be1,
                  const float* __restrict__ b2,
                  const float* __restrict__ g2, const float* __restrict__ be2)
{
    extern __shared__ uint32_t smu[];
    uint32_t* Hg = smu;              // 8192
    uint32_t* Wg = smu + 8192;       // 2*4096
    uint32_t* Xg = smu + 16384;      // 1024
    float*    Xf = (float*)(smu + 17408); // 2 * 64*32 fp32

    const float* X   = blockIdx.y ? xB    : xA;
    __nv_bfloat16* E = blockIdx.y ? g_eBh : g_eAh;
    float* NRM       = blockIdx.y ? g_nB  : g_nA;

    const int tid  = threadIdx.x;
    const int lane = tid & 31;
    const int warp = tid >> 5;
    const int wm   = warp & 3;
    const int wn   = warp >> 2;
    const int g    = lane >> 2;
    const int t    = lane & 3;
    const int row0 = blockIdx.x * 64;

    const int sw = ((g>>1)&3) << 2;
    const int fA = sw | ((g&1) << 4);

    float c[16][4];
    #pragma unroll
    for (int j = 0; j < 16; j++)
        #pragma unroll
        for (int q = 0; q < 4; q++) c[j][q] = 0.f;

    {
        #pragma unroll
        for (int i = 0; i < 4; i++) {
            int ch = tid + i*256;
            int row = ch >> 2, q = ch & 3;
            cp_async16(&Wg[row*16 + ((q*4) ^ (((row>>1)&3)<<2))],
                       g_W1t + (size_t)row*DD + q*8);
        }
        #pragma unroll
        for (int i = 0; i < 2; i++) {
            int ch = tid + i*256;
            int row = ch >> 3, q = ch & 7;
            cp_async16(Xf + row*32 + q*4, X + (size_t)(row0 + row)*DD + q*4);
        }
        cp_commit(); cp_wait0();
    }
    __syncthreads();

    for (int kt = 0; kt < 8; kt++) {
        const int cur = kt & 1, nxt = cur ^ 1;
        {
            const float* Xs = Xf + cur*2048;
            #pragma unroll
            for (int i = 0; i < 4; i++) {
                int gi = tid + i*256;
                int r = gi >> 4, gx = gi & 15;
                float2 v = *(const float2*)(Xs + r*32 + gx*2);
                Xg[r*16 + (gx ^ (((r>>1)&3)<<2))] = pack_bf2(v.x, v.y);
            }
        }
        __syncthreads();
        if (kt < 7) {
            #pragma unroll
            for (int i = 0; i < 4; i++) {
                int ch = tid + i*256;
                int row = ch >> 2, q = ch & 3;
                cp_async16(&Wg[nxt*4096 + row*16 + ((q*4) ^ (((row>>1)&3)<<2))],
                           g_W1t + (size_t)row*DD + (kt+1)*32 + q*8);
            }
            #pragma unroll
            for (int i = 0; i < 2; i++) {
                int ch = tid + i*256;
                int row = ch >> 3, q = ch & 7;
                cp_async16(Xf + nxt*2048 + row*32 + q*4,
                           X + (size_t)(row0 + row)*DD + (kt+1)*32 + q*4);
            }
            cp_commit();
        }
        const uint32_t* Wc = Wg + cur*4096;
        #pragma unroll
        for (int h = 0; h < 2; h++) {
            const int gb = h*8;
            int r = wm*16 + g;
            uint32_t a0 = Xg[(r  )*16 + ((gb+t  ) ^ sw)];
            uint32_t a1 = Xg[(r+8)*16 + ((gb+t  ) ^ sw)];
            uint32_t a2 = Xg[(r  )*16 + ((gb+t+4) ^ sw)];
            uint32_t a3 = Xg[(r+8)*16 + ((gb+t+4) ^ sw)];
            #pragma unroll
            for (int j = 0; j < 16; j++) {
                int n = wn*128 + j*8 + g;
                uint32_t b0 = Wc[n*16 + ((gb+t  ) ^ sw)];
                uint32_t b1 = Wc[n*16 + ((gb+t+4) ^ sw)];
                mma_bf16(c[j], a0, a1, a2, a3, b0, b1);
            }
        }
        if (kt < 7) cp_wait0();
        __syncthreads();
    }

    {
        #pragma unroll
        for (int i = 0; i < 4; i++) {
            int ch = tid + i*256;
            int row = ch >> 2, q = ch & 3;
            cp_async16(&Wg[row*16 + ((q*4) ^ (((row>>1)&3)<<2))],
                       g_W2t + (size_t)row*DD + q*8);
        }
        cp_commit();
    }

    {
        int r = wm*16 + g;
        #pragma unroll
        for (int j = 0; j < 16; j++) {
            int gidx = wn*64 + j*4 + t;
            Hg[(r  )*128 + (gidx ^ fA)] = pack_bf2(c[j][0], c[j][1]);
            Hg[(r+8)*128 + (gidx ^ fA)] = pack_bf2(c[j][2], c[j][3]);
        }
    }
    __syncthreads();

    {
        const int c0 = lane*4, c1 = 128 + lane*4;
        float4 bv0 = *(const float4*)(b1 + c0), bv1 = *(const float4*)(b1 + c1);
        float4 gv0 = *(const float4*)(g1 + c0), gv1 = *(const float4*)(g1 + c1);
        float4 ev0 = *(const float4*)(be1 + c0), ev1 = *(const float4*)(be1 + c1);
        #pragma unroll
        for (int r = 0; r < 8; r++) {
            int row = warp*8 + r;
            int f = ((row&1)<<4) | (((row>>1)&3)<<2);
            uint2 u0 = *(uint2*)&Hg[row*128 + ((lane*2)      ^ f)];
            uint2 u1 = *(uint2*)&Hg[row*128 + ((64 + lane*2) ^ f)];
            float v[8], o[8];
            unpack_bf2(u0.x, v[0], v[1]); unpack_bf2(u0.y, v[2], v[3]);
            unpack_bf2(u1.x, v[4], v[5]); unpack_bf2(u1.y, v[6], v[7]);
            v[0]+=bv0.x; v[1]+=bv0.y; v[2]+=bv0.z; v[3]+=bv0.w;
            v[4]+=bv1.x; v[5]+=bv1.y; v[6]+=bv1.z; v[7]+=bv1.w;
            ln_row(v, gv0, gv1, ev0, ev1, o);
            uint2 w0, w1;
            w0.x = pack_bf2(o[0], o[1]); w0.y = pack_bf2(o[2], o[3]);
            w1.x = pack_bf2(o[4], o[5]); w1.y = pack_bf2(o[6], o[7]);
            *(uint2*)&Hg[row*128 + ((lane*2)      ^ f)] = w0;
            *(uint2*)&Hg[row*128 + ((64 + lane*2) ^ f)] = w1;
        }
    }
    cp_wait0();
    __syncthreads();

    #pragma unroll
    for (int j = 0; j < 16; j++)
        #pragma unroll
        for (int q = 0; q < 4; q++) c[j][q] = 0.f;

    for (int kt = 0; kt < 8; kt++) {
        const int cur = kt & 1, nxt = cur ^ 1;
        if (kt < 7) {
            #pragma unroll
            for (int i = 0; i < 4; i++) {
                int ch = tid + i*256;
                int row = ch >> 2, q = ch & 3;
                cp_async16(&Wg[nxt*4096 + row*16 + ((q*4) ^ (((row>>1)&3)<<2))],
                           g_W2t + (size_t)row*DD + (kt+1)*32 + q*8);
            }
            cp_commit();
        }
        const uint32_t* Wc = Wg + cur*4096;
        const uint32_t* H0 = Hg + (wm*16 + g    )*128;
        const uint32_t* H1 = Hg + (wm*16 + g + 8)*128;
        #pragma unroll
        for (int h = 0; h < 2; h++) {
            const int gb = kt*16 + h*8;
            uint32_t a0 = H0[(gb+t  ) ^ fA];
            uint32_t a1 = H1[(gb+t  ) ^ fA];
            uint32_t a2 = H0[(gb+t+4) ^ fA];
            uint32_t a3 = H1[(gb+t+4) ^ fA];
            const int gs = h*8;
            #pragma unroll
            for (int j = 0; j < 16; j++) {
                int n = wn*128 + j*8 + g;
                uint32_t b0 = Wc[n*16 + ((gs+t  ) ^ sw)];
                uint32_t b1 = Wc[n*16 + ((gs+t+4) ^ sw)];
                mma_bf16(c[j], a0, a1, a2, a3, b0, b1);
            }
        }
        if (kt < 7) cp_wait0();
        __syncthreads();
    }

    {
        int r = wm*16 + g;
        #pragma unroll
        for (int j = 0; j < 16; j++) {
            int gidx = wn*64 + j*4 + t;
            Hg[(r  )*128 + (gidx ^ fA)] = pack_bf2(c[j][0], c[j][1]);
            Hg[(r+8)*128 + (gidx ^ fA)] = pack_bf2(c[j][2], c[j][3]);
        }
    }
    __syncthreads();

    {
        const int c0 = lane*4, c1 = 128 + lane*4;
        float4 bv0 = *(const float4*)(b2 + c0), bv1 = *(const float4*)(b2 + c1);
        float4 gv0 = *(const float4*)(g2 + c0), gv1 = *(const float4*)(g2 + c1);
        float4 ev0 = *(const float4*)(be2 + c0), ev1 = *(const float4*)(be2 + c1);
        #pragma unroll
        for (int r = 0; r < 8; r++) {
            int row = warp*8 + r;
            int f = ((row&1)<<4) | (((row>>1)&3)<<2);
            uint2 u0 = *(uint2*)&Hg[row*128 + ((lane*2)      ^ f)];
            uint2 u1 = *(uint2*)&Hg[row*128 + ((64 + lane*2) ^ f)];
            float v[8], o[8];
            unpack_bf2(u0.x, v[0], v[1]); unpack_bf2(u0.y, v[2], v[3]);
            unpack_bf2(u1.x, v[4], v[5]); unpack_bf2(u1.y, v[6], v[7]);
            v[0]+=bv0.x; v[1]+=bv0.y; v[2]+=bv0.z; v[3]+=bv0.w;
            v[4]+=bv1.x; v[5]+=bv1.y; v[6]+=bv1.z; v[7]+=bv1.w;
            ln_row(v, gv0, gv1, ev0, ev1, o);
            float ns = o[0]*o[0]+o[1]*o[1]+o[2]*o[2]+o[3]*o[3]
                     + o[4]*o[4]+o[5]*o[5]+o[6]*o[6]+o[7]*o[7];
            #pragma unroll
            for (int off = 16; off; off >>= 1)
                ns += __shfl_xor_sync(0xffffffffu, ns, off);
            size_t grow = (size_t)(row0 + row);
            uint2 p0, p1;
            p0.x = pack_bf2(o[0], o[1]); p0.y = pack_bf2(o[2], o[3]);
            p1.x = pack_bf2(o[4], o[5]); p1.y = pack_bf2(o[6], o[7]);
            *(uint2*)(E + grow*DD + c0) = p0;
            *(uint2*)(E + grow*DD + c1) = p1;
            if (lane == 0) NRM[grow] = ns;
        }
    }
}

// cdist + cost_class + in/out loss + K(bf16) via bf16 mma (unchanged).
__global__ __launch_bounds__(256, 2)
void cost_kernel(const float* __restrict__ pa, const float* __restrict__ pb)
{
    __shared__ __align__(16) uint32_t As[2][128*16];
    __shared__ __align__(16) uint32_t Bs[2][128*16];
    __shared__ float redi[8], redo[8];

    const int b  = blockIdx.z;
    const int ti = blockIdx.y;
    const int tj = blockIdx.x;
    const int tid = threadIdx.x;
    const int lane = tid & 31;
    const int warp = tid >> 5;
    const int wm   = warp & 3;
    const int wn   = warp >> 2;
    const int g    = lane >> 2;
    const int t    = lane & 3;

    const __nv_bfloat16* Ab = g_eAh + (size_t)b*NN*DD + (size_t)ti*128*DD;
    const __nv_bfloat16* Bb = g_eBh + (size_t)b*NN*DD + (size_t)tj*128*DD;

    float c[2][8][4];
    #pragma unroll
    for (int m = 0; m < 2; m++)
        #pragma unroll
        for (int j = 0; j < 8; j++)
            #pragma unroll
            for (int q = 0; q < 4; q++) c[m][j][q] = 0.f;

    {
        #pragma unroll
        for (int i = 0; i < 2; i++) {
            int ch = tid + i*256;
            int row = ch >> 2, q = ch & 3;
            int dstg = row*16 + ((q*4) ^ (((row>>1)&3)<<2));
            cp_async16(&As[0][dstg], Ab + (size_t)row*DD + q*8);
            cp_async16(&Bs[0][dstg], Bb + (size_t)row*DD + q*8);
        }
        cp_commit(); cp_wait0();
    }
    __syncthreads();

    const int sw = ((g>>1)&3) << 2;

    for (int kt = 0; kt < 8; kt++) {
        const int cur = kt & 1, nxt = cur ^ 1;
        if (kt < 7) {
            #pragma unroll
            for (int i = 0; i < 2; i++) {
                int ch = tid + i*256;
                int row = ch >> 2, q = ch & 3;
                int dstg = row*16 + ((q*4) ^ (((row>>1)&3)<<2));
                cp_async16(&As[nxt][dstg], Ab + (size_t)row*DD + (kt+1)*32 + q*8);
                cp_async16(&Bs[nxt][dstg], Bb + (size_t)row*DD + (kt+1)*32 + q*8);
            }
            cp_commit();
        }
        const uint32_t* Ac = As[cur];
        const uint32_t* Bc = Bs[cur];
        #pragma unroll
        for (int h = 0; h < 2; h++) {
            const int gb = h*8;
            uint32_t a[2][4];
            #pragma unroll
            for (int m = 0; m < 2; m++) {
                int r = wm*32 + m*16 + g;
                a[m][0] = Ac[(r  )*16 + ((gb+t  ) ^ sw)];
                a[m][1] = Ac[(r+8)*16 + ((gb+t  ) ^ sw)];
                a[m][2] = Ac[(r  )*16 + ((gb+t+4) ^ sw)];
                a[m][3] = Ac[(r+8)*16 + ((gb+t+4) ^ sw)];
            }
            #pragma unroll
            for (int j = 0; j < 8; j++) {
                int n = wn*64 + j*8 + g;
                uint32_t b0 = Bc[n*16 + ((gb+t  ) ^ sw)];
                uint32_t b1 = Bc[n*16 + ((gb+t+4) ^ sw)];
                mma_bf16(c[0][j], a[0][0], a[0][1], a[0][2], a[0][3], b0, b1);
                mma_bf16(c[1][j], a[1][0], a[1][1], a[1][2], a[1][3], b0, b1);
            }
        }
        if (kt < 7) cp_wait0();
        __syncthreads();
    }

    float sin = 0.f, sout = 0.f;
    #pragma unroll
    for (int m = 0; m < 2; m++) {
        int il1 = ti*128 + wm*32 + m*16 + g;
        int il2 = il1 + 8;
        int gi1 = b*NN + il1, gi2 = b*NN + il2;
        float ni1 = g_nA[gi1], ni2 = g_nA[gi2];
        float pa1 = pa[gi1],   pa2 = pa[gi2];
        int   ca1 = g_cA[gi1], ca2 = g_cA[gi2];
        size_t rb1 = (size_t)gi1 * NN;
        size_t rb2 = (size_t)gi2 * NN;
        #pragma unroll
        for (int j = 0; j < 8; j++) {
            int jl = tj*128 + wn*64 + j*8 + 2*t;
            int gj = b*NN + jl;
            float nj0 = g_nB[gj], nj1 = g_nB[gj+1];
            float pb0 = pb[gj],   pb1 = pb[gj+1];
            int   cb0 = g_cB[gj], cb1 = g_cB[gj+1];

            float sq, cost, pm, cc, w;
            float k00, k01, k10, k11;

            sq = ni1 + nj0 - 2.f*c[m][j][0];
            cost = sqrtf(fmaxf(sq, 0.f));
            pm = pa1*pb0; cc = cost + (BIGC - BIGC*pm); w = cc*pm;
            if (ca1 == cb0) sin += w; else sout += w;
            k00 = __expf(-2.f*cc);

            sq = ni1 + nj1 - 2.f*c[m][j][1];
            cost = sqrtf(fmaxf(sq, 0.f));
            pm = pa1*pb1; cc = cost + (BIGC - BIGC*pm); w = cc*pm;
            if (ca1 == cb1) sin += w; else sout += w;
            k01 = __expf(-2.f*cc);

            sq = ni2 + nj0 - 2.f*c[m][j][2];
            cost = sqrtf(fmaxf(sq, 0.f));
            pm = pa2*pb0; cc = cost + (BIGC - BIGC*pm); w = cc*pm;
            if (ca2 == cb0) sin += w; else sout += w;
            k10 = __expf(-2.f*cc);

            sq = ni2 + nj1 - 2.f*c[m][j][3];
            cost = sqrtf(fmaxf(sq, 0.f));
            pm = pa2*pb1; cc = cost + (BIGC - BIGC*pm); w = cc*pm;
            if (ca2 == cb1) sin += w; else sout += w;
            k11 = __expf(-2.f*cc);

            *(uint32_t*)(g_K + rb1 + jl) = pack_bf2(k00, k01);
            *(uint32_t*)(g_K + rb2 + jl) = pack_bf2(k10, k11);
        }
    }
    #pragma unroll
    for (int off = 16; off; off >>= 1) {
        sin  += __shfl_xor_sync(0xffffffffu, sin,  off);
        sout += __shfl_xor_sync(0xffffffffu, sout, off);
    }
    if (lane == 0) { redi[warp] = sin; redo[warp] = sout; }
    __syncthreads();
    if (tid == 0) {
        float a = 0.f, o2 = 0.f;
        #pragma unroll
        for (int w = 0; w < 8; w++) { a += redi[w]; o2 += redo[w]; }
        atomicAdd(&g_acc[0], (double)a);
        atomicAdd(&g_acc[1], (double)o2);
    }
}

// Sinkhorn + fused sup loss: 8-CTA cluster per batch, K resident in smem.
// Rank r owns rows [64r, 64r+64); padded smem layout (260 words/row) makes
// both matvec phases bank-conflict-free. Column partials pushed to per-chunk
// owner CTA (DSMEM); owner reduces and broadcasts its v chunk to peers.
#define SK_SMEM ((SK_ROWS*SK_WPR + 512 + 512 + 64 + 8) * 4)

__global__ __launch_bounds__(256) __cluster_dims__(8, 1, 1)
void sinkhorn_kernel(const float* __restrict__ rel, const float* __restrict__ pa)
{
    extern __shared__ uint32_t sks[];
    uint32_t* Ks  = sks;                            // 64*260 words
    float* sv     = (float*)(sks + SK_ROWS*SK_WPR); // 512
    float* pcol   = sv + 512;                       // 8*64
    float* su     = pcol + 512;                     // 64
    float* sred   = su + 64;                        // 8

    uint32_t rank;
    asm("mov.u32 %0, %%cluster_ctarank;" : "=r"(rank));
    const int b = blockIdx.x >> 3;
    const __nv_bfloat16* Kb = g_K + (size_t)b*NN*NN + (size_t)rank*SK_ROWS*NN;

    const int tid  = threadIdx.x;
    const int lane = tid & 31;
    const int warp = tid >> 5;
    const int p2row = tid >> 2, p2seg = tid & 3;   // phase-2: 4 lanes per row
    const int owner = tid >> 5;                     // col-chunk owner CTA
    const int cl    = (tid & 31) * 2;               // local col within chunk

    // load own 64x512 K slice into smem (padded rows)
    #pragma unroll
    for (int i = 0; i < 16; i++) {
        int ch = tid + i*256;
        int row = ch >> 6, cq = ch & 63;
        cp_async16(&Ks[row*SK_WPR + cq*4], Kb + (size_t)row*NN + cq*8);
    }
    cp_commit();
    if (tid < SK_ROWS) su[tid] = 1.f/512.f;
    cp_wait0();
    __syncthreads();
    CLUSTER_SYNC();

    for (int it = 0; it < 10; it++) {
        // phase 1: partial column sums over own rows; thread owns cols 2tid,2tid+1
        float a0 = 0.f, a1 = 0.f;
        #pragma unroll 8
        for (int i = 0; i < 64; i++) {
            uint32_t kq = Ks[i*SK_WPR + tid];
            float k0, k1; unpack_bf2(kq, k0, k1);
            float ui = su[i];
            a0 = fmaf(k0, ui, a0);
            a1 = fmaf(k1, ui, a1);
        }
        dsmem_st_f32(&pcol[rank*64 + cl],     owner, a0);
        dsmem_st_f32(&pcol[rank*64 + cl + 1], owner, a1);
        CLUSTER_SYNC();
        // owner: reduce 8 partials for its 64 columns, broadcast v chunk
        if (tid < 64) {
            float y = 0.f;
            #pragma unroll
            for (int r = 0; r < 8; r++) y += pcol[r*64 + tid];
            float v = (1.f/512.f) / y;
            int gc = rank*64 + tid;
            sv[gc] = v;
            #pragma unroll
            for (int r = 0; r < 8; r++)
                if (r != (int)rank) dsmem_st_f32(&sv[gc], r, v);
        }
        CLUSTER_SYNC();
        // phase 2: row sums over own rows; 4 lanes/row, conflict-free
        float s = 0.f;
        #pragma unroll 8
        for (int q = 0; q < 64; q++) {
            int w = q*4 + p2seg;
            uint32_t kq = Ks[p2row*SK_WPR + w];
            float k0, k1; unpack_bf2(kq, k0, k1);
            float2 vv = *(const float2*)(sv + 2*w);
            s = fmaf(k0, vv.x, s);
            s = fmaf(k1, vv.y, s);
        }
        s += __shfl_xor_sync(0xffffffffu, s, 1);
        s += __shfl_xor_sync(0xffffffffu, s, 2);
        if (p2seg == 0) su[p2row] = (1.f/512.f) / s;
        __syncthreads();
    }

    // fused sup loss over own 64 rows (K in smem, rel streamed once)
    const float* relb = rel + (size_t)b*NN*NN + (size_t)rank*SK_ROWS*NN;
    const float* pab  = pa + b*NN + rank*SK_ROWS;
    float lacc = 0.f;
    {
        float ui  = su[p2row] * 512.f;
        float pai = pab[p2row];
        #pragma unroll 8
        for (int q = 0; q < 64; q++) {
            int w = q*4 + p2seg;
            uint32_t kq = Ks[p2row*SK_WPR + w];
            float k0, k1; unpack_bf2(kq, k0, k1);
            float2 vv = *(const float2*)(sv + 2*w);
            float2 rv = *(const float2*)(relb + (size_t)p2row*NN + 2*w);
            float d0 = ui*k0*vv.x - rv.x;
            float d1 = ui*k1*vv.y - rv.y;
            lacc += pai * (d0*d0 + d1*d1);
        }
    }
    #pragma unroll
    for (int off = 16; off; off >>= 1)
        lacc += __shfl_xor_sync(0xffffffffu, lacc, off);
    if (lane == 0) sred[warp] = lacc;
    __syncthreads();
    if (tid == 0) {
        float s = 0.f;
        #pragma unroll
        for (int w = 0; w < 8; w++) s += sred[w];
        atomicAdd(&g_acc[2], (double)s);
    }
    CLUSTER_SYNC();
}

__global__ void finalize_kernel(const float* __restrict__ pa, float* __restrict__ out)
{
    __shared__ float red[256];
    float s = 0.f;
    for (int i = threadIdx.x; i < BSZ*NN; i += 256) s += pa[i];
    red[threadIdx.x] = s;
    __syncthreads();
    for (int off = 128; off; off >>= 1) {
        if (threadIdx.x < off) red[threadIdx.x] += red[threadIdx.x + off];
        __syncthreads();
    }
    if (threadIdx.x == 0) {
        double M = (double)BSZ * (double)NN * (double)NN;
        out[0] = (float)(g_acc[0]/M - g_acc[1]/M + 10.0*(g_acc[2]/(double)red[0]));
    }
}

extern "C" void kernel_launch(void* const* d_in, const int* in_sizes, int n_in,
                              void* d_out, int out_size)
{
    const float* la  = (const float*)d_in[0];
    const float* lb  = (const float*)d_in[1];
    const float* xA  = (const float*)d_in[2];
    const float* xB  = (const float*)d_in[3];
    const float* rel = (const float*)d_in[4];
    const float* pa  = (const float*)d_in[5];
    const float* pb  = (const float*)d_in[6];
    const float* W1  = (const float*)d_in[7];
    const float* b1  = (const float*)d_in[8];
    const float* g1  = (const float*)d_in[9];
    const float* be1 = (const float*)d_in[10];
    const float* W2  = (const float*)d_in[11];
    const float* b2  = (const float*)d_in[12];
    const float* g2  = (const float*)d_in[13];
    const float* be2 = (const float*)d_in[14];
    float* out = (float*)d_out;

    cudaFuncSetAttribute(embed_kernel,
                         cudaFuncAttributeMaxDynamicSharedMemorySize, EMBED_SMEM);
    cudaFuncSetAttribute(sinkhorn_kernel,
                         cudaFuncAttributeMaxDynamicSharedMemorySize, SK_SMEM);

    prep_kernel<<<640, 256>>>(la, lb, W1, W2);
    embed_kernel<<<dim3(BSZ*NN/64, 2), 256, EMBED_SMEM>>>(
        xA, xB, b1, g1, be1, b2, g2, be2);
    cost_kernel<<<dim3(4, 4, BSZ), 256>>>(pa, pb);
    sinkhorn_kernel<<<BSZ*8, 256, SK_SMEM>>>(rel, pa);
    finalize_kernel<<<1, 256>>>(pa, out);
}